// round 1
// baseline (speedup 1.0000x reference)
#include <cuda_runtime.h>
#include <cuda_bf16.h>
#include <math.h>

// Problem constants
constexpr int Bc   = 512;          // batch
constexpr int Gc   = 131;          // graph size
constexpr int Dd   = 512;          // all dims (input/key/val/embed)
constexpr int MTOT = Bc * Gc;      // 67072
constexpr int SLD  = 132;          // padded leading dim for score rows (16B-aligned rows)
constexpr int LEAF_LO = 80;        // internal_node_holder
constexpr int LEAF_HI = 130;       // graph_size - next_holder

// Scratch (device globals: allocation-free, zero-initialized at module load)
__device__ float g_Q[(size_t)MTOT * Dd];
__device__ float g_K[(size_t)MTOT * Dd];
__device__ float g_V[(size_t)MTOT * Dd];
__device__ float g_H[(size_t)MTOT * Dd];
__device__ float g_S[(size_t)Bc * Gc * SLD];

// ---------------------------------------------------------------------------
// Generic SGEMM-NT: C[M,N] = A[M,K] @ W[N,K]^T (+ bias[n]).
// Requires M%128==0, N%64==0, K%16==0 (true for all uses here).
// BM=128, BN=64, BK=16, 256 threads, 8x4 per-thread tile.
// ---------------------------------------------------------------------------
template <bool BIAS>
__global__ __launch_bounds__(256)
void sgemm_nt(const float* __restrict__ A, const float* __restrict__ W,
              const float* __restrict__ bias, float* __restrict__ C,
              int M, int N, int K) {
    __shared__ float As[16][132];   // [k][m], padded stride
    __shared__ float Ws[16][68];    // [k][n]
    const int tid = threadIdx.x;
    const int tx  = tid & 15;
    const int ty  = tid >> 4;
    const int bm  = blockIdx.y * 128;
    const int bn  = blockIdx.x * 64;
    const float* Ag = A + (size_t)bm * K;
    const float* Wg = W + (size_t)bn * K;

    float acc[8][4];
#pragma unroll
    for (int i = 0; i < 8; i++)
#pragma unroll
        for (int j = 0; j < 4; j++) acc[i][j] = 0.f;

    for (int k0 = 0; k0 < K; k0 += 16) {
#pragma unroll
        for (int l = 0; l < 2; l++) {
            int idx = tid + l * 256;          // 0..511
            int m   = idx >> 2;               // 0..127
            int kq  = (idx & 3) << 2;         // 0,4,8,12
            float4 v = *reinterpret_cast<const float4*>(Ag + (size_t)m * K + k0 + kq);
            As[kq + 0][m] = v.x; As[kq + 1][m] = v.y;
            As[kq + 2][m] = v.z; As[kq + 3][m] = v.w;
        }
        {
            int n  = tid >> 2;                // 0..63
            int kq = (tid & 3) << 2;
            float4 v = *reinterpret_cast<const float4*>(Wg + (size_t)n * K + k0 + kq);
            Ws[kq + 0][n] = v.x; Ws[kq + 1][n] = v.y;
            Ws[kq + 2][n] = v.z; Ws[kq + 3][n] = v.w;
        }
        __syncthreads();
#pragma unroll
        for (int k = 0; k < 16; k++) {
            float4 a0 = *reinterpret_cast<const float4*>(&As[k][ty * 8]);
            float4 a1 = *reinterpret_cast<const float4*>(&As[k][ty * 8 + 4]);
            float4 bv = *reinterpret_cast<const float4*>(&Ws[k][tx * 4]);
            float a[8] = {a0.x, a0.y, a0.z, a0.w, a1.x, a1.y, a1.z, a1.w};
            float bb[4] = {bv.x, bv.y, bv.z, bv.w};
#pragma unroll
            for (int i = 0; i < 8; i++)
#pragma unroll
                for (int j = 0; j < 4; j++)
                    acc[i][j] = fmaf(a[i], bb[j], acc[i][j]);
        }
        __syncthreads();
    }

    float b0 = 0.f, b1 = 0.f, b2 = 0.f, b3 = 0.f;
    if (BIAS) {
        b0 = bias[bn + tx * 4 + 0]; b1 = bias[bn + tx * 4 + 1];
        b2 = bias[bn + tx * 4 + 2]; b3 = bias[bn + tx * 4 + 3];
    }
#pragma unroll
    for (int i = 0; i < 8; i++) {
        int m = bm + ty * 8 + i;
        float4 o;
        o.x = acc[i][0] + b0; o.y = acc[i][1] + b1;
        o.z = acc[i][2] + b2; o.w = acc[i][3] + b3;
        *reinterpret_cast<float4*>(C + (size_t)m * N + bn + tx * 4) = o;
    }
}

// ---------------------------------------------------------------------------
// Batched scores: S[b,i,j] = masked ? -30 : (1/sqrt(512)) * dot(Q[b,i,:], K[b,j,:])
// One block per (j-tile 32, i-tile 32, batch). 256 threads, 2x2 per thread.
// ---------------------------------------------------------------------------
__global__ __launch_bounds__(256)
void scores_kernel(const float* __restrict__ Q, const float* __restrict__ Kmat,
                   const int* __restrict__ mask, float* __restrict__ S) {
    const int b  = blockIdx.z;
    const int i0 = blockIdx.y * 32;
    const int j0 = blockIdx.x * 32;
    __shared__ float Qs[32][33];   // [k][i]
    __shared__ float Ks[32][33];   // [k][j]
    const int tid = threadIdx.x;
    const int tx = tid & 15, ty = tid >> 4;
    const float* Qb = Q    + (size_t)b * Gc * Dd;
    const float* Kb = Kmat + (size_t)b * Gc * Dd;
    float acc[2][2] = {{0.f, 0.f}, {0.f, 0.f}};
    const int r = tid >> 3;          // 0..31 (row within tile)
    const int c = (tid & 7) << 2;    // 0,4,...,28 (k offset)

    for (int k0 = 0; k0 < Dd; k0 += 32) {
        int gi = i0 + r;
        float4 vq = make_float4(0.f, 0.f, 0.f, 0.f);
        if (gi < Gc) vq = *reinterpret_cast<const float4*>(Qb + (size_t)gi * Dd + k0 + c);
        Qs[c + 0][r] = vq.x; Qs[c + 1][r] = vq.y; Qs[c + 2][r] = vq.z; Qs[c + 3][r] = vq.w;
        int gj = j0 + r;
        float4 vk = make_float4(0.f, 0.f, 0.f, 0.f);
        if (gj < Gc) vk = *reinterpret_cast<const float4*>(Kb + (size_t)gj * Dd + k0 + c);
        Ks[c + 0][r] = vk.x; Ks[c + 1][r] = vk.y; Ks[c + 2][r] = vk.z; Ks[c + 3][r] = vk.w;
        __syncthreads();
#pragma unroll
        for (int k = 0; k < 32; k++) {
            float a0 = Qs[k][ty * 2], a1 = Qs[k][ty * 2 + 1];
            float c0 = Ks[k][tx * 2], c1 = Ks[k][tx * 2 + 1];
            acc[0][0] = fmaf(a0, c0, acc[0][0]);
            acc[0][1] = fmaf(a0, c1, acc[0][1]);
            acc[1][0] = fmaf(a1, c0, acc[1][0]);
            acc[1][1] = fmaf(a1, c1, acc[1][1]);
        }
        __syncthreads();
    }

    const float norm = 0.04419417382415922f;   // 1/sqrt(512)
#pragma unroll
    for (int ii = 0; ii < 2; ii++) {
#pragma unroll
        for (int jj = 0; jj < 2; jj++) {
            int i = i0 + ty * 2 + ii;
            int j = j0 + tx * 2 + jj;
            if (i < Gc && j < Gc) {
                bool li = (i >= LEAF_LO) && (i < LEAF_HI);
                bool lj = (j >= LEAF_LO) && (j < LEAF_HI);
                bool msk = (mask[b * Gc + j] > 0) || (li && lj);
                S[((size_t)b * Gc + i) * SLD + j] = msk ? -30.f : norm * acc[ii][jj];
            }
        }
    }
}

// ---------------------------------------------------------------------------
// Row softmax over 131 (masked entries included in denominator, then zeroed —
// matches the reference). One block per (i, b); 160 threads (5 warps).
// ---------------------------------------------------------------------------
__global__ __launch_bounds__(160)
void softmax_kernel(float* __restrict__ S, const int* __restrict__ mask) {
    const int i = blockIdx.x;
    const int b = blockIdx.y;
    const int t = threadIdx.x;   // 0..159
    float* row = S + ((size_t)b * Gc + i) * SLD;
    float v = (t < Gc) ? row[t] : -3.0e38f;

    float m = v;
#pragma unroll
    for (int o = 16; o; o >>= 1) m = fmaxf(m, __shfl_xor_sync(0xffffffffu, m, o));
    __shared__ float rmax[5], rsum[5];
    int w = t >> 5;
    if ((t & 31) == 0) rmax[w] = m;
    __syncthreads();
    m = fmaxf(fmaxf(fmaxf(rmax[0], rmax[1]), fmaxf(rmax[2], rmax[3])), rmax[4]);

    float e = (t < Gc) ? expf(v - m) : 0.f;
    float s = e;
#pragma unroll
    for (int o = 16; o; o >>= 1) s += __shfl_xor_sync(0xffffffffu, s, o);
    if ((t & 31) == 0) rsum[w] = s;
    __syncthreads();
    float tot = rsum[0] + rsum[1] + rsum[2] + rsum[3] + rsum[4];

    if (t < Gc) {
        bool li = (i >= LEAF_LO) && (i < LEAF_HI);
        bool lj = (t >= LEAF_LO) && (t < LEAF_HI);
        bool msk = (mask[b * Gc + t] > 0) || (li && lj);
        row[t] = msk ? 0.f : e / tot;
    }
}

// ---------------------------------------------------------------------------
// Batched heads: H[b,i,n] = sum_j S[b,i,j] * V[b,j,n]. M=131, N=512, K=131.
// BM=32, BN=64, BK=32. 256 threads, 2x4 per thread.
// ---------------------------------------------------------------------------
__global__ __launch_bounds__(256)
void heads_kernel(const float* __restrict__ S, const float* __restrict__ V,
                  float* __restrict__ H) {
    const int b  = blockIdx.z;
    const int i0 = blockIdx.y * 32;
    const int n0 = blockIdx.x * 64;
    __shared__ float Ss[32][33];   // [j][i]
    __shared__ float Vs[32][68];   // [j][n]
    const float* Sb = S + (size_t)b * Gc * SLD;
    const float* Vb = V + (size_t)b * Gc * Dd;
    const int tid = threadIdx.x;
    const int tx = tid & 15, ty = tid >> 4;
    float acc[2][4] = {{0.f,0.f,0.f,0.f},{0.f,0.f,0.f,0.f}};

    for (int k0 = 0; k0 < Gc; k0 += 32) {
        if (k0 + 32 <= Gc) {
            // fast path: j fully in range
            int r = tid >> 3, c = (tid & 7) << 2;
            int gi = i0 + r;
            float4 v = make_float4(0.f, 0.f, 0.f, 0.f);
            if (gi < Gc) v = *reinterpret_cast<const float4*>(Sb + (size_t)gi * SLD + k0 + c);
            Ss[c + 0][r] = v.x; Ss[c + 1][r] = v.y; Ss[c + 2][r] = v.z; Ss[c + 3][r] = v.w;
#pragma unroll
            for (int l = 0; l < 2; l++) {
                int idx = tid + l * 256;
                int rr = idx >> 4, c4 = (idx & 15) << 2;
                float4 vv = *reinterpret_cast<const float4*>(Vb + (size_t)(k0 + rr) * Dd + n0 + c4);
                *reinterpret_cast<float4*>(&Vs[rr][c4]) = vv;
            }
        } else {
            // bounded tail: zero-fill out-of-range j
            for (int idx = tid; idx < 32 * 32; idx += 256) {
                int rr = idx >> 5, j = idx & 31;
                int gi = i0 + rr, gj = k0 + j;
                Ss[j][rr] = (gi < Gc && gj < Gc) ? Sb[(size_t)gi * SLD + gj] : 0.f;
            }
            for (int idx = tid; idx < 32 * 64; idx += 256) {
                int rr = idx >> 6, n = idx & 63;
                int gj = k0 + rr;
                Vs[rr][n] = (gj < Gc) ? Vb[(size_t)gj * Dd + n0 + n] : 0.f;
            }
        }
        __syncthreads();
#pragma unroll
        for (int k = 0; k < 32; k++) {
            float a0 = Ss[k][ty * 2], a1 = Ss[k][ty * 2 + 1];
            float4 bv = *reinterpret_cast<const float4*>(&Vs[k][tx * 4]);
            acc[0][0] = fmaf(a0, bv.x, acc[0][0]);
            acc[0][1] = fmaf(a0, bv.y, acc[0][1]);
            acc[0][2] = fmaf(a0, bv.z, acc[0][2]);
            acc[0][3] = fmaf(a0, bv.w, acc[0][3]);
            acc[1][0] = fmaf(a1, bv.x, acc[1][0]);
            acc[1][1] = fmaf(a1, bv.y, acc[1][1]);
            acc[1][2] = fmaf(a1, bv.z, acc[1][2]);
            acc[1][3] = fmaf(a1, bv.w, acc[1][3]);
        }
        __syncthreads();
    }

#pragma unroll
    for (int ii = 0; ii < 2; ii++) {
        int i = i0 + ty * 2 + ii;
        if (i < Gc) {
            float4 o = make_float4(acc[ii][0], acc[ii][1], acc[ii][2], acc[ii][3]);
            *reinterpret_cast<float4*>(H + ((size_t)b * Gc + i) * Dd + n0 + tx * 4) = o;
        }
    }
}

// ---------------------------------------------------------------------------
// Launch
// ---------------------------------------------------------------------------
extern "C" void kernel_launch(void* const* d_in, const int* in_sizes, int n_in,
                              void* d_out, int out_size) {
    const float* q    = (const float*)d_in[0];   // (B*G, 512)
    const int*   mask = (const int*)d_in[1];     // (B, G)
    // d_in[2]=graph_size, d_in[3]=evaluate (compile-time constants here)
    const float* h    = (const float*)d_in[4];   // (B, G, 512) contiguous
    const float* Wq   = (const float*)d_in[5];
    const float* Wk   = (const float*)d_in[6];
    const float* Wv   = (const float*)d_in[7];
    const float* Wo   = (const float*)d_in[8];
    const float* bo   = (const float*)d_in[9];
    float* out = (float*)d_out;

    float *gQ, *gK, *gV, *gH, *gS;
    cudaGetSymbolAddress((void**)&gQ, g_Q);
    cudaGetSymbolAddress((void**)&gK, g_K);
    cudaGetSymbolAddress((void**)&gV, g_V);
    cudaGetSymbolAddress((void**)&gH, g_H);
    cudaGetSymbolAddress((void**)&gS, g_S);

    dim3 gemmGrid(Dd / 64, MTOT / 128);   // (8, 524)

    sgemm_nt<false><<<gemmGrid, 256>>>(q, Wq, nullptr, gQ, MTOT, Dd, Dd);
    sgemm_nt<false><<<gemmGrid, 256>>>(h, Wk, nullptr, gK, MTOT, Dd, Dd);
    sgemm_nt<false><<<gemmGrid, 256>>>(h, Wv, nullptr, gV, MTOT, Dd, Dd);

    scores_kernel<<<dim3(5, 5, Bc), 256>>>(gQ, gK, mask, gS);
    softmax_kernel<<<dim3(Gc, Bc), 160>>>(gS, mask);
    heads_kernel<<<dim3(Dd / 64, 5, Bc), 256>>>(gS, gV, gH);

    sgemm_nt<true><<<gemmGrid, 256>>>(gH, Wo, bo, out, MTOT, Dd, Dd);
}

// round 3
// speedup vs baseline: 2.1798x; 2.1798x over previous
#include <cuda_runtime.h>
#include <math.h>
#include <stdint.h>

// ---------------------------------------------------------------------------
// Problem constants
// ---------------------------------------------------------------------------
constexpr int Bc   = 512;          // batch
constexpr int Gc   = 131;          // graph size
constexpr int Dd   = 512;          // all dims
constexpr int MTOT = Bc * Gc;      // 67072
constexpr int SLD  = 132;          // padded score row stride
constexpr int LEAF_LO = 80;
constexpr int LEAF_HI = 130;

// Scratch (device globals: allocation-free)
__device__ float g_Q [(size_t)MTOT * Dd];
__device__ float g_K [(size_t)MTOT * Dd];
__device__ float g_V [(size_t)MTOT * Dd];
__device__ float g_H [(size_t)MTOT * Dd];
__device__ float g_S [(size_t)Bc * Gc * SLD];
__device__ float g_qr[(size_t)MTOT * Dd];       // tf32-rounded q
__device__ float g_hr[(size_t)MTOT * Dd];       // tf32-rounded h
__device__ float g_Wr[4][512 * 512];            // tf32-rounded Wq,Wk,Wv,Wo

// ---------------------------------------------------------------------------
// Small PTX helpers (all baseline sm_80 PTX — valid for compute_103)
// ---------------------------------------------------------------------------
__device__ __forceinline__ float tf32_rn(float x) {
    uint32_t u;
    asm("cvt.rna.tf32.f32 %0, %1;" : "=r"(u) : "f"(x));
    return __uint_as_float(u);
}

__device__ __forceinline__ void cp_async16(uint32_t sdst, const void* gsrc) {
    asm volatile("cp.async.cg.shared.global [%0], [%1], 16;" :: "r"(sdst), "l"(gsrc));
}
__device__ __forceinline__ void cp_commit() {
    asm volatile("cp.async.commit_group;");
}
__device__ __forceinline__ void cp_wait0() {
    asm volatile("cp.async.wait_group 0;");
}

__device__ __forceinline__ void ldsm_x4(uint32_t& r0, uint32_t& r1, uint32_t& r2,
                                        uint32_t& r3, uint32_t addr) {
    asm volatile("ldmatrix.sync.aligned.m8n8.x4.shared.b16 {%0,%1,%2,%3}, [%4];"
                 : "=r"(r0), "=r"(r1), "=r"(r2), "=r"(r3) : "r"(addr));
}

__device__ __forceinline__ void mma_tf32(float* c, const uint32_t* a, const uint32_t* b) {
    asm volatile(
        "mma.sync.aligned.m16n8k8.row.col.f32.tf32.tf32.f32 "
        "{%0,%1,%2,%3}, {%4,%5,%6,%7}, {%8,%9}, {%0,%1,%2,%3};"
        : "+f"(c[0]), "+f"(c[1]), "+f"(c[2]), "+f"(c[3])
        : "r"(a[0]), "r"(a[1]), "r"(a[2]), "r"(a[3]), "r"(b[0]), "r"(b[1]));
}

// ---------------------------------------------------------------------------
// tf32 round prepass
// ---------------------------------------------------------------------------
__global__ void round_tf32_kernel(const float4* __restrict__ in,
                                  float4* __restrict__ out, int n4) {
    int i = blockIdx.x * blockDim.x + threadIdx.x;
    int stride = gridDim.x * blockDim.x;
    for (; i < n4; i += stride) {
        float4 v = in[i];
        v.x = tf32_rn(v.x); v.y = tf32_rn(v.y);
        v.z = tf32_rn(v.z); v.w = tf32_rn(v.w);
        out[i] = v;
    }
}

// ---------------------------------------------------------------------------
// tf32 mma.sync GEMM-NT: C[M,512] = A[M,512] @ W[512,512]^T (+bias)
// BM=128, BN=128, BK=32, 256 threads (8 warps: 4(m) x 2(n), warp tile 32x64).
// Double-buffered cp.async. Inputs must be pre-rounded to tf32.
// ---------------------------------------------------------------------------
constexpr int GM_BM = 128;
constexpr int GM_BN = 128;
constexpr int GM_BK = 32;
constexpr int GM_ROW = GM_BK + 4;                 // 36 floats = 144 B padded row
constexpr int GM_STAGE_F = (GM_BM + GM_BN) * GM_ROW;   // floats per stage (9216)
constexpr int GM_SMEM = 2 * GM_STAGE_F * 4;       // 73728 bytes
constexpr int GM_ITERS = 512 / GM_BK;             // 16

template <bool BIAS>
__global__ void __launch_bounds__(256)
mma_gemm_kernel(const float* __restrict__ A, const float* __restrict__ W,
                const float* __restrict__ bias, float* __restrict__ C) {
    extern __shared__ __align__(16) float sm[];
    const uint32_t smb = (uint32_t)__cvta_generic_to_shared(sm);
    const int tid = threadIdx.x;
    const int wid = tid >> 5;
    const int lane = tid & 31;
    const int bm = blockIdx.y * GM_BM;
    const int bn = blockIdx.x * GM_BN;
    const int wm = (wid & 3) * 32;    // warp m offset in tile
    const int wn = (wid >> 2) * 64;   // warp n offset in tile

    const float* Ag = A + (size_t)bm * 512;
    const float* Wg = W + (size_t)bn * 512;

    float c[2][8][4];
#pragma unroll
    for (int t = 0; t < 2; t++)
#pragma unroll
        for (int j = 0; j < 8; j++)
#pragma unroll
            for (int v = 0; v < 4; v++) c[t][j][v] = 0.f;

    // per-thread staging assignments: 4 A-chunks + 4 W-chunks of 16B
    // chunk id = tid + i*256; row = id>>3 (0..127), c4 = (id&7)*4
    // ldmatrix per-thread byte offsets (within a stage)
    const int lr = lane & 7;
    uint32_t aoff[2], boff[4];
#pragma unroll
    for (int t = 0; t < 2; t++)
        aoff[t] = (uint32_t)((wm + t * 16 + ((lane >> 3) & 1) * 8 + lr) * (GM_ROW * 4)
                             + (lane >> 4) * 16);
#pragma unroll
    for (int jp = 0; jp < 4; jp++)
        boff[jp] = (uint32_t)(GM_BM * GM_ROW * 4
                              + (wn + jp * 16 + ((lane >> 4) & 1) * 8 + lr) * (GM_ROW * 4)
                              + ((lane >> 3) & 1) * 16);

    auto load_stage = [&](int s, int k0) {
        uint32_t base = smb + (uint32_t)(s * GM_STAGE_F * 4);
#pragma unroll
        for (int i = 0; i < 4; i++) {
            int id = tid + i * 256;
            int row = id >> 3, c4 = (id & 7) << 2;
            cp_async16(base + (uint32_t)((row * GM_ROW + c4) * 4),
                       Ag + (size_t)row * 512 + k0 + c4);
        }
#pragma unroll
        for (int i = 0; i < 4; i++) {
            int id = tid + i * 256;
            int row = id >> 3, c4 = (id & 7) << 2;
            cp_async16(base + (uint32_t)((GM_BM * GM_ROW + row * GM_ROW + c4) * 4),
                       Wg + (size_t)row * 512 + k0 + c4);
        }
    };

    load_stage(0, 0);
    cp_commit();
    cp_wait0();
    __syncthreads();

    for (int it = 0; it < GM_ITERS; ++it) {
        if (it + 1 < GM_ITERS) {
            load_stage((it + 1) & 1, (it + 1) * GM_BK);
            cp_commit();
        }
        uint32_t base = smb + (uint32_t)((it & 1) * GM_STAGE_F * 4);
#pragma unroll
        for (int kk = 0; kk < 4; kk++) {
            uint32_t a[2][4], b[8][2];
#pragma unroll
            for (int t = 0; t < 2; t++)
                ldsm_x4(a[t][0], a[t][1], a[t][2], a[t][3], base + aoff[t] + kk * 32);
#pragma unroll
            for (int jp = 0; jp < 4; jp++) {
                uint32_t r0, r1, r2, r3;
                ldsm_x4(r0, r1, r2, r3, base + boff[jp] + kk * 32);
                b[2 * jp][0] = r0; b[2 * jp][1] = r1;
                b[2 * jp + 1][0] = r2; b[2 * jp + 1][1] = r3;
            }
#pragma unroll
            for (int t = 0; t < 2; t++)
#pragma unroll
                for (int j = 0; j < 8; j++)
                    mma_tf32(c[t][j], a[t], b[j]);
        }
        if (it + 1 < GM_ITERS) cp_wait0();
        __syncthreads();
    }

    // epilogue: c0:(g,2q) c1:(g,2q+1) c2:(g+8,2q) c3:(g+8,2q+1)
    const int g = lane >> 2;
    const int q = lane & 3;
#pragma unroll
    for (int j = 0; j < 8; j++) {
        int col = bn + wn + j * 8 + 2 * q;
        float b0 = 0.f, b1 = 0.f;
        if (BIAS) { b0 = bias[col]; b1 = bias[col + 1]; }
#pragma unroll
        for (int t = 0; t < 2; t++) {
            int row0 = bm + wm + t * 16 + g;
            float2 v0 = make_float2(c[t][j][0] + b0, c[t][j][1] + b1);
            float2 v1 = make_float2(c[t][j][2] + b0, c[t][j][3] + b1);
            *reinterpret_cast<float2*>(C + (size_t)row0 * 512 + col) = v0;
            *reinterpret_cast<float2*>(C + (size_t)(row0 + 8) * 512 + col) = v1;
        }
    }
}

// ---------------------------------------------------------------------------
// Batched scores: S[b,i,j] = masked ? -30 : (1/sqrt(512)) * dot(Q[b,i,:],K[b,j,:])
// 32x32 tile, 64 threads, 4x4 per thread. 2 LDS.128 per 16 FMA.
// ---------------------------------------------------------------------------
__global__ __launch_bounds__(64)
void scores_kernel(const float* __restrict__ Q, const float* __restrict__ Kmat,
                   const int* __restrict__ mask, float* __restrict__ S) {
    const int b  = blockIdx.z;
    const int i0 = blockIdx.y * 32;
    const int j0 = blockIdx.x * 32;
    __shared__ float Qs[16][36];
    __shared__ float Ks[16][36];
    const int tid = threadIdx.x;          // 0..63
    const int tx = tid & 7, ty = tid >> 3;
    const float* Qb = Q    + (size_t)b * Gc * Dd;
    const float* Kb = Kmat + (size_t)b * Gc * Dd;
    float acc[4][4];
#pragma unroll
    for (int i = 0; i < 4; i++)
#pragma unroll
        for (int j = 0; j < 4; j++) acc[i][j] = 0.f;

    for (int k0 = 0; k0 < Dd; k0 += 16) {
#pragma unroll
        for (int l = 0; l < 2; l++) {
            int id = tid + l * 64;        // 0..127
            int row = id >> 2;            // 0..31
            int c4 = (id & 3) << 2;       // 0,4,8,12
            int gi = i0 + row;
            float4 vq = make_float4(0.f, 0.f, 0.f, 0.f);
            if (gi < Gc) vq = *reinterpret_cast<const float4*>(Qb + (size_t)gi * Dd + k0 + c4);
            Qs[c4 + 0][row] = vq.x; Qs[c4 + 1][row] = vq.y;
            Qs[c4 + 2][row] = vq.z; Qs[c4 + 3][row] = vq.w;
            int gj = j0 + row;
            float4 vk = make_float4(0.f, 0.f, 0.f, 0.f);
            if (gj < Gc) vk = *reinterpret_cast<const float4*>(Kb + (size_t)gj * Dd + k0 + c4);
            Ks[c4 + 0][row] = vk.x; Ks[c4 + 1][row] = vk.y;
            Ks[c4 + 2][row] = vk.z; Ks[c4 + 3][row] = vk.w;
        }
        __syncthreads();
#pragma unroll
        for (int k = 0; k < 16; k++) {
            float4 a = *reinterpret_cast<const float4*>(&Qs[k][ty * 4]);
            float4 bb = *reinterpret_cast<const float4*>(&Ks[k][tx * 4]);
            float av[4] = {a.x, a.y, a.z, a.w};
            float bv[4] = {bb.x, bb.y, bb.z, bb.w};
#pragma unroll
            for (int i = 0; i < 4; i++)
#pragma unroll
                for (int j = 0; j < 4; j++)
                    acc[i][j] = fmaf(av[i], bv[j], acc[i][j]);
        }
        __syncthreads();
    }

    const float norm = 0.04419417382415922f;
#pragma unroll
    for (int ii = 0; ii < 4; ii++) {
        int i = i0 + ty * 4 + ii;
        if (i >= Gc) break;
        bool li = (i >= LEAF_LO) && (i < LEAF_HI);
#pragma unroll
        for (int jj = 0; jj < 4; jj++) {
            int j = j0 + tx * 4 + jj;
            if (j < Gc) {
                bool lj = (j >= LEAF_LO) && (j < LEAF_HI);
                bool msk = (mask[b * Gc + j] > 0) || (li && lj);
                S[((size_t)b * Gc + i) * SLD + j] = msk ? -30.f : norm * acc[ii][jj];
            }
        }
    }
}

// ---------------------------------------------------------------------------
// Row softmax (masked entries included in denominator, then zeroed)
// ---------------------------------------------------------------------------
__global__ __launch_bounds__(160)
void softmax_kernel(float* __restrict__ S, const int* __restrict__ mask) {
    const int i = blockIdx.x;
    const int b = blockIdx.y;
    const int t = threadIdx.x;
    float* row = S + ((size_t)b * Gc + i) * SLD;
    float v = (t < Gc) ? row[t] : -3.0e38f;

    float m = v;
#pragma unroll
    for (int o = 16; o; o >>= 1) m = fmaxf(m, __shfl_xor_sync(0xffffffffu, m, o));
    __shared__ float rmax[5], rsum[5];
    int w = t >> 5;
    if ((t & 31) == 0) rmax[w] = m;
    __syncthreads();
    m = fmaxf(fmaxf(fmaxf(rmax[0], rmax[1]), fmaxf(rmax[2], rmax[3])), rmax[4]);

    float e = (t < Gc) ? expf(v - m) : 0.f;
    float s = e;
#pragma unroll
    for (int o = 16; o; o >>= 1) s += __shfl_xor_sync(0xffffffffu, s, o);
    if ((t & 31) == 0) rsum[w] = s;
    __syncthreads();
    float tot = rsum[0] + rsum[1] + rsum[2] + rsum[3] + rsum[4];

    if (t < Gc) {
        bool li = (i >= LEAF_LO) && (i < LEAF_HI);
        bool lj = (t >= LEAF_LO) && (t < LEAF_HI);
        bool msk = (mask[b * Gc + t] > 0) || (li && lj);
        row[t] = msk ? 0.f : e / tot;
    }
}

// ---------------------------------------------------------------------------
// Batched heads: H[b,i,n] = sum_j S[b,i,j]*V[b,j,n]; output rounded to tf32
// ---------------------------------------------------------------------------
__global__ __launch_bounds__(256)
void heads_kernel(const float* __restrict__ S, const float* __restrict__ V,
                  float* __restrict__ H) {
    const int b  = blockIdx.z;
    const int i0 = blockIdx.y * 32;
    const int n0 = blockIdx.x * 64;
    __shared__ float Ss[32][33];
    __shared__ float Vs[32][68];
    const float* Sb = S + (size_t)b * Gc * SLD;
    const float* Vb = V + (size_t)b * Gc * Dd;
    const int tid = threadIdx.x;
    const int tx = tid & 15, ty = tid >> 4;
    float acc[2][4] = {{0.f,0.f,0.f,0.f},{0.f,0.f,0.f,0.f}};

    for (int k0 = 0; k0 < Gc; k0 += 32) {
        if (k0 + 32 <= Gc) {
            int r = tid >> 3, c = (tid & 7) << 2;
            int gi = i0 + r;
            float4 v = make_float4(0.f, 0.f, 0.f, 0.f);
            if (gi < Gc) v = *reinterpret_cast<const float4*>(Sb + (size_t)gi * SLD + k0 + c);
            Ss[c + 0][r] = v.x; Ss[c + 1][r] = v.y; Ss[c + 2][r] = v.z; Ss[c + 3][r] = v.w;
#pragma unroll
            for (int l = 0; l < 2; l++) {
                int idx = tid + l * 256;
                int rr = idx >> 4, c4 = (idx & 15) << 2;
                float4 vv = *reinterpret_cast<const float4*>(Vb + (size_t)(k0 + rr) * Dd + n0 + c4);
                *reinterpret_cast<float4*>(&Vs[rr][c4]) = vv;
            }
        } else {
            for (int idx = tid; idx < 32 * 32; idx += 256) {
                int rr = idx >> 5, j = idx & 31;
                int gi = i0 + rr, gj = k0 + j;
                Ss[j][rr] = (gi < Gc && gj < Gc) ? Sb[(size_t)gi * SLD + gj] : 0.f;
            }
            for (int idx = tid; idx < 32 * 64; idx += 256) {
                int rr = idx >> 6, n = idx & 63;
                int gj = k0 + rr;
                Vs[rr][n] = (gj < Gc) ? Vb[(size_t)gj * Dd + n0 + n] : 0.f;
            }
        }
        __syncthreads();
#pragma unroll
        for (int k = 0; k < 32; k++) {
            float a0 = Ss[k][ty * 2], a1 = Ss[k][ty * 2 + 1];
            float4 bv = *reinterpret_cast<const float4*>(&Vs[k][tx * 4]);
            acc[0][0] = fmaf(a0, bv.x, acc[0][0]);
            acc[0][1] = fmaf(a0, bv.y, acc[0][1]);
            acc[0][2] = fmaf(a0, bv.z, acc[0][2]);
            acc[0][3] = fmaf(a0, bv.w, acc[0][3]);
            acc[1][0] = fmaf(a1, bv.x, acc[1][0]);
            acc[1][1] = fmaf(a1, bv.y, acc[1][1]);
            acc[1][2] = fmaf(a1, bv.z, acc[1][2]);
            acc[1][3] = fmaf(a1, bv.w, acc[1][3]);
        }
        __syncthreads();
    }

#pragma unroll
    for (int ii = 0; ii < 2; ii++) {
        int i = i0 + ty * 2 + ii;
        if (i < Gc) {
            float4 o;
            o.x = tf32_rn(acc[ii][0]); o.y = tf32_rn(acc[ii][1]);
            o.z = tf32_rn(acc[ii][2]); o.w = tf32_rn(acc[ii][3]);
            *reinterpret_cast<float4*>(H + ((size_t)b * Gc + i) * Dd + n0 + tx * 4) = o;
        }
    }
}

// ---------------------------------------------------------------------------
// Launch
// ---------------------------------------------------------------------------
extern "C" void kernel_launch(void* const* d_in, const int* in_sizes, int n_in,
                              void* d_out, int out_size) {
    const float* q    = (const float*)d_in[0];
    const int*   mask = (const int*)d_in[1];
    const float* h    = (const float*)d_in[4];
    const float* Wq   = (const float*)d_in[5];
    const float* Wk   = (const float*)d_in[6];
    const float* Wv   = (const float*)d_in[7];
    const float* Wo   = (const float*)d_in[8];
    const float* bo   = (const float*)d_in[9];
    float* out = (float*)d_out;

    float *gQ, *gK, *gV, *gH, *gS, *gqr, *ghr, *gWr;
    cudaGetSymbolAddress((void**)&gQ,  g_Q);
    cudaGetSymbolAddress((void**)&gK,  g_K);
    cudaGetSymbolAddress((void**)&gV,  g_V);
    cudaGetSymbolAddress((void**)&gH,  g_H);
    cudaGetSymbolAddress((void**)&gS,  g_S);
    cudaGetSymbolAddress((void**)&gqr, g_qr);
    cudaGetSymbolAddress((void**)&ghr, g_hr);
    cudaGetSymbolAddress((void**)&gWr, g_Wr);
    float* gWq = gWr;
    float* gWk = gWr + 1 * 512 * 512;
    float* gWv = gWr + 2 * 512 * 512;
    float* gWo = gWr + 3 * 512 * 512;

    static bool attr_done = false;
    if (!attr_done) {
        cudaFuncSetAttribute(mma_gemm_kernel<false>,
                             cudaFuncAttributeMaxDynamicSharedMemorySize, GM_SMEM);
        cudaFuncSetAttribute(mma_gemm_kernel<true>,
                             cudaFuncAttributeMaxDynamicSharedMemorySize, GM_SMEM);
        attr_done = true;
    }

    // 1) tf32-RN prepass
    int n4_big = (MTOT * Dd) / 4;
    round_tf32_kernel<<<2048, 256>>>((const float4*)q, (float4*)gqr, n4_big);
    round_tf32_kernel<<<2048, 256>>>((const float4*)h, (float4*)ghr, n4_big);
    round_tf32_kernel<<<128, 256>>>((const float4*)Wq, (float4*)gWq, 512 * 512 / 4);
    round_tf32_kernel<<<128, 256>>>((const float4*)Wk, (float4*)gWk, 512 * 512 / 4);
    round_tf32_kernel<<<128, 256>>>((const float4*)Wv, (float4*)gWv, 512 * 512 / 4);
    round_tf32_kernel<<<128, 256>>>((const float4*)Wo, (float4*)gWo, 512 * 512 / 4);

    // 2) projections on tensor cores (legacy mma.sync tf32)
    dim3 gg(512 / GM_BN, MTOT / GM_BM);   // (4, 524)
    mma_gemm_kernel<false><<<gg, 256, GM_SMEM>>>(gqr, gWq, nullptr, gQ);
    mma_gemm_kernel<false><<<gg, 256, GM_SMEM>>>(ghr, gWk, nullptr, gK);
    mma_gemm_kernel<false><<<gg, 256, GM_SMEM>>>(ghr, gWv, nullptr, gV);

    // 3) attention (fp32 SIMT)
    scores_kernel<<<dim3(5, 5, Bc), 64>>>(gQ, gK, mask, gS);
    softmax_kernel<<<dim3(Gc, Bc), 160>>>(gS, mask);
    heads_kernel<<<dim3(Dd / 64, 5, Bc), 256>>>(gS, gV, gH);

    // 4) output projection (+bias) on tensor cores
    mma_gemm_kernel<true><<<gg, 256, GM_SMEM>>>(gH, gWo, bo, out);
}

// round 5
// speedup vs baseline: 3.4987x; 1.6051x over previous
#include <cuda_runtime.h>
#include <math.h>
#include <stdint.h>

// ---------------------------------------------------------------------------
// Problem constants
// ---------------------------------------------------------------------------
constexpr int Bc   = 512;          // batch
constexpr int Gc   = 131;          // graph size
constexpr int Dd   = 512;          // dims
constexpr int MTOT = Bc * Gc;      // 67072
constexpr int SLD  = 144;          // padded score row stride (zero-filled 131..143)
constexpr int LEAF_LO = 80;
constexpr int LEAF_HI = 130;

// Scratch (device globals: allocation-free)
__device__ float g_Q [(size_t)MTOT * Dd];
__device__ float g_KV[(size_t)MTOT * 1024];     // cols 0-511 = K, 512-1023 = V
__device__ float g_H [(size_t)MTOT * Dd];
__device__ float g_S [(size_t)Bc * Gc * SLD];
__device__ float g_qr[(size_t)MTOT * Dd];       // tf32-rounded q
__device__ float g_hr[(size_t)MTOT * Dd];       // tf32-rounded h
__device__ float g_Wr[4][512 * 512];            // tf32-rounded Wq,Wk,Wv,Wo

// ---------------------------------------------------------------------------
// PTX helpers (baseline sm_80 PTX only — valid for compute_103)
// ---------------------------------------------------------------------------
__device__ __forceinline__ float tf32_rn(float x) {
    uint32_t u;
    asm("cvt.rna.tf32.f32 %0, %1;" : "=r"(u) : "f"(x));
    return __uint_as_float(u);
}
__device__ __forceinline__ uint32_t smem_u32(const void* p) {
    return (uint32_t)__cvta_generic_to_shared(p);
}
__device__ __forceinline__ void cp_async16(uint32_t sdst, const void* gsrc) {
    asm volatile("cp.async.cg.shared.global [%0], [%1], 16;" :: "r"(sdst), "l"(gsrc));
}
// zero-fill variant: src_size = 0 writes 16B of zeros (src not dereferenced)
__device__ __forceinline__ void cp_async16z(uint32_t sdst, const void* gsrc, bool valid) {
    int sz = valid ? 16 : 0;
    asm volatile("cp.async.cg.shared.global [%0], [%1], 16, %2;"
                 :: "r"(sdst), "l"(gsrc), "r"(sz));
}
__device__ __forceinline__ void cp_commit() { asm volatile("cp.async.commit_group;"); }
__device__ __forceinline__ void cp_wait0()  { asm volatile("cp.async.wait_group 0;"); }

__device__ __forceinline__ void ldsm_x4(uint32_t& r0, uint32_t& r1, uint32_t& r2,
                                        uint32_t& r3, uint32_t addr) {
    asm volatile("ldmatrix.sync.aligned.m8n8.x4.shared.b16 {%0,%1,%2,%3}, [%4];"
                 : "=r"(r0), "=r"(r1), "=r"(r2), "=r"(r3) : "r"(addr));
}
__device__ __forceinline__ void mma_tf32(float* c, const uint32_t* a, const uint32_t* b) {
    asm volatile(
        "mma.sync.aligned.m16n8k8.row.col.f32.tf32.tf32.f32 "
        "{%0,%1,%2,%3}, {%4,%5,%6,%7}, {%8,%9}, {%0,%1,%2,%3};"
        : "+f"(c[0]), "+f"(c[1]), "+f"(c[2]), "+f"(c[3])
        : "r"(a[0]), "r"(a[1]), "r"(a[2]), "r"(a[3]), "r"(b[0]), "r"(b[1]));
}

// ---------------------------------------------------------------------------
// tf32 round prepass
// ---------------------------------------------------------------------------
__global__ void round_tf32_kernel(const float4* __restrict__ in,
                                  float4* __restrict__ out, int n4) {
    int i = blockIdx.x * blockDim.x + threadIdx.x;
    int stride = gridDim.x * blockDim.x;
    for (; i < n4; i += stride) {
        float4 v = in[i];
        v.x = tf32_rn(v.x); v.y = tf32_rn(v.y);
        v.z = tf32_rn(v.z); v.w = tf32_rn(v.w);
        out[i] = v;
    }
}

// round all four 512x512 weights in one launch (outputs contiguous in g_Wr)
__global__ void round_w4_kernel(const float4* __restrict__ w0, const float4* __restrict__ w1,
                                const float4* __restrict__ w2, const float4* __restrict__ w3,
                                float4* __restrict__ out) {
    int idx = blockIdx.x * blockDim.x + threadIdx.x;   // 0..262143
    const float4* src[4] = {w0, w1, w2, w3};
    int sel = idx >> 16;
    int off = idx & 65535;
    float4 v = src[sel][off];
    v.x = tf32_rn(v.x); v.y = tf32_rn(v.y);
    v.z = tf32_rn(v.z); v.w = tf32_rn(v.w);
    out[idx] = v;
}

// ---------------------------------------------------------------------------
// tf32 mma.sync GEMM-NT: C[M,N] = A[M,512] @ W[N,512]^T (+bias), C row stride CS
// BM=128, BN=128, BK=32, 256 threads (8 warps: 4m x 2n, warp tile 32x64).
// ---------------------------------------------------------------------------
constexpr int GM_BK = 32;
constexpr int GM_ROW = GM_BK + 4;                 // 36 floats / row (144 B)
constexpr int GM_STAGE_F = 256 * GM_ROW;          // (128+128) rows
constexpr int GM_SMEM = 2 * GM_STAGE_F * 4;       // 73728 bytes
constexpr int GM_ITERS = 512 / GM_BK;             // 16

template <bool BIAS, bool ROUND>
__global__ void __launch_bounds__(256)
mma_gemm_kernel(const float* __restrict__ A, const float* __restrict__ W,
                const float* __restrict__ bias, float* __restrict__ C, int CS) {
    extern __shared__ __align__(16) float sm[];
    const uint32_t smb = smem_u32(sm);
    const int tid = threadIdx.x;
    const int wid = tid >> 5;
    const int lane = tid & 31;
    const int bm = blockIdx.y * 128;
    const int bn = blockIdx.x * 128;
    const int wm = (wid & 3) * 32;
    const int wn = (wid >> 2) * 64;

    const float* Ag = A + (size_t)bm * 512;
    const float* Wg = W + (size_t)bn * 512;

    float c[2][8][4];
#pragma unroll
    for (int t = 0; t < 2; t++)
#pragma unroll
        for (int j = 0; j < 8; j++)
#pragma unroll
            for (int v = 0; v < 4; v++) c[t][j][v] = 0.f;

    const int lr = lane & 7;
    uint32_t aoff[2], boff[4];
#pragma unroll
    for (int t = 0; t < 2; t++)
        aoff[t] = (uint32_t)((wm + t * 16 + ((lane >> 3) & 1) * 8 + lr) * (GM_ROW * 4)
                             + (lane >> 4) * 16);
#pragma unroll
    for (int jp = 0; jp < 4; jp++)
        boff[jp] = (uint32_t)(128 * GM_ROW * 4
                              + (wn + jp * 16 + ((lane >> 4) & 1) * 8 + lr) * (GM_ROW * 4)
                              + ((lane >> 3) & 1) * 16);

    auto load_stage = [&](int s, int k0) {
        uint32_t base = smb + (uint32_t)(s * GM_STAGE_F * 4);
#pragma unroll
        for (int i = 0; i < 4; i++) {
            int id = tid + i * 256;
            int row = id >> 3, c4 = (id & 7) << 2;
            cp_async16(base + (uint32_t)((row * GM_ROW + c4) * 4),
                       Ag + (size_t)row * 512 + k0 + c4);
        }
#pragma unroll
        for (int i = 0; i < 4; i++) {
            int id = tid + i * 256;
            int row = id >> 3, c4 = (id & 7) << 2;
            cp_async16(base + (uint32_t)(((128 + row) * GM_ROW + c4) * 4),
                       Wg + (size_t)row * 512 + k0 + c4);
        }
    };

    load_stage(0, 0);
    cp_commit();
    cp_wait0();
    __syncthreads();

    for (int it = 0; it < GM_ITERS; ++it) {
        if (it + 1 < GM_ITERS) {
            load_stage((it + 1) & 1, (it + 1) * GM_BK);
            cp_commit();
        }
        uint32_t base = smb + (uint32_t)((it & 1) * GM_STAGE_F * 4);
#pragma unroll
        for (int kk = 0; kk < 4; kk++) {
            uint32_t a[2][4], b[8][2];
#pragma unroll
            for (int t = 0; t < 2; t++)
                ldsm_x4(a[t][0], a[t][1], a[t][2], a[t][3], base + aoff[t] + kk * 32);
#pragma unroll
            for (int jp = 0; jp < 4; jp++) {
                uint32_t r0, r1, r2, r3;
                ldsm_x4(r0, r1, r2, r3, base + boff[jp] + kk * 32);
                b[2 * jp][0] = r0; b[2 * jp][1] = r1;
                b[2 * jp + 1][0] = r2; b[2 * jp + 1][1] = r3;
            }
#pragma unroll
            for (int t = 0; t < 2; t++)
#pragma unroll
                for (int j = 0; j < 8; j++)
                    mma_tf32(c[t][j], a[t], b[j]);
        }
        if (it + 1 < GM_ITERS) cp_wait0();
        __syncthreads();
    }

    const int g = lane >> 2;
    const int q = lane & 3;
#pragma unroll
    for (int j = 0; j < 8; j++) {
        int col = bn + wn + j * 8 + 2 * q;
        float b0 = 0.f, b1 = 0.f;
        if (BIAS) { b0 = bias[col]; b1 = bias[col + 1]; }
#pragma unroll
        for (int t = 0; t < 2; t++) {
            int row0 = bm + wm + t * 16 + g;
            float v00 = c[t][j][0] + b0, v01 = c[t][j][1] + b1;
            float v10 = c[t][j][2] + b0, v11 = c[t][j][3] + b1;
            if (ROUND) {
                v00 = tf32_rn(v00); v01 = tf32_rn(v01);
                v10 = tf32_rn(v10); v11 = tf32_rn(v11);
            }
            *reinterpret_cast<float2*>(C + (size_t)row0 * CS + col) = make_float2(v00, v01);
            *reinterpret_cast<float2*>(C + (size_t)(row0 + 8) * CS + col) = make_float2(v10, v11);
        }
    }
}

// ---------------------------------------------------------------------------
// Fused scores + softmax (tf32 mma): per CTA 64 i-rows x all 131 j x K=512.
// Writes attn probs (tf32-rounded) to g_S rows of stride 144 (zeros 131..143).
// ---------------------------------------------------------------------------
constexpr int SC_STAGE = 18560;                  // Q(64x20f=5120B) + K(168x20f=13440B)
constexpr int SC_EPI   = 64 * 164 * 4;           // 41984 epilogue buffer
constexpr int SC_DYN   = (2 * SC_STAGE > SC_EPI) ? 2 * SC_STAGE : SC_EPI;

__global__ void __launch_bounds__(256)
scores_softmax_kernel(const float* __restrict__ Q, const float* __restrict__ KV,
                      const int* __restrict__ mask, float* __restrict__ S) {
    extern __shared__ __align__(16) char smc[];
    __shared__ int mask_s[144];
    const uint32_t smb = smem_u32(smc);
    float* Ss = reinterpret_cast<float*>(smc);   // epilogue view: [64][164]
    const int tid = threadIdx.x;
    const int wid = tid >> 5;
    const int lane = tid & 31;
    const int m0 = blockIdx.x * 64;
    const int b  = blockIdx.y;

    if (tid < 144) mask_s[tid] = (tid < Gc) ? mask[b * Gc + tid] : 1;

    const float* Qb = Q  + (size_t)b * Gc * 512;
    const float* Kb = KV + (size_t)b * Gc * 1024;   // K = cols 0..511

    const int wm = (wid & 1) * 32;        // 2 m-warps
    const int wn = (wid >> 1) * 40;       // 4 n-warps x 40 cols
    const int lr = lane & 7;

    float c[2][5][4];
#pragma unroll
    for (int t = 0; t < 2; t++)
#pragma unroll
        for (int n = 0; n < 5; n++)
#pragma unroll
            for (int v = 0; v < 4; v++) c[t][n][v] = 0.f;

    // aoff: offset within Q tile; boff: offset within stage (includes +5120 K base)
    uint32_t aoff[2], boff[3];
#pragma unroll
    for (int t = 0; t < 2; t++)
        aoff[t] = (uint32_t)((wm + t * 16 + ((lane >> 3) & 1) * 8 + lr) * 80
                             + (lane >> 4) * 16);
#pragma unroll
    for (int jp = 0; jp < 3; jp++)
        boff[jp] = (uint32_t)(5120 + (wn + jp * 16 + ((lane >> 4) & 1) * 8 + lr) * 80
                              + ((lane >> 3) & 1) * 16);

    auto load_stage = [&](int s, int k0) {
        uint32_t qb = smb + (uint32_t)(s * SC_STAGE);
        uint32_t kb = qb + 5120;
        {   // Q tile: 64 rows x 16 floats = 256 chunks, 1/thread
            int row = tid >> 2, c4 = (tid & 3) << 2;
            bool v = (m0 + row) < Gc;
            const float* src = v ? Qb + (size_t)(m0 + row) * 512 + k0 + c4 : Qb;
            cp_async16z(qb + (uint32_t)((row * 20 + c4) * 4), src, v);
        }
#pragma unroll
        for (int i = 0; i < 3; i++) {   // K tile: 160 rows x 16 floats = 640 chunks
            int id = tid + i * 256;
            if (id < 640) {
                int row = id >> 2, c4 = (id & 3) << 2;
                bool v = row < Gc;
                const float* src = v ? Kb + (size_t)row * 1024 + k0 + c4 : Kb;
                cp_async16z(kb + (uint32_t)((row * 20 + c4) * 4), src, v);
            }
        }
    };

    load_stage(0, 0);
    cp_commit();
    cp_wait0();
    __syncthreads();

    for (int it = 0; it < 32; ++it) {
        if (it + 1 < 32) {
            load_stage((it + 1) & 1, (it + 1) * 16);
            cp_commit();
        }
        uint32_t qb = smb + (uint32_t)((it & 1) * SC_STAGE);
#pragma unroll
        for (int kk = 0; kk < 2; kk++) {
            uint32_t a[2][4], bfr[6][2];
#pragma unroll
            for (int t = 0; t < 2; t++)
                ldsm_x4(a[t][0], a[t][1], a[t][2], a[t][3], qb + aoff[t] + kk * 32);
#pragma unroll
            for (int jp = 0; jp < 3; jp++) {
                uint32_t r0, r1, r2, r3;
                // boff already contains the +5120 K-tile base (bug fix: use qb, not kb)
                ldsm_x4(r0, r1, r2, r3, qb + boff[jp] + kk * 32);
                bfr[2 * jp][0] = r0; bfr[2 * jp][1] = r1;
                bfr[2 * jp + 1][0] = r2; bfr[2 * jp + 1][1] = r3;
            }
#pragma unroll
            for (int t = 0; t < 2; t++)
#pragma unroll
                for (int n = 0; n < 5; n++)   // bfr[5] is discarded padding
                    mma_tf32(c[t][n], a[t], bfr[n]);
        }
        if (it + 1 < 32) cp_wait0();
        __syncthreads();
    }

    // ---- stash accumulators in smem: Ss[64][164]
    const int g = lane >> 2;
    const int qd = lane & 3;
#pragma unroll
    for (int t = 0; t < 2; t++) {
        int r0 = wm + t * 16 + g;
#pragma unroll
        for (int n = 0; n < 5; n++) {
            int col = wn + n * 8 + 2 * qd;
            *reinterpret_cast<float2*>(&Ss[r0 * 164 + col]) = make_float2(c[t][n][0], c[t][n][1]);
            *reinterpret_cast<float2*>(&Ss[(r0 + 8) * 164 + col]) = make_float2(c[t][n][2], c[t][n][3]);
        }
    }
    __syncthreads();

    // ---- softmax: warp w handles rows w*8 .. w*8+7
    const float norm = 0.04419417382415922f;   // 1/sqrt(512)
#pragma unroll
    for (int rr = 0; rr < 8; rr++) {
        int i_loc = wid * 8 + rr;
        int gi = m0 + i_loc;
        if (gi >= Gc) break;                    // uniform per warp
        bool li = (gi >= LEAF_LO) && (gi < LEAF_HI);
        float v[5];
        float mx = -3.0e38f;
#pragma unroll
        for (int ch = 0; ch < 5; ch++) {
            int j = lane + ch * 32;
            float val = -3.0e38f;
            if (j < Gc) {
                float s = Ss[i_loc * 164 + j] * norm;
                bool mj = (mask_s[j] > 0) || (li && j >= LEAF_LO && j < LEAF_HI);
                val = mj ? -30.f : s;
            }
            v[ch] = val;
            mx = fmaxf(mx, val);
        }
#pragma unroll
        for (int o = 16; o; o >>= 1) mx = fmaxf(mx, __shfl_xor_sync(0xffffffffu, mx, o));
        float e[5];
        float sum = 0.f;
#pragma unroll
        for (int ch = 0; ch < 5; ch++) {
            int j = lane + ch * 32;
            e[ch] = (j < Gc) ? expf(v[ch] - mx) : 0.f;
            sum += e[ch];
        }
#pragma unroll
        for (int o = 16; o; o >>= 1) sum += __shfl_xor_sync(0xffffffffu, sum, o);
        float inv = 1.f / sum;
        float* Srow = S + ((size_t)b * Gc + gi) * SLD;
#pragma unroll
        for (int ch = 0; ch < 5; ch++) {
            int j = lane + ch * 32;
            if (j < SLD) {
                float p = 0.f;
                if (j < Gc) {
                    bool mj = (mask_s[j] > 0) || (li && j >= LEAF_LO && j < LEAF_HI);
                    p = mj ? 0.f : tf32_rn(e[ch] * inv);
                }
                Srow[j] = p;
            }
        }
    }
}

// ---------------------------------------------------------------------------
// heads (tf32 mma): H[i,n] = sum_j S[i,j] * V[j,n].  K=144 (zero-padded).
// A = S via ldsm, B = V via direct LDS.32 fragments. Output tf32-rounded.
// ---------------------------------------------------------------------------
constexpr int HD_STAGE = 5120 + 8448;            // S(64x20f) + V(16x132f) bytes
constexpr int HD_DYN   = 2 * HD_STAGE;           // 27136

__global__ void __launch_bounds__(256)
heads_kernel(const float* __restrict__ S, const float* __restrict__ KV,
             float* __restrict__ H) {
    extern __shared__ __align__(16) char smc[];
    const uint32_t smb = smem_u32(smc);
    const int tid = threadIdx.x;
    const int wid = tid >> 5;
    const int lane = tid & 31;
    const int n0 = blockIdx.x * 128;
    const int m0 = blockIdx.y * 64;
    const int b  = blockIdx.z;

    const float* Sb = S  + (size_t)b * Gc * SLD;
    const float* Vb = KV + (size_t)b * Gc * 1024 + 512;   // V = cols 512..1023

    const int wm = (wid & 1) * 32;
    const int wn = (wid >> 1) * 32;
    const int lr = lane & 7;

    float c[2][4][4];
#pragma unroll
    for (int t = 0; t < 2; t++)
#pragma unroll
        for (int n = 0; n < 4; n++)
#pragma unroll
            for (int v = 0; v < 4; v++) c[t][n][v] = 0.f;

    uint32_t aoff[2];
#pragma unroll
    for (int t = 0; t < 2; t++)
        aoff[t] = (uint32_t)((wm + t * 16 + ((lane >> 3) & 1) * 8 + lr) * 80
                             + (lane >> 4) * 16);

    auto load_stage = [&](int s, int k0) {
        uint32_t sbse = smb + (uint32_t)(s * HD_STAGE);
        uint32_t vbse = sbse + 5120;
        {   // S tile: 64 rows x 16 floats
            int row = tid >> 2, c4 = (tid & 3) << 2;
            bool v = (m0 + row) < Gc;
            const float* src = v ? Sb + (size_t)(m0 + row) * SLD + k0 + c4 : Sb;
            cp_async16z(sbse + (uint32_t)((row * 20 + c4) * 4), src, v);
        }
#pragma unroll
        for (int i = 0; i < 2; i++) {   // V tile: 16 k-rows x 128 n
            int id = tid + i * 256;
            int row = id >> 5, c4 = (id & 31) << 2;
            bool v = (k0 + row) < Gc;
            const float* src = v ? Vb + (size_t)(k0 + row) * 1024 + n0 + c4 : Vb;
            cp_async16z(vbse + (uint32_t)((row * 132 + c4) * 4), src, v);
        }
    };

    load_stage(0, 0);
    cp_commit();
    cp_wait0();
    __syncthreads();

    for (int it = 0; it < 9; ++it) {            // K = 144 = 9 x 16
        if (it + 1 < 9) {
            load_stage((it + 1) & 1, (it + 1) * 16);
            cp_commit();
        }
        uint32_t sbse = smb + (uint32_t)((it & 1) * HD_STAGE);
        const float* Vsm = reinterpret_cast<const float*>(smc + (it & 1) * HD_STAGE + 5120);
#pragma unroll
        for (int kk = 0; kk < 2; kk++) {
            uint32_t a[2][4];
#pragma unroll
            for (int t = 0; t < 2; t++)
                ldsm_x4(a[t][0], a[t][1], a[t][2], a[t][3], sbse + aoff[t] + kk * 32);
#pragma unroll
            for (int n = 0; n < 4; n++) {
                uint32_t bfr[2];
                int krow = kk * 8 + (lane & 3);
                int ncol = wn + n * 8 + (lane >> 2);
                bfr[0] = __float_as_uint(Vsm[krow * 132 + ncol]);
                bfr[1] = __float_as_uint(Vsm[(krow + 4) * 132 + ncol]);
#pragma unroll
                for (int t = 0; t < 2; t++)
                    mma_tf32(c[t][n], a[t], bfr);
            }
        }
        if (it + 1 < 9) cp_wait0();
        __syncthreads();
    }

    const int g = lane >> 2;
    const int qd = lane & 3;
#pragma unroll
    for (int t = 0; t < 2; t++) {
#pragma unroll
        for (int n = 0; n < 4; n++) {
            int col = n0 + wn + n * 8 + 2 * qd;
            int i0r = m0 + wm + t * 16 + g;
            if (i0r < Gc)
                *reinterpret_cast<float2*>(H + ((size_t)b * Gc + i0r) * 512 + col) =
                    make_float2(tf32_rn(c[t][n][0]), tf32_rn(c[t][n][1]));
            if (i0r + 8 < Gc)
                *reinterpret_cast<float2*>(H + ((size_t)b * Gc + i0r + 8) * 512 + col) =
                    make_float2(tf32_rn(c[t][n][2]), tf32_rn(c[t][n][3]));
        }
    }
}

// ---------------------------------------------------------------------------
// Launch
// ---------------------------------------------------------------------------
extern "C" void kernel_launch(void* const* d_in, const int* in_sizes, int n_in,
                              void* d_out, int out_size) {
    const float* q    = (const float*)d_in[0];
    const int*   mask = (const int*)d_in[1];
    const float* h    = (const float*)d_in[4];
    const float* Wq   = (const float*)d_in[5];
    const float* Wk   = (const float*)d_in[6];
    const float* Wv   = (const float*)d_in[7];
    const float* Wo   = (const float*)d_in[8];
    const float* bo   = (const float*)d_in[9];
    float* out = (float*)d_out;

    float *gQ, *gKV, *gH, *gS, *gqr, *ghr, *gWr;
    cudaGetSymbolAddress((void**)&gQ,  g_Q);
    cudaGetSymbolAddress((void**)&gKV, g_KV);
    cudaGetSymbolAddress((void**)&gH,  g_H);
    cudaGetSymbolAddress((void**)&gS,  g_S);
    cudaGetSymbolAddress((void**)&gqr, g_qr);
    cudaGetSymbolAddress((void**)&ghr, g_hr);
    cudaGetSymbolAddress((void**)&gWr, g_Wr);
    float* gWq = gWr;
    float* gWkv = gWr + 1 * 512 * 512;   // Wk ‖ Wv contiguous (1024 rows)
    float* gWo = gWr + 3 * 512 * 512;

    cudaFuncSetAttribute(mma_gemm_kernel<false, true>,
                         cudaFuncAttributeMaxDynamicSharedMemorySize, GM_SMEM);
    cudaFuncSetAttribute(mma_gemm_kernel<true, false>,
                         cudaFuncAttributeMaxDynamicSharedMemorySize, GM_SMEM);

    // 0) round all weights (1 launch)
    round_w4_kernel<<<1024, 256>>>((const float4*)Wq, (const float4*)Wk,
                                   (const float4*)Wv, (const float4*)Wo, (float4*)gWr);
    // 1-2) round activations
    int n4_big = (MTOT * Dd) / 4;
    round_tf32_kernel<<<4096, 256>>>((const float4*)q, (float4*)gqr, n4_big);
    round_tf32_kernel<<<4096, 256>>>((const float4*)h, (float4*)ghr, n4_big);

    // 3) fused K|V projection (N=1024), outputs tf32-rounded
    mma_gemm_kernel<false, true><<<dim3(8, MTOT / 128), 256, GM_SMEM>>>(
        ghr, gWkv, nullptr, gKV, 1024);
    // 4) Q projection, tf32-rounded
    mma_gemm_kernel<false, true><<<dim3(4, MTOT / 128), 256, GM_SMEM>>>(
        gqr, gWq, nullptr, gQ, 512);

    // 5) fused scores + softmax  (ncu -s 5 captures this one)
    scores_softmax_kernel<<<dim3(3, Bc), 256, SC_DYN>>>(gQ, gKV, mask, gS);

    // 6) heads on tensor cores
    heads_kernel<<<dim3(4, 3, Bc), 256, HD_DYN>>>(gS, gKV, gH);

    // 7) output projection (+bias)
    mma_gemm_kernel<true, false><<<dim3(4, MTOT / 128), 256, GM_SMEM>>>(
        gH, gWo, bo, out, 512);
}

// round 6
// speedup vs baseline: 3.6184x; 1.0342x over previous
#include <cuda_runtime.h>
#include <math.h>
#include <stdint.h>

// ---------------------------------------------------------------------------
// Problem constants
// ---------------------------------------------------------------------------
constexpr int Bc   = 512;          // batch
constexpr int Gc   = 131;          // graph size
constexpr int Dd   = 512;          // dims
constexpr int MTOT = Bc * Gc;      // 67072
constexpr int SLD  = 144;          // padded score row stride (zero-filled 131..143)
constexpr int LEAF_LO = 80;
constexpr int LEAF_HI = 130;

// Scratch (device globals: allocation-free)
__device__ float g_Q [(size_t)MTOT * Dd];
__device__ float g_KV[(size_t)MTOT * 1024];     // cols 0-511 = K, 512-1023 = V
__device__ float g_H [(size_t)MTOT * Dd];
__device__ float g_S [(size_t)Bc * Gc * SLD];
__device__ float g_qr[(size_t)MTOT * Dd];       // tf32-rounded q
__device__ float g_hr[(size_t)MTOT * Dd];       // tf32-rounded h
__device__ float g_Wr[4][512 * 512];            // tf32-rounded Wq,Wk,Wv,Wo

// ---------------------------------------------------------------------------
// PTX helpers (baseline sm_80 PTX only — valid for compute_103)
// ---------------------------------------------------------------------------
__device__ __forceinline__ float tf32_rn(float x) {
    uint32_t u;
    asm("cvt.rna.tf32.f32 %0, %1;" : "=r"(u) : "f"(x));
    return __uint_as_float(u);
}
__device__ __forceinline__ uint32_t smem_u32(const void* p) {
    return (uint32_t)__cvta_generic_to_shared(p);
}
__device__ __forceinline__ void cp_async16(uint32_t sdst, const void* gsrc) {
    asm volatile("cp.async.cg.shared.global [%0], [%1], 16;" :: "r"(sdst), "l"(gsrc));
}
// zero-fill variant: src_size = 0 writes 16B of zeros (src not dereferenced)
__device__ __forceinline__ void cp_async16z(uint32_t sdst, const void* gsrc, bool valid) {
    int sz = valid ? 16 : 0;
    asm volatile("cp.async.cg.shared.global [%0], [%1], 16, %2;"
                 :: "r"(sdst), "l"(gsrc), "r"(sz));
}
__device__ __forceinline__ void cp_commit() { asm volatile("cp.async.commit_group;"); }
__device__ __forceinline__ void cp_wait0()  { asm volatile("cp.async.wait_group 0;"); }
__device__ __forceinline__ void cp_wait1()  { asm volatile("cp.async.wait_group 1;"); }

__device__ __forceinline__ void ldsm_x4(uint32_t& r0, uint32_t& r1, uint32_t& r2,
                                        uint32_t& r3, uint32_t addr) {
    asm volatile("ldmatrix.sync.aligned.m8n8.x4.shared.b16 {%0,%1,%2,%3}, [%4];"
                 : "=r"(r0), "=r"(r1), "=r"(r2), "=r"(r3) : "r"(addr));
}
__device__ __forceinline__ void mma_tf32(float* c, const uint32_t* a, const uint32_t* b) {
    asm volatile(
        "mma.sync.aligned.m16n8k8.row.col.f32.tf32.tf32.f32 "
        "{%0,%1,%2,%3}, {%4,%5,%6,%7}, {%8,%9}, {%0,%1,%2,%3};"
        : "+f"(c[0]), "+f"(c[1]), "+f"(c[2]), "+f"(c[3])
        : "r"(a[0]), "r"(a[1]), "r"(a[2]), "r"(a[3]), "r"(b[0]), "r"(b[1]));
}

// ---------------------------------------------------------------------------
// tf32 round prepass
// ---------------------------------------------------------------------------
__global__ void round_tf32_kernel(const float4* __restrict__ in,
                                  float4* __restrict__ out, int n4) {
    int i = blockIdx.x * blockDim.x + threadIdx.x;
    int stride = gridDim.x * blockDim.x;
    for (; i < n4; i += stride) {
        float4 v = in[i];
        v.x = tf32_rn(v.x); v.y = tf32_rn(v.y);
        v.z = tf32_rn(v.z); v.w = tf32_rn(v.w);
        out[i] = v;
    }
}

// round all four 512x512 weights in one launch (outputs contiguous in g_Wr)
__global__ void round_w4_kernel(const float4* __restrict__ w0, const float4* __restrict__ w1,
                                const float4* __restrict__ w2, const float4* __restrict__ w3,
                                float4* __restrict__ out) {
    int idx = blockIdx.x * blockDim.x + threadIdx.x;   // 0..262143
    const float4* src[4] = {w0, w1, w2, w3};
    int sel = idx >> 16;
    int off = idx & 65535;
    float4 v = src[sel][off];
    v.x = tf32_rn(v.x); v.y = tf32_rn(v.y);
    v.z = tf32_rn(v.z); v.w = tf32_rn(v.w);
    out[idx] = v;
}

// ---------------------------------------------------------------------------
// tf32 mma.sync GEMM-NT: C[M,N] = A[M,512] @ W[N,512]^T (+bias), C row stride CS
// BM=128, BN=128, BK=32, 256 threads (8 warps: 4m x 2n, warp tile 32x64).
// 3-stage cp.async pipeline (prefetch 2 iters ahead, wait_group 1).
// ---------------------------------------------------------------------------
constexpr int GM_BK = 32;
constexpr int GM_ROW = GM_BK + 4;                 // 36 floats / row (144 B)
constexpr int GM_STAGE_F = 256 * GM_ROW;          // (128+128) rows = 9216 floats
constexpr int GM_STAGES = 3;
constexpr int GM_SMEM = GM_STAGES * GM_STAGE_F * 4;   // 110592 bytes
constexpr int GM_ITERS = 512 / GM_BK;             // 16

template <bool BIAS, bool ROUND>
__global__ void __launch_bounds__(256)
mma_gemm_kernel(const float* __restrict__ A, const float* __restrict__ W,
                const float* __restrict__ bias, float* __restrict__ C, int CS) {
    extern __shared__ __align__(16) float sm[];
    const uint32_t smb = smem_u32(sm);
    const int tid = threadIdx.x;
    const int wid = tid >> 5;
    const int lane = tid & 31;
    const int bm = blockIdx.y * 128;
    const int bn = blockIdx.x * 128;
    const int wm = (wid & 3) * 32;
    const int wn = (wid >> 2) * 64;

    const float* Ag = A + (size_t)bm * 512;
    const float* Wg = W + (size_t)bn * 512;

    float c[2][8][4];
#pragma unroll
    for (int t = 0; t < 2; t++)
#pragma unroll
        for (int j = 0; j < 8; j++)
#pragma unroll
            for (int v = 0; v < 4; v++) c[t][j][v] = 0.f;

    const int lr = lane & 7;
    uint32_t aoff[2], boff[4];
#pragma unroll
    for (int t = 0; t < 2; t++)
        aoff[t] = (uint32_t)((wm + t * 16 + ((lane >> 3) & 1) * 8 + lr) * (GM_ROW * 4)
                             + (lane >> 4) * 16);
#pragma unroll
    for (int jp = 0; jp < 4; jp++)
        boff[jp] = (uint32_t)(128 * GM_ROW * 4
                              + (wn + jp * 16 + ((lane >> 4) & 1) * 8 + lr) * (GM_ROW * 4)
                              + ((lane >> 3) & 1) * 16);

    auto load_stage = [&](int s, int k0) {
        uint32_t base = smb + (uint32_t)(s * GM_STAGE_F * 4);
#pragma unroll
        for (int i = 0; i < 4; i++) {
            int id = tid + i * 256;
            int row = id >> 3, c4 = (id & 7) << 2;
            cp_async16(base + (uint32_t)((row * GM_ROW + c4) * 4),
                       Ag + (size_t)row * 512 + k0 + c4);
        }
#pragma unroll
        for (int i = 0; i < 4; i++) {
            int id = tid + i * 256;
            int row = id >> 3, c4 = (id & 7) << 2;
            cp_async16(base + (uint32_t)(((128 + row) * GM_ROW + c4) * 4),
                       Wg + (size_t)row * 512 + k0 + c4);
        }
    };

    load_stage(0, 0);           cp_commit();
    load_stage(1, GM_BK);       cp_commit();
    cp_wait1();                 // stage 0 ready
    __syncthreads();

    int sc = 0;                 // compute stage
    int sl = 2;                 // next load stage
    for (int it = 0; it < GM_ITERS; ++it) {
        if (it + 2 < GM_ITERS) {
            load_stage(sl, (it + 2) * GM_BK);
            cp_commit();
            sl = (sl == GM_STAGES - 1) ? 0 : sl + 1;
        }
        uint32_t base = smb + (uint32_t)(sc * GM_STAGE_F * 4);
        sc = (sc == GM_STAGES - 1) ? 0 : sc + 1;
#pragma unroll
        for (int kk = 0; kk < 4; kk++) {
            uint32_t a[2][4], b[8][2];
#pragma unroll
            for (int t = 0; t < 2; t++)
                ldsm_x4(a[t][0], a[t][1], a[t][2], a[t][3], base + aoff[t] + kk * 32);
#pragma unroll
            for (int jp = 0; jp < 4; jp++) {
                uint32_t r0, r1, r2, r3;
                ldsm_x4(r0, r1, r2, r3, base + boff[jp] + kk * 32);
                b[2 * jp][0] = r0; b[2 * jp][1] = r1;
                b[2 * jp + 1][0] = r2; b[2 * jp + 1][1] = r3;
            }
#pragma unroll
            for (int t = 0; t < 2; t++)
#pragma unroll
                for (int j = 0; j < 8; j++)
                    mma_tf32(c[t][j], a[t], b[j]);
        }
        if (it + 2 < GM_ITERS)      cp_wait1();   // next stage ready
        else if (it + 1 < GM_ITERS) cp_wait0();   // drain tail
        __syncthreads();
    }

    const int g = lane >> 2;
    const int q = lane & 3;
#pragma unroll
    for (int j = 0; j < 8; j++) {
        int col = bn + wn + j * 8 + 2 * q;
        float b0 = 0.f, b1 = 0.f;
        if (BIAS) { b0 = bias[col]; b1 = bias[col + 1]; }
#pragma unroll
        for (int t = 0; t < 2; t++) {
            int row0 = bm + wm + t * 16 + g;
            float v00 = c[t][j][0] + b0, v01 = c[t][j][1] + b1;
            float v10 = c[t][j][2] + b0, v11 = c[t][j][3] + b1;
            if (ROUND) {
                v00 = tf32_rn(v00); v01 = tf32_rn(v01);
                v10 = tf32_rn(v10); v11 = tf32_rn(v11);
            }
            *reinterpret_cast<float2*>(C + (size_t)row0 * CS + col) = make_float2(v00, v01);
            *reinterpret_cast<float2*>(C + (size_t)(row0 + 8) * CS + col) = make_float2(v10, v11);
        }
    }
}

// ---------------------------------------------------------------------------
// Fused scores + softmax (tf32 mma): per CTA 64 i-rows x all 131 j x K=512.
// BK=32 (16 iters), 3-stage cp.async pipeline.
// Writes attn probs (tf32-rounded) to g_S rows of stride 144 (zeros 131..143).
// ---------------------------------------------------------------------------
constexpr int SC_QBYTES = 64 * 36 * 4;           // 9216
constexpr int SC_STAGE  = SC_QBYTES + 168 * 36 * 4;   // 33408
constexpr int SC_EPI    = 64 * 164 * 4;          // 41984 epilogue buffer
constexpr int SC_DYN    = (3 * SC_STAGE > SC_EPI) ? 3 * SC_STAGE : SC_EPI;  // 100224

__global__ void __launch_bounds__(256)
scores_softmax_kernel(const float* __restrict__ Q, const float* __restrict__ KV,
                      const int* __restrict__ mask, float* __restrict__ S) {
    extern __shared__ __align__(16) char smc[];
    __shared__ int mask_s[144];
    const uint32_t smb = smem_u32(smc);
    float* Ss = reinterpret_cast<float*>(smc);   // epilogue view: [64][164]
    const int tid = threadIdx.x;
    const int wid = tid >> 5;
    const int lane = tid & 31;
    const int m0 = blockIdx.x * 64;
    const int b  = blockIdx.y;

    if (tid < 144) mask_s[tid] = (tid < Gc) ? mask[b * Gc + tid] : 1;

    const float* Qb = Q  + (size_t)b * Gc * 512;
    const float* Kb = KV + (size_t)b * Gc * 1024;   // K = cols 0..511

    const int wm = (wid & 1) * 32;        // 2 m-warps
    const int wn = (wid >> 1) * 40;       // 4 n-warps x 40 cols
    const int lr = lane & 7;

    float c[2][5][4];
#pragma unroll
    for (int t = 0; t < 2; t++)
#pragma unroll
        for (int n = 0; n < 5; n++)
#pragma unroll
            for (int v = 0; v < 4; v++) c[t][n][v] = 0.f;

    // aoff: offset within Q tile; boff: offset within stage (includes K base)
    uint32_t aoff[2], boff[3];
#pragma unroll
    for (int t = 0; t < 2; t++)
        aoff[t] = (uint32_t)((wm + t * 16 + ((lane >> 3) & 1) * 8 + lr) * 144
                             + (lane >> 4) * 16);
#pragma unroll
    for (int jp = 0; jp < 3; jp++)
        boff[jp] = (uint32_t)(SC_QBYTES
                              + (wn + jp * 16 + ((lane >> 4) & 1) * 8 + lr) * 144
                              + ((lane >> 3) & 1) * 16);

    auto load_stage = [&](int s, int k0) {
        uint32_t qb = smb + (uint32_t)(s * SC_STAGE);
        uint32_t kb = qb + SC_QBYTES;
#pragma unroll
        for (int l = 0; l < 2; l++) {   // Q tile: 64 rows x 32 floats = 512 chunks
            int id = tid + l * 256;
            int row = id >> 3, c4 = (id & 7) << 2;
            bool v = (m0 + row) < Gc;
            const float* src = v ? Qb + (size_t)(m0 + row) * 512 + k0 + c4 : Qb;
            cp_async16z(qb + (uint32_t)((row * 36 + c4) * 4), src, v);
        }
#pragma unroll
        for (int i = 0; i < 5; i++) {   // K tile: 160 rows x 32 floats = 1280 chunks
            int id = tid + i * 256;
            int row = id >> 3, c4 = (id & 7) << 2;
            bool v = row < Gc;
            const float* src = v ? Kb + (size_t)row * 1024 + k0 + c4 : Kb;
            cp_async16z(kb + (uint32_t)((row * 36 + c4) * 4), src, v);
        }
    };

    load_stage(0, 0);   cp_commit();
    load_stage(1, 32);  cp_commit();
    cp_wait1();
    __syncthreads();

    int scur = 0, sl = 2;
    for (int it = 0; it < 16; ++it) {
        if (it + 2 < 16) {
            load_stage(sl, (it + 2) * 32);
            cp_commit();
            sl = (sl == 2) ? 0 : sl + 1;
        }
        uint32_t qb = smb + (uint32_t)(scur * SC_STAGE);
        scur = (scur == 2) ? 0 : scur + 1;
#pragma unroll
        for (int kk = 0; kk < 4; kk++) {
            uint32_t a[2][4], bfr[6][2];
#pragma unroll
            for (int t = 0; t < 2; t++)
                ldsm_x4(a[t][0], a[t][1], a[t][2], a[t][3], qb + aoff[t] + kk * 32);
#pragma unroll
            for (int jp = 0; jp < 3; jp++) {
                uint32_t r0, r1, r2, r3;
                ldsm_x4(r0, r1, r2, r3, qb + boff[jp] + kk * 32);
                bfr[2 * jp][0] = r0; bfr[2 * jp][1] = r1;
                bfr[2 * jp + 1][0] = r2; bfr[2 * jp + 1][1] = r3;
            }
#pragma unroll
            for (int t = 0; t < 2; t++)
#pragma unroll
                for (int n = 0; n < 5; n++)   // bfr[5] is discarded padding
                    mma_tf32(c[t][n], a[t], bfr[n]);
        }
        if (it + 2 < 16)      cp_wait1();
        else if (it + 1 < 16) cp_wait0();
        __syncthreads();
    }

    // ---- stash accumulators in smem: Ss[64][164]
    const int g = lane >> 2;
    const int qd = lane & 3;
#pragma unroll
    for (int t = 0; t < 2; t++) {
        int r0 = wm + t * 16 + g;
#pragma unroll
        for (int n = 0; n < 5; n++) {
            int col = wn + n * 8 + 2 * qd;
            *reinterpret_cast<float2*>(&Ss[r0 * 164 + col]) = make_float2(c[t][n][0], c[t][n][1]);
            *reinterpret_cast<float2*>(&Ss[(r0 + 8) * 164 + col]) = make_float2(c[t][n][2], c[t][n][3]);
        }
    }
    __syncthreads();

    // ---- softmax: warp w handles rows w*8 .. w*8+7
    const float norm = 0.04419417382415922f;   // 1/sqrt(512)
#pragma unroll
    for (int rr = 0; rr < 8; rr++) {
        int i_loc = wid * 8 + rr;
        int gi = m0 + i_loc;
        if (gi >= Gc) break;                    // uniform per warp
        bool li = (gi >= LEAF_LO) && (gi < LEAF_HI);
        float v[5];
        float mx = -3.0e38f;
#pragma unroll
        for (int ch = 0; ch < 5; ch++) {
            int j = lane + ch * 32;
            float val = -3.0e38f;
            if (j < Gc) {
                float s = Ss[i_loc * 164 + j] * norm;
                bool mj = (mask_s[j] > 0) || (li && j >= LEAF_LO && j < LEAF_HI);
                val = mj ? -30.f : s;
            }
            v[ch] = val;
            mx = fmaxf(mx, val);
        }
#pragma unroll
        for (int o = 16; o; o >>= 1) mx = fmaxf(mx, __shfl_xor_sync(0xffffffffu, mx, o));
        float e[5];
        float sum = 0.f;
#pragma unroll
        for (int ch = 0; ch < 5; ch++) {
            int j = lane + ch * 32;
            e[ch] = (j < Gc) ? expf(v[ch] - mx) : 0.f;
            sum += e[ch];
        }
#pragma unroll
        for (int o = 16; o; o >>= 1) sum += __shfl_xor_sync(0xffffffffu, sum, o);
        float inv = 1.f / sum;
        float* Srow = S + ((size_t)b * Gc + gi) * SLD;
#pragma unroll
        for (int ch = 0; ch < 5; ch++) {
            int j = lane + ch * 32;
            if (j < SLD) {
                float p = 0.f;
                if (j < Gc) {
                    bool mj = (mask_s[j] > 0) || (li && j >= LEAF_LO && j < LEAF_HI);
                    p = mj ? 0.f : tf32_rn(e[ch] * inv);
                }
                Srow[j] = p;
            }
        }
    }
}

// ---------------------------------------------------------------------------
// heads (tf32 mma): H[i,n] = sum_j S[i,j] * V[j,n].  K=144 (zero-padded).
// A = S via ldsm, B = V via direct LDS.32 fragments. Output tf32-rounded.
// ---------------------------------------------------------------------------
constexpr int HD_STAGE = 5120 + 8448;            // S(64x20f) + V(16x132f) bytes
constexpr int HD_DYN   = 2 * HD_STAGE;           // 27136

__global__ void __launch_bounds__(256)
heads_kernel(const float* __restrict__ S, const float* __restrict__ KV,
             float* __restrict__ H) {
    extern __shared__ __align__(16) char smc[];
    const uint32_t smb = smem_u32(smc);
    const int tid = threadIdx.x;
    const int wid = tid >> 5;
    const int lane = tid & 31;
    const int n0 = blockIdx.x * 128;
    const int m0 = blockIdx.y * 64;
    const int b  = blockIdx.z;

    const float* Sb = S  + (size_t)b * Gc * SLD;
    const float* Vb = KV + (size_t)b * Gc * 1024 + 512;   // V = cols 512..1023

    const int wm = (wid & 1) * 32;
    const int wn = (wid >> 1) * 32;
    const int lr = lane & 7;

    float c[2][4][4];
#pragma unroll
    for (int t = 0; t < 2; t++)
#pragma unroll
        for (int n = 0; n < 4; n++)
#pragma unroll
            for (int v = 0; v < 4; v++) c[t][n][v] = 0.f;

    uint32_t aoff[2];
#pragma unroll
    for (int t = 0; t < 2; t++)
        aoff[t] = (uint32_t)((wm + t * 16 + ((lane >> 3) & 1) * 8 + lr) * 80
                             + (lane >> 4) * 16);

    auto load_stage = [&](int s, int k0) {
        uint32_t sbse = smb + (uint32_t)(s * HD_STAGE);
        uint32_t vbse = sbse + 5120;
        {   // S tile: 64 rows x 16 floats
            int row = tid >> 2, c4 = (tid & 3) << 2;
            bool v = (m0 + row) < Gc;
            const float* src = v ? Sb + (size_t)(m0 + row) * SLD + k0 + c4 : Sb;
            cp_async16z(sbse + (uint32_t)((row * 20 + c4) * 4), src, v);
        }
#pragma unroll
        for (int i = 0; i < 2; i++) {   // V tile: 16 k-rows x 128 n
            int id = tid + i * 256;
            int row = id >> 5, c4 = (id & 31) << 2;
            bool v = (k0 + row) < Gc;
            const float* src = v ? Vb + (size_t)(k0 + row) * 1024 + n0 + c4 : Vb;
            cp_async16z(vbse + (uint32_t)((row * 132 + c4) * 4), src, v);
        }
    };

    load_stage(0, 0);
    cp_commit();
    cp_wait0();
    __syncthreads();

    for (int it = 0; it < 9; ++it) {            // K = 144 = 9 x 16
        if (it + 1 < 9) {
            load_stage((it + 1) & 1, (it + 1) * 16);
            cp_commit();
        }
        uint32_t sbse = smb + (uint32_t)((it & 1) * HD_STAGE);
        const float* Vsm = reinterpret_cast<const float*>(smc + (it & 1) * HD_STAGE + 5120);
#pragma unroll
        for (int kk = 0; kk < 2; kk++) {
            uint32_t a[2][4];
#pragma unroll
            for (int t = 0; t < 2; t++)
                ldsm_x4(a[t][0], a[t][1], a[t][2], a[t][3], sbse + aoff[t] + kk * 32);
#pragma unroll
            for (int n = 0; n < 4; n++) {
                uint32_t bfr[2];
                int krow = kk * 8 + (lane & 3);
                int ncol = wn + n * 8 + (lane >> 2);
                bfr[0] = __float_as_uint(Vsm[krow * 132 + ncol]);
                bfr[1] = __float_as_uint(Vsm[(krow + 4) * 132 + ncol]);
#pragma unroll
                for (int t = 0; t < 2; t++)
                    mma_tf32(c[t][n], a[t], bfr);
            }
        }
        if (it + 1 < 9) cp_wait0();
        __syncthreads();
    }

    const int g = lane >> 2;
    const int qd = lane & 3;
#pragma unroll
    for (int t = 0; t < 2; t++) {
#pragma unroll
        for (int n = 0; n < 4; n++) {
            int col = n0 + wn + n * 8 + 2 * qd;
            int i0r = m0 + wm + t * 16 + g;
            if (i0r < Gc)
                *reinterpret_cast<float2*>(H + ((size_t)b * Gc + i0r) * 512 + col) =
                    make_float2(tf32_rn(c[t][n][0]), tf32_rn(c[t][n][1]));
            if (i0r + 8 < Gc)
                *reinterpret_cast<float2*>(H + ((size_t)b * Gc + i0r + 8) * 512 + col) =
                    make_float2(tf32_rn(c[t][n][2]), tf32_rn(c[t][n][3]));
        }
    }
}

// ---------------------------------------------------------------------------
// Launch
// ---------------------------------------------------------------------------
extern "C" void kernel_launch(void* const* d_in, const int* in_sizes, int n_in,
                              void* d_out, int out_size) {
    const float* q    = (const float*)d_in[0];
    const int*   mask = (const int*)d_in[1];
    const float* h    = (const float*)d_in[4];
    const float* Wq   = (const float*)d_in[5];
    const float* Wk   = (const float*)d_in[6];
    const float* Wv   = (const float*)d_in[7];
    const float* Wo   = (const float*)d_in[8];
    const float* bo   = (const float*)d_in[9];
    float* out = (float*)d_out;

    float *gQ, *gKV, *gH, *gS, *gqr, *ghr, *gWr;
    cudaGetSymbolAddress((void**)&gQ,  g_Q);
    cudaGetSymbolAddress((void**)&gKV, g_KV);
    cudaGetSymbolAddress((void**)&gH,  g_H);
    cudaGetSymbolAddress((void**)&gS,  g_S);
    cudaGetSymbolAddress((void**)&gqr, g_qr);
    cudaGetSymbolAddress((void**)&ghr, g_hr);
    cudaGetSymbolAddress((void**)&gWr, g_Wr);
    float* gWq = gWr;
    float* gWkv = gWr + 1 * 512 * 512;   // Wk ‖ Wv contiguous (1024 rows)
    float* gWo = gWr + 3 * 512 * 512;

    cudaFuncSetAttribute(mma_gemm_kernel<false, true>,
                         cudaFuncAttributeMaxDynamicSharedMemorySize, GM_SMEM);
    cudaFuncSetAttribute(mma_gemm_kernel<true, false>,
                         cudaFuncAttributeMaxDynamicSharedMemorySize, GM_SMEM);
    cudaFuncSetAttribute(scores_softmax_kernel,
                         cudaFuncAttributeMaxDynamicSharedMemorySize, SC_DYN);

    // 0) round all weights (1 launch)
    round_w4_kernel<<<1024, 256>>>((const float4*)Wq, (const float4*)Wk,
                                   (const float4*)Wv, (const float4*)Wo, (float4*)gWr);
    // 1-2) round activations
    int n4_big = (MTOT * Dd) / 4;
    round_tf32_kernel<<<4096, 256>>>((const float4*)q, (float4*)gqr, n4_big);
    round_tf32_kernel<<<4096, 256>>>((const float4*)h, (float4*)ghr, n4_big);

    // 3) fused K|V projection (N=1024), outputs tf32-rounded
    mma_gemm_kernel<false, true><<<dim3(8, MTOT / 128), 256, GM_SMEM>>>(
        ghr, gWkv, nullptr, gKV, 1024);
    // 4) Q projection, tf32-rounded
    mma_gemm_kernel<false, true><<<dim3(4, MTOT / 128), 256, GM_SMEM>>>(
        gqr, gWq, nullptr, gQ, 512);

    // 5) fused scores + softmax
    scores_softmax_kernel<<<dim3(3, Bc), 256, SC_DYN>>>(gQ, gKV, mask, gS);

    // 6) heads on tensor cores
    heads_kernel<<<dim3(4, 3, Bc), 256, HD_DYN>>>(gS, gKV, gH);

    // 7) output projection (+bias)
    mma_gemm_kernel<true, false><<<dim3(4, MTOT / 128), 256, GM_SMEM>>>(
        gH, gWo, bo, out, 512);
}

// round 7
// speedup vs baseline: 5.2966x; 1.4638x over previous
#include <cuda_runtime.h>
#include <math.h>
#include <stdint.h>

// ---------------------------------------------------------------------------
// Problem constants
// ---------------------------------------------------------------------------
constexpr int Bc   = 512;          // batch
constexpr int Gc   = 131;          // graph size
constexpr int Dd   = 512;          // dims
constexpr int MTOT = Bc * Gc;      // 67072
constexpr int SLD  = 144;          // padded score row stride (zero-filled 131..143)
constexpr int LEAF_LO = 80;
constexpr int LEAF_HI = 130;

// Scratch (device globals: allocation-free)
__device__ float g_Q [(size_t)MTOT * Dd];       // q' = q·M
__device__ float g_H [(size_t)MTOT * Dd];       // X  = attn·h
__device__ float g_S [(size_t)Bc * Gc * SLD];
__device__ float g_qr[(size_t)MTOT * Dd];       // tf32-rounded q
__device__ float g_hr[(size_t)MTOT * Dd];       // tf32-rounded h
__device__ float g_Wr[4][512 * 512];            // WqT, WkT, WvT, Wo (all tf32-rounded)
__device__ float g_WM[2][512 * 512];            // Wm = (q·M weight), Wn = (X·N weight)

// ---------------------------------------------------------------------------
// PTX helpers (baseline sm_80 PTX only — valid for compute_103)
// ---------------------------------------------------------------------------
__device__ __forceinline__ float tf32_rn(float x) {
    uint32_t u;
    asm("cvt.rna.tf32.f32 %0, %1;" : "=r"(u) : "f"(x));
    return __uint_as_float(u);
}
__device__ __forceinline__ uint32_t smem_u32(const void* p) {
    return (uint32_t)__cvta_generic_to_shared(p);
}
__device__ __forceinline__ void cp_async16(uint32_t sdst, const void* gsrc) {
    asm volatile("cp.async.cg.shared.global [%0], [%1], 16;" :: "r"(sdst), "l"(gsrc));
}
// zero-fill variant: src_size = 0 writes 16B of zeros (src not dereferenced)
__device__ __forceinline__ void cp_async16z(uint32_t sdst, const void* gsrc, bool valid) {
    int sz = valid ? 16 : 0;
    asm volatile("cp.async.cg.shared.global [%0], [%1], 16, %2;"
                 :: "r"(sdst), "l"(gsrc), "r"(sz));
}
__device__ __forceinline__ void cp_commit() { asm volatile("cp.async.commit_group;"); }
__device__ __forceinline__ void cp_wait0()  { asm volatile("cp.async.wait_group 0;"); }
__device__ __forceinline__ void cp_wait1()  { asm volatile("cp.async.wait_group 1;"); }

__device__ __forceinline__ void ldsm_x4(uint32_t& r0, uint32_t& r1, uint32_t& r2,
                                        uint32_t& r3, uint32_t addr) {
    asm volatile("ldmatrix.sync.aligned.m8n8.x4.shared.b16 {%0,%1,%2,%3}, [%4];"
                 : "=r"(r0), "=r"(r1), "=r"(r2), "=r"(r3) : "r"(addr));
}
__device__ __forceinline__ void mma_tf32(float* c, const uint32_t* a, const uint32_t* b) {
    asm volatile(
        "mma.sync.aligned.m16n8k8.row.col.f32.tf32.tf32.f32 "
        "{%0,%1,%2,%3}, {%4,%5,%6,%7}, {%8,%9}, {%0,%1,%2,%3};"
        : "+f"(c[0]), "+f"(c[1]), "+f"(c[2]), "+f"(c[3])
        : "r"(a[0]), "r"(a[1]), "r"(a[2]), "r"(a[3]), "r"(b[0]), "r"(b[1]));
}

// ---------------------------------------------------------------------------
// tf32 round prepass (activations)
// ---------------------------------------------------------------------------
__global__ void round_tf32_kernel(const float4* __restrict__ in,
                                  float4* __restrict__ out, int n4) {
    int i = blockIdx.x * blockDim.x + threadIdx.x;
    int stride = gridDim.x * blockDim.x;
    for (; i < n4; i += stride) {
        float4 v = in[i];
        v.x = tf32_rn(v.x); v.y = tf32_rn(v.y);
        v.z = tf32_rn(v.z); v.w = tf32_rn(v.w);
        out[i] = v;
    }
}

// Weight prep: z=0,1,2 -> transpose+round Wq,Wk,Wv; z=3 -> plain round Wo.
// grid (16,16,4), block (32,8)
__global__ void prep_weights_kernel(const float* __restrict__ w0, const float* __restrict__ w1,
                                    const float* __restrict__ w2, const float* __restrict__ w3,
                                    float* __restrict__ out) {
    __shared__ float tile[32][33];
    const int z = blockIdx.z;
    const float* in = (z == 0) ? w0 : (z == 1) ? w1 : (z == 2) ? w2 : w3;
    float* o = out + (size_t)z * 512 * 512;
    const int tx = threadIdx.x, ty = threadIdx.y;
    const int x = blockIdx.x * 32 + tx;
    const int y0 = blockIdx.y * 32;
    if (z < 3) {
#pragma unroll
        for (int j = 0; j < 32; j += 8)
            tile[ty + j][tx] = in[(size_t)(y0 + ty + j) * 512 + x];
        __syncthreads();
        const int x2 = y0 + tx;
        const int y2 = blockIdx.x * 32;
#pragma unroll
        for (int j = 0; j < 32; j += 8)
            o[(size_t)(y2 + ty + j) * 512 + x2] = tf32_rn(tile[tx][ty + j]);
    } else {
#pragma unroll
        for (int j = 0; j < 32; j += 8)
            o[(size_t)(y0 + ty + j) * 512 + x] = tf32_rn(in[(size_t)(y0 + ty + j) * 512 + x]);
    }
}

// ---------------------------------------------------------------------------
// tf32 mma.sync GEMM-NT: C[M,N] = A[M,512] @ W[N,512]^T (+bias), C row stride CS
// BM=128, BN=128, BK=32, 256 threads (8 warps: 4m x 2n, warp tile 32x64).
// 3-stage cp.async pipeline.
// ---------------------------------------------------------------------------
constexpr int GM_BK = 32;
constexpr int GM_ROW = GM_BK + 4;                 // 36 floats / row (144 B)
constexpr int GM_STAGE_F = 256 * GM_ROW;          // 9216 floats
constexpr int GM_STAGES = 3;
constexpr int GM_SMEM = GM_STAGES * GM_STAGE_F * 4;   // 110592 bytes
constexpr int GM_ITERS = 512 / GM_BK;             // 16

template <bool BIAS, bool ROUND>
__global__ void __launch_bounds__(256)
mma_gemm_kernel(const float* __restrict__ A, const float* __restrict__ W,
                const float* __restrict__ bias, float* __restrict__ C, int CS) {
    extern __shared__ __align__(16) float sm[];
    const uint32_t smb = smem_u32(sm);
    const int tid = threadIdx.x;
    const int wid = tid >> 5;
    const int lane = tid & 31;
    const int bm = blockIdx.y * 128;
    const int bn = blockIdx.x * 128;
    const int wm = (wid & 3) * 32;
    const int wn = (wid >> 2) * 64;

    const float* Ag = A + (size_t)bm * 512;
    const float* Wg = W + (size_t)bn * 512;

    float c[2][8][4];
#pragma unroll
    for (int t = 0; t < 2; t++)
#pragma unroll
        for (int j = 0; j < 8; j++)
#pragma unroll
            for (int v = 0; v < 4; v++) c[t][j][v] = 0.f;

    const int lr = lane & 7;
    uint32_t aoff[2], boff[4];
#pragma unroll
    for (int t = 0; t < 2; t++)
        aoff[t] = (uint32_t)((wm + t * 16 + ((lane >> 3) & 1) * 8 + lr) * (GM_ROW * 4)
                             + (lane >> 4) * 16);
#pragma unroll
    for (int jp = 0; jp < 4; jp++)
        boff[jp] = (uint32_t)(128 * GM_ROW * 4
                              + (wn + jp * 16 + ((lane >> 4) & 1) * 8 + lr) * (GM_ROW * 4)
                              + ((lane >> 3) & 1) * 16);

    auto load_stage = [&](int s, int k0) {
        uint32_t base = smb + (uint32_t)(s * GM_STAGE_F * 4);
#pragma unroll
        for (int i = 0; i < 4; i++) {
            int id = tid + i * 256;
            int row = id >> 3, c4 = (id & 7) << 2;
            cp_async16(base + (uint32_t)((row * GM_ROW + c4) * 4),
                       Ag + (size_t)row * 512 + k0 + c4);
        }
#pragma unroll
        for (int i = 0; i < 4; i++) {
            int id = tid + i * 256;
            int row = id >> 3, c4 = (id & 7) << 2;
            cp_async16(base + (uint32_t)(((128 + row) * GM_ROW + c4) * 4),
                       Wg + (size_t)row * 512 + k0 + c4);
        }
    };

    load_stage(0, 0);           cp_commit();
    load_stage(1, GM_BK);       cp_commit();
    cp_wait1();
    __syncthreads();

    int sc = 0;
    int sl = 2;
    for (int it = 0; it < GM_ITERS; ++it) {
        if (it + 2 < GM_ITERS) {
            load_stage(sl, (it + 2) * GM_BK);
            cp_commit();
            sl = (sl == GM_STAGES - 1) ? 0 : sl + 1;
        }
        uint32_t base = smb + (uint32_t)(sc * GM_STAGE_F * 4);
        sc = (sc == GM_STAGES - 1) ? 0 : sc + 1;
#pragma unroll
        for (int kk = 0; kk < 4; kk++) {
            uint32_t a[2][4], b[8][2];
#pragma unroll
            for (int t = 0; t < 2; t++)
                ldsm_x4(a[t][0], a[t][1], a[t][2], a[t][3], base + aoff[t] + kk * 32);
#pragma unroll
            for (int jp = 0; jp < 4; jp++) {
                uint32_t r0, r1, r2, r3;
                ldsm_x4(r0, r1, r2, r3, base + boff[jp] + kk * 32);
                b[2 * jp][0] = r0; b[2 * jp][1] = r1;
                b[2 * jp + 1][0] = r2; b[2 * jp + 1][1] = r3;
            }
#pragma unroll
            for (int t = 0; t < 2; t++)
#pragma unroll
                for (int j = 0; j < 8; j++)
                    mma_tf32(c[t][j], a[t], b[j]);
        }
        if (it + 2 < GM_ITERS)      cp_wait1();
        else if (it + 1 < GM_ITERS) cp_wait0();
        __syncthreads();
    }

    const int g = lane >> 2;
    const int q = lane & 3;
#pragma unroll
    for (int j = 0; j < 8; j++) {
        int col = bn + wn + j * 8 + 2 * q;
        float b0 = 0.f, b1 = 0.f;
        if (BIAS) { b0 = bias[col]; b1 = bias[col + 1]; }
#pragma unroll
        for (int t = 0; t < 2; t++) {
            int row0 = bm + wm + t * 16 + g;
            float v00 = c[t][j][0] + b0, v01 = c[t][j][1] + b1;
            float v10 = c[t][j][2] + b0, v11 = c[t][j][3] + b1;
            if (ROUND) {
                v00 = tf32_rn(v00); v01 = tf32_rn(v01);
                v10 = tf32_rn(v10); v11 = tf32_rn(v11);
            }
            *reinterpret_cast<float2*>(C + (size_t)row0 * CS + col) = make_float2(v00, v01);
            *reinterpret_cast<float2*>(C + (size_t)(row0 + 8) * CS + col) = make_float2(v10, v11);
        }
    }
}

// ---------------------------------------------------------------------------
// Fused scores + softmax (tf32 mma): per CTA 64 i-rows x all 131 j x K=512.
// Q-side = q' (stride 512), K-side = rounded h (stride 512).
// BK=32 (16 iters), 3-stage cp.async pipeline.
// ---------------------------------------------------------------------------
constexpr int SC_QBYTES = 64 * 36 * 4;           // 9216
constexpr int SC_STAGE  = SC_QBYTES + 168 * 36 * 4;   // 33408
constexpr int SC_EPI    = 64 * 164 * 4;          // 41984 epilogue buffer
constexpr int SC_DYN    = (3 * SC_STAGE > SC_EPI) ? 3 * SC_STAGE : SC_EPI;  // 100224

__global__ void __launch_bounds__(256)
scores_softmax_kernel(const float* __restrict__ Q, const float* __restrict__ Hm,
                      const int* __restrict__ mask, float* __restrict__ S) {
    extern __shared__ __align__(16) char smc[];
    __shared__ int mask_s[144];
    const uint32_t smb = smem_u32(smc);
    float* Ss = reinterpret_cast<float*>(smc);   // epilogue view: [64][164]
    const int tid = threadIdx.x;
    const int wid = tid >> 5;
    const int lane = tid & 31;
    const int m0 = blockIdx.x * 64;
    const int b  = blockIdx.y;

    if (tid < 144) mask_s[tid] = (tid < Gc) ? mask[b * Gc + tid] : 1;

    const float* Qb = Q  + (size_t)b * Gc * 512;
    const float* Kb = Hm + (size_t)b * Gc * 512;

    const int wm = (wid & 1) * 32;        // 2 m-warps
    const int wn = (wid >> 1) * 40;       // 4 n-warps x 40 cols
    const int lr = lane & 7;

    float c[2][5][4];
#pragma unroll
    for (int t = 0; t < 2; t++)
#pragma unroll
        for (int n = 0; n < 5; n++)
#pragma unroll
            for (int v = 0; v < 4; v++) c[t][n][v] = 0.f;

    uint32_t aoff[2], boff[3];
#pragma unroll
    for (int t = 0; t < 2; t++)
        aoff[t] = (uint32_t)((wm + t * 16 + ((lane >> 3) & 1) * 8 + lr) * 144
                             + (lane >> 4) * 16);
#pragma unroll
    for (int jp = 0; jp < 3; jp++)
        boff[jp] = (uint32_t)(SC_QBYTES
                              + (wn + jp * 16 + ((lane >> 4) & 1) * 8 + lr) * 144
                              + ((lane >> 3) & 1) * 16);

    auto load_stage = [&](int s, int k0) {
        uint32_t qb = smb + (uint32_t)(s * SC_STAGE);
        uint32_t kb = qb + SC_QBYTES;
#pragma unroll
        for (int l = 0; l < 2; l++) {   // Q tile: 64 rows x 32 floats
            int id = tid + l * 256;
            int row = id >> 3, c4 = (id & 7) << 2;
            bool v = (m0 + row) < Gc;
            const float* src = v ? Qb + (size_t)(m0 + row) * 512 + k0 + c4 : Qb;
            cp_async16z(qb + (uint32_t)((row * 36 + c4) * 4), src, v);
        }
#pragma unroll
        for (int i = 0; i < 5; i++) {   // K tile: 160 rows x 32 floats
            int id = tid + i * 256;
            int row = id >> 3, c4 = (id & 7) << 2;
            bool v = row < Gc;
            const float* src = v ? Kb + (size_t)row * 512 + k0 + c4 : Kb;
            cp_async16z(kb + (uint32_t)((row * 36 + c4) * 4), src, v);
        }
    };

    load_stage(0, 0);   cp_commit();
    load_stage(1, 32);  cp_commit();
    cp_wait1();
    __syncthreads();

    int scur = 0, sl = 2;
    for (int it = 0; it < 16; ++it) {
        if (it + 2 < 16) {
            load_stage(sl, (it + 2) * 32);
            cp_commit();
            sl = (sl == 2) ? 0 : sl + 1;
        }
        uint32_t qb = smb + (uint32_t)(scur * SC_STAGE);
        scur = (scur == 2) ? 0 : scur + 1;
#pragma unroll
        for (int kk = 0; kk < 4; kk++) {
            uint32_t a[2][4], bfr[6][2];
#pragma unroll
            for (int t = 0; t < 2; t++)
                ldsm_x4(a[t][0], a[t][1], a[t][2], a[t][3], qb + aoff[t] + kk * 32);
#pragma unroll
            for (int jp = 0; jp < 3; jp++) {
                uint32_t r0, r1, r2, r3;
                ldsm_x4(r0, r1, r2, r3, qb + boff[jp] + kk * 32);
                bfr[2 * jp][0] = r0; bfr[2 * jp][1] = r1;
                bfr[2 * jp + 1][0] = r2; bfr[2 * jp + 1][1] = r3;
            }
#pragma unroll
            for (int t = 0; t < 2; t++)
#pragma unroll
                for (int n = 0; n < 5; n++)
                    mma_tf32(c[t][n], a[t], bfr[n]);
        }
        if (it + 2 < 16)      cp_wait1();
        else if (it + 1 < 16) cp_wait0();
        __syncthreads();
    }

    const int g = lane >> 2;
    const int qd = lane & 3;
#pragma unroll
    for (int t = 0; t < 2; t++) {
        int r0 = wm + t * 16 + g;
#pragma unroll
        for (int n = 0; n < 5; n++) {
            int col = wn + n * 8 + 2 * qd;
            *reinterpret_cast<float2*>(&Ss[r0 * 164 + col]) = make_float2(c[t][n][0], c[t][n][1]);
            *reinterpret_cast<float2*>(&Ss[(r0 + 8) * 164 + col]) = make_float2(c[t][n][2], c[t][n][3]);
        }
    }
    __syncthreads();

    const float norm = 0.04419417382415922f;   // 1/sqrt(512)
#pragma unroll
    for (int rr = 0; rr < 8; rr++) {
        int i_loc = wid * 8 + rr;
        int gi = m0 + i_loc;
        if (gi >= Gc) break;
        bool li = (gi >= LEAF_LO) && (gi < LEAF_HI);
        float v[5];
        float mx = -3.0e38f;
#pragma unroll
        for (int ch = 0; ch < 5; ch++) {
            int j = lane + ch * 32;
            float val = -3.0e38f;
            if (j < Gc) {
                float s = Ss[i_loc * 164 + j] * norm;
                bool mj = (mask_s[j] > 0) || (li && j >= LEAF_LO && j < LEAF_HI);
                val = mj ? -30.f : s;
            }
            v[ch] = val;
            mx = fmaxf(mx, val);
        }
#pragma unroll
        for (int o = 16; o; o >>= 1) mx = fmaxf(mx, __shfl_xor_sync(0xffffffffu, mx, o));
        float e[5];
        float sum = 0.f;
#pragma unroll
        for (int ch = 0; ch < 5; ch++) {
            int j = lane + ch * 32;
            e[ch] = (j < Gc) ? expf(v[ch] - mx) : 0.f;
            sum += e[ch];
        }
#pragma unroll
        for (int o = 16; o; o >>= 1) sum += __shfl_xor_sync(0xffffffffu, sum, o);
        float inv = 1.f / sum;
        float* Srow = S + ((size_t)b * Gc + gi) * SLD;
#pragma unroll
        for (int ch = 0; ch < 5; ch++) {
            int j = lane + ch * 32;
            if (j < SLD) {
                float p = 0.f;
                if (j < Gc) {
                    bool mj = (mask_s[j] > 0) || (li && j >= LEAF_LO && j < LEAF_HI);
                    p = mj ? 0.f : tf32_rn(e[ch] * inv);
                }
                Srow[j] = p;
            }
        }
    }
}

// ---------------------------------------------------------------------------
// heads (tf32 mma): X[i,n] = sum_j S[i,j] * h[j,n].  K=144 (zero-padded).
// A = S via ldsm, B = rounded h via direct LDS.32 fragments. Output tf32-rounded.
// ---------------------------------------------------------------------------
constexpr int HD_STAGE = 5120 + 8448;            // S(64x20f) + V(16x132f) bytes
constexpr int HD_DYN   = 2 * HD_STAGE;           // 27136

__global__ void __launch_bounds__(256)
heads_kernel(const float* __restrict__ S, const float* __restrict__ Hm,
             float* __restrict__ X) {
    extern __shared__ __align__(16) char smc[];
    const uint32_t smb = smem_u32(smc);
    const int tid = threadIdx.x;
    const int wid = tid >> 5;
    const int lane = tid & 31;
    const int n0 = blockIdx.x * 128;
    const int m0 = blockIdx.y * 64;
    const int b  = blockIdx.z;

    const float* Sb = S  + (size_t)b * Gc * SLD;
    const float* Vb = Hm + (size_t)b * Gc * 512;

    const int wm = (wid & 1) * 32;
    const int wn = (wid >> 1) * 32;
    const int lr = lane & 7;

    float c[2][4][4];
#pragma unroll
    for (int t = 0; t < 2; t++)
#pragma unroll
        for (int n = 0; n < 4; n++)
#pragma unroll
            for (int v = 0; v < 4; v++) c[t][n][v] = 0.f;

    uint32_t aoff[2];
#pragma unroll
    for (int t = 0; t < 2; t++)
        aoff[t] = (uint32_t)((wm + t * 16 + ((lane >> 3) & 1) * 8 + lr) * 80
                             + (lane >> 4) * 16);

    auto load_stage = [&](int s, int k0) {
        uint32_t sbse = smb + (uint32_t)(s * HD_STAGE);
        uint32_t vbse = sbse + 5120;
        {   // S tile: 64 rows x 16 floats
            int row = tid >> 2, c4 = (tid & 3) << 2;
            bool v = (m0 + row) < Gc;
            const float* src = v ? Sb + (size_t)(m0 + row) * SLD + k0 + c4 : Sb;
            cp_async16z(sbse + (uint32_t)((row * 20 + c4) * 4), src, v);
        }
#pragma unroll
        for (int i = 0; i < 2; i++) {   // h tile: 16 k-rows x 128 n
            int id = tid + i * 256;
            int row = id >> 5, c4 = (id & 31) << 2;
            bool v = (k0 + row) < Gc;
            const float* src = v ? Vb + (size_t)(k0 + row) * 512 + n0 + c4 : Vb;
            cp_async16z(vbse + (uint32_t)((row * 132 + c4) * 4), src, v);
        }
    };

    load_stage(0, 0);
    cp_commit();
    cp_wait0();
    __syncthreads();

    for (int it = 0; it < 9; ++it) {            // K = 144 = 9 x 16
        if (it + 1 < 9) {
            load_stage((it + 1) & 1, (it + 1) * 16);
            cp_commit();
        }
        uint32_t sbse = smb + (uint32_t)((it & 1) * HD_STAGE);
        const float* Vsm = reinterpret_cast<const float*>(smc + (it & 1) * HD_STAGE + 5120);
#pragma unroll
        for (int kk = 0; kk < 2; kk++) {
            uint32_t a[2][4];
#pragma unroll
            for (int t = 0; t < 2; t++)
                ldsm_x4(a[t][0], a[t][1], a[t][2], a[t][3], sbse + aoff[t] + kk * 32);
#pragma unroll
            for (int n = 0; n < 4; n++) {
                uint32_t bfr[2];
                int krow = kk * 8 + (lane & 3);
                int ncol = wn + n * 8 + (lane >> 2);
                bfr[0] = __float_as_uint(Vsm[krow * 132 + ncol]);
                bfr[1] = __float_as_uint(Vsm[(krow + 4) * 132 + ncol]);
#pragma unroll
                for (int t = 0; t < 2; t++)
                    mma_tf32(c[t][n], a[t], bfr);
            }
        }
        if (it + 1 < 9) cp_wait0();
        __syncthreads();
    }

    const int g = lane >> 2;
    const int qd = lane & 3;
#pragma unroll
    for (int t = 0; t < 2; t++) {
#pragma unroll
        for (int n = 0; n < 4; n++) {
            int col = n0 + wn + n * 8 + 2 * qd;
            int i0r = m0 + wm + t * 16 + g;
            if (i0r < Gc)
                *reinterpret_cast<float2*>(X + ((size_t)b * Gc + i0r) * 512 + col) =
                    make_float2(tf32_rn(c[t][n][0]), tf32_rn(c[t][n][1]));
            if (i0r + 8 < Gc)
                *reinterpret_cast<float2*>(X + ((size_t)b * Gc + i0r + 8) * 512 + col) =
                    make_float2(tf32_rn(c[t][n][2]), tf32_rn(c[t][n][3]));
        }
    }
}

// ---------------------------------------------------------------------------
// Launch
// ---------------------------------------------------------------------------
extern "C" void kernel_launch(void* const* d_in, const int* in_sizes, int n_in,
                              void* d_out, int out_size) {
    const float* q    = (const float*)d_in[0];
    const int*   mask = (const int*)d_in[1];
    const float* h    = (const float*)d_in[4];
    const float* Wq   = (const float*)d_in[5];
    const float* Wk   = (const float*)d_in[6];
    const float* Wv   = (const float*)d_in[7];
    const float* Wo   = (const float*)d_in[8];
    const float* bo   = (const float*)d_in[9];
    float* out = (float*)d_out;

    float *gQ, *gH, *gS, *gqr, *ghr, *gWr, *gWM;
    cudaGetSymbolAddress((void**)&gQ,  g_Q);
    cudaGetSymbolAddress((void**)&gH,  g_H);
    cudaGetSymbolAddress((void**)&gS,  g_S);
    cudaGetSymbolAddress((void**)&gqr, g_qr);
    cudaGetSymbolAddress((void**)&ghr, g_hr);
    cudaGetSymbolAddress((void**)&gWr, g_Wr);
    cudaGetSymbolAddress((void**)&gWM, g_WM);
    float* gWqT = gWr;                    // transposed+rounded Wq
    float* gWkT = gWr + 1 * 512 * 512;    // transposed+rounded Wk
    float* gWvT = gWr + 2 * 512 * 512;    // transposed+rounded Wv
    float* gWo_ = gWr + 3 * 512 * 512;    // rounded Wo (as-is)
    float* gWm  = gWM;                    // Wm[i,k] = M[k,i],  M = Wq^T Wk
    float* gWn  = gWM + 512 * 512;        // Wn[j,i] = N[i,j],  N = Wv^T Wo^T

    cudaFuncSetAttribute(mma_gemm_kernel<false, true>,
                         cudaFuncAttributeMaxDynamicSharedMemorySize, GM_SMEM);
    cudaFuncSetAttribute(mma_gemm_kernel<true, false>,
                         cudaFuncAttributeMaxDynamicSharedMemorySize, GM_SMEM);
    cudaFuncSetAttribute(scores_softmax_kernel,
                         cudaFuncAttributeMaxDynamicSharedMemorySize, SC_DYN);

    // 0) weight prep: WqT, WkT, WvT (transpose+round), Wo (round)
    prep_weights_kernel<<<dim3(16, 16, 4), dim3(32, 8)>>>(Wq, Wk, Wv, Wo, gWr);

    // 1-2) round activations
    int n4_big = (MTOT * Dd) / 4;
    round_tf32_kernel<<<4096, 256>>>((const float4*)q, (float4*)gqr, n4_big);
    round_tf32_kernel<<<4096, 256>>>((const float4*)h, (float4*)ghr, n4_big);

    // 3) Wm[i,k] = sum_j WkT[i,j] * WqT[k,j]   (tiny 512^3)
    mma_gemm_kernel<false, true><<<dim3(4, 4), 256, GM_SMEM>>>(gWkT, gWqT, nullptr, gWm, 512);
    // 4) Wn[j,i] = sum_k Wo[j,k] * WvT[i,k]    (tiny 512^3)
    mma_gemm_kernel<false, true><<<dim3(4, 4), 256, GM_SMEM>>>(gWo_, gWvT, nullptr, gWn, 512);

    // 5) q' = q @ Wm^T  (big; replaces Q AND K projections)
    mma_gemm_kernel<false, true><<<dim3(4, MTOT / 128), 256, GM_SMEM>>>(
        gqr, gWm, nullptr, gQ, 512);

    // 6) fused scores + softmax vs raw rounded h
    scores_softmax_kernel<<<dim3(3, Bc), 256, SC_DYN>>>(gQ, ghr, mask, gS);

    // 7) X = attn @ h  (replaces V projection input)
    heads_kernel<<<dim3(4, 3, Bc), 256, HD_DYN>>>(gS, ghr, gH);

    // 8) out = X @ Wn^T + bias  (folds Wv^T Wo^T)
    mma_gemm_kernel<true, false><<<dim3(4, MTOT / 128), 256, GM_SMEM>>>(
        gH, gWn, bo, out, 512);
}

// round 8
// speedup vs baseline: 5.5224x; 1.0426x over previous
#include <cuda_runtime.h>
#include <math.h>
#include <stdint.h>

// ---------------------------------------------------------------------------
// Problem constants
// ---------------------------------------------------------------------------
constexpr int Bc   = 512;          // batch
constexpr int Gc   = 131;          // graph size
constexpr int Dd   = 512;          // dims
constexpr int MTOT = Bc * Gc;      // 67072
constexpr int SLD  = 144;          // padded score row stride (zero-filled 131..143)
constexpr int LEAF_LO = 80;
constexpr int LEAF_HI = 130;

// Scratch (device globals: allocation-free)
__device__ float g_Q [(size_t)MTOT * Dd];       // q' = q·M
__device__ float g_H [(size_t)MTOT * Dd];       // X  = attn·h
__device__ float g_S [(size_t)Bc * Gc * SLD];
__device__ float g_Wr[4][512 * 512];            // WqT, WkT, WvT, Wo (tf32-rounded)
__device__ float g_WM[2][512 * 512];            // Wm, Wn (folded weights)

// ---------------------------------------------------------------------------
// PTX helpers (baseline sm_80 PTX only — valid for compute_103)
// ---------------------------------------------------------------------------
__device__ __forceinline__ float tf32_rn(float x) {
    uint32_t u;
    asm("cvt.rna.tf32.f32 %0, %1;" : "=r"(u) : "f"(x));
    return __uint_as_float(u);
}
__device__ __forceinline__ uint32_t tf32_bits_u(uint32_t x) {
    uint32_t u;
    asm("cvt.rna.tf32.f32 %0, %1;" : "=r"(u) : "f"(__uint_as_float(x)));
    return u;
}
__device__ __forceinline__ uint32_t tf32_bits_f(float x) {
    uint32_t u;
    asm("cvt.rna.tf32.f32 %0, %1;" : "=r"(u) : "f"(x));
    return u;
}
__device__ __forceinline__ uint32_t smem_u32(const void* p) {
    return (uint32_t)__cvta_generic_to_shared(p);
}
__device__ __forceinline__ void cp_async16(uint32_t sdst, const void* gsrc) {
    asm volatile("cp.async.cg.shared.global [%0], [%1], 16;" :: "r"(sdst), "l"(gsrc));
}
__device__ __forceinline__ void cp_async16z(uint32_t sdst, const void* gsrc, bool valid) {
    int sz = valid ? 16 : 0;
    asm volatile("cp.async.cg.shared.global [%0], [%1], 16, %2;"
                 :: "r"(sdst), "l"(gsrc), "r"(sz));
}
__device__ __forceinline__ void cp_commit() { asm volatile("cp.async.commit_group;"); }
__device__ __forceinline__ void cp_wait0()  { asm volatile("cp.async.wait_group 0;"); }
__device__ __forceinline__ void cp_wait1()  { asm volatile("cp.async.wait_group 1;"); }

__device__ __forceinline__ void ldsm_x4(uint32_t& r0, uint32_t& r1, uint32_t& r2,
                                        uint32_t& r3, uint32_t addr) {
    asm volatile("ldmatrix.sync.aligned.m8n8.x4.shared.b16 {%0,%1,%2,%3}, [%4];"
                 : "=r"(r0), "=r"(r1), "=r"(r2), "=r"(r3) : "r"(addr));
}
__device__ __forceinline__ void mma_tf32(float* c, const uint32_t* a, const uint32_t* b) {
    asm volatile(
        "mma.sync.aligned.m16n8k8.row.col.f32.tf32.tf32.f32 "
        "{%0,%1,%2,%3}, {%4,%5,%6,%7}, {%8,%9}, {%0,%1,%2,%3};"
        : "+f"(c[0]), "+f"(c[1]), "+f"(c[2]), "+f"(c[3])
        : "r"(a[0]), "r"(a[1]), "r"(a[2]), "r"(a[3]), "r"(b[0]), "r"(b[1]));
}

// ---------------------------------------------------------------------------
// Weight prep: z=0,1,2 -> transpose+round Wq,Wk,Wv; z=3 -> plain round Wo.
// ---------------------------------------------------------------------------
__global__ void prep_weights_kernel(const float* __restrict__ w0, const float* __restrict__ w1,
                                    const float* __restrict__ w2, const float* __restrict__ w3,
                                    float* __restrict__ out) {
    __shared__ float tile[32][33];
    const int z = blockIdx.z;
    const float* in = (z == 0) ? w0 : (z == 1) ? w1 : (z == 2) ? w2 : w3;
    float* o = out + (size_t)z * 512 * 512;
    const int tx = threadIdx.x, ty = threadIdx.y;
    const int x = blockIdx.x * 32 + tx;
    const int y0 = blockIdx.y * 32;
    if (z < 3) {
#pragma unroll
        for (int j = 0; j < 32; j += 8)
            tile[ty + j][tx] = in[(size_t)(y0 + ty + j) * 512 + x];
        __syncthreads();
        const int x2 = y0 + tx;
        const int y2 = blockIdx.x * 32;
#pragma unroll
        for (int j = 0; j < 32; j += 8)
            o[(size_t)(y2 + ty + j) * 512 + x2] = tf32_rn(tile[tx][ty + j]);
    } else {
#pragma unroll
        for (int j = 0; j < 32; j += 8)
            o[(size_t)(y0 + ty + j) * 512 + x] = tf32_rn(in[(size_t)(y0 + ty + j) * 512 + x]);
    }
}

// ---------------------------------------------------------------------------
// tf32 mma.sync GEMM-NT body: C[M,N] = A[M,512] @ W[N,512]^T (+bias)
// BM=128, BN=128, BK=32, 256 threads. 3-stage cp.async pipeline.
// ROUND_A: A is raw fp32; round fragments in-register before mma.
// ---------------------------------------------------------------------------
constexpr int GM_BK = 32;
constexpr int GM_ROW = GM_BK + 4;                 // 36 floats / row
constexpr int GM_STAGE_F = 256 * GM_ROW;          // 9216 floats
constexpr int GM_STAGES = 3;
constexpr int GM_SMEM = GM_STAGES * GM_STAGE_F * 4;   // 110592 bytes
constexpr int GM_ITERS = 512 / GM_BK;             // 16

template <bool BIAS, bool ROUND, bool ROUND_A>
__device__ __forceinline__ void gemm_body(const float* __restrict__ A,
                                          const float* __restrict__ W,
                                          const float* __restrict__ bias,
                                          float* __restrict__ C, int CS,
                                          int bm, int bn) {
    extern __shared__ __align__(16) float sm[];
    const uint32_t smb = smem_u32(sm);
    const int tid = threadIdx.x;
    const int wid = tid >> 5;
    const int lane = tid & 31;
    const int wm = (wid & 3) * 32;
    const int wn = (wid >> 2) * 64;

    const float* Ag = A + (size_t)bm * 512;
    const float* Wg = W + (size_t)bn * 512;

    float c[2][8][4];
#pragma unroll
    for (int t = 0; t < 2; t++)
#pragma unroll
        for (int j = 0; j < 8; j++)
#pragma unroll
            for (int v = 0; v < 4; v++) c[t][j][v] = 0.f;

    const int lr = lane & 7;
    uint32_t aoff[2], boff[4];
#pragma unroll
    for (int t = 0; t < 2; t++)
        aoff[t] = (uint32_t)((wm + t * 16 + ((lane >> 3) & 1) * 8 + lr) * (GM_ROW * 4)
                             + (lane >> 4) * 16);
#pragma unroll
    for (int jp = 0; jp < 4; jp++)
        boff[jp] = (uint32_t)(128 * GM_ROW * 4
                              + (wn + jp * 16 + ((lane >> 4) & 1) * 8 + lr) * (GM_ROW * 4)
                              + ((lane >> 3) & 1) * 16);

    auto load_stage = [&](int s, int k0) {
        uint32_t base = smb + (uint32_t)(s * GM_STAGE_F * 4);
#pragma unroll
        for (int i = 0; i < 4; i++) {
            int id = tid + i * 256;
            int row = id >> 3, c4 = (id & 7) << 2;
            cp_async16(base + (uint32_t)((row * GM_ROW + c4) * 4),
                       Ag + (size_t)row * 512 + k0 + c4);
        }
#pragma unroll
        for (int i = 0; i < 4; i++) {
            int id = tid + i * 256;
            int row = id >> 3, c4 = (id & 7) << 2;
            cp_async16(base + (uint32_t)(((128 + row) * GM_ROW + c4) * 4),
                       Wg + (size_t)row * 512 + k0 + c4);
        }
    };

    load_stage(0, 0);           cp_commit();
    load_stage(1, GM_BK);       cp_commit();
    cp_wait1();
    __syncthreads();

    int sc = 0;
    int sl = 2;
    for (int it = 0; it < GM_ITERS; ++it) {
        if (it + 2 < GM_ITERS) {
            load_stage(sl, (it + 2) * GM_BK);
            cp_commit();
            sl = (sl == GM_STAGES - 1) ? 0 : sl + 1;
        }
        uint32_t base = smb + (uint32_t)(sc * GM_STAGE_F * 4);
        sc = (sc == GM_STAGES - 1) ? 0 : sc + 1;
#pragma unroll
        for (int kk = 0; kk < 4; kk++) {
            uint32_t a[2][4], b[8][2];
#pragma unroll
            for (int t = 0; t < 2; t++) {
                ldsm_x4(a[t][0], a[t][1], a[t][2], a[t][3], base + aoff[t] + kk * 32);
                if (ROUND_A) {
#pragma unroll
                    for (int r = 0; r < 4; r++) a[t][r] = tf32_bits_u(a[t][r]);
                }
            }
#pragma unroll
            for (int jp = 0; jp < 4; jp++) {
                uint32_t r0, r1, r2, r3;
                ldsm_x4(r0, r1, r2, r3, base + boff[jp] + kk * 32);
                b[2 * jp][0] = r0; b[2 * jp][1] = r1;
                b[2 * jp + 1][0] = r2; b[2 * jp + 1][1] = r3;
            }
#pragma unroll
            for (int t = 0; t < 2; t++)
#pragma unroll
                for (int j = 0; j < 8; j++)
                    mma_tf32(c[t][j], a[t], b[j]);
        }
        if (it + 2 < GM_ITERS)      cp_wait1();
        else if (it + 1 < GM_ITERS) cp_wait0();
        __syncthreads();
    }

    const int g = lane >> 2;
    const int q = lane & 3;
#pragma unroll
    for (int j = 0; j < 8; j++) {
        int col = bn + wn + j * 8 + 2 * q;
        float b0 = 0.f, b1 = 0.f;
        if (BIAS) { b0 = bias[col]; b1 = bias[col + 1]; }
#pragma unroll
        for (int t = 0; t < 2; t++) {
            int row0 = bm + wm + t * 16 + g;
            float v00 = c[t][j][0] + b0, v01 = c[t][j][1] + b1;
            float v10 = c[t][j][2] + b0, v11 = c[t][j][3] + b1;
            if (ROUND) {
                v00 = tf32_rn(v00); v01 = tf32_rn(v01);
                v10 = tf32_rn(v10); v11 = tf32_rn(v11);
            }
            *reinterpret_cast<float2*>(C + (size_t)row0 * CS + col) = make_float2(v00, v01);
            *reinterpret_cast<float2*>(C + (size_t)(row0 + 8) * CS + col) = make_float2(v10, v11);
        }
    }
}

template <bool BIAS, bool ROUND, bool ROUND_A>
__global__ void __launch_bounds__(256)
mma_gemm_kernel(const float* __restrict__ A, const float* __restrict__ W,
                const float* __restrict__ bias, float* __restrict__ C, int CS) {
    gemm_body<BIAS, ROUND, ROUND_A>(A, W, bias, C, CS,
                                    blockIdx.y * 128, blockIdx.x * 128);
}

// both folded-weight 512^3 GEMMs in one launch (z selects)
__global__ void __launch_bounds__(256)
tiny2_gemm_kernel(const float* __restrict__ A0, const float* __restrict__ W0,
                  float* __restrict__ C0,
                  const float* __restrict__ A1, const float* __restrict__ W1,
                  float* __restrict__ C1) {
    if (blockIdx.z == 0)
        gemm_body<false, true, false>(A0, W0, nullptr, C0, 512,
                                      blockIdx.y * 128, blockIdx.x * 128);
    else
        gemm_body<false, true, false>(A1, W1, nullptr, C1, 512,
                                      blockIdx.y * 128, blockIdx.x * 128);
}

// ---------------------------------------------------------------------------
// Fused scores + softmax: per CTA 64 i-rows (rows 0..127 only) x 131 j x K=512.
// K-side = RAW h; fragments rounded in-register.
// ---------------------------------------------------------------------------
constexpr int SC_QBYTES = 64 * 36 * 4;                // 9216
constexpr int SC_STAGE  = SC_QBYTES + 168 * 36 * 4;   // 33408
constexpr int SC_EPI    = 64 * 164 * 4;               // 41984
constexpr int SC_DYN    = (3 * SC_STAGE > SC_EPI) ? 3 * SC_STAGE : SC_EPI;

__global__ void __launch_bounds__(256)
scores_softmax_kernel(const float* __restrict__ Q, const float* __restrict__ Hm,
                      const int* __restrict__ mask, float* __restrict__ S) {
    extern __shared__ __align__(16) char smc[];
    __shared__ int mask_s[144];
    const uint32_t smb = smem_u32(smc);
    float* Ss = reinterpret_cast<float*>(smc);   // epilogue view: [64][164]
    const int tid = threadIdx.x;
    const int wid = tid >> 5;
    const int lane = tid & 31;
    const int m0 = blockIdx.x * 64;              // 0 or 64 (rows always valid)
    const int b  = blockIdx.y;

    if (tid < 144) mask_s[tid] = (tid < Gc) ? mask[b * Gc + tid] : 1;

    const float* Qb = Q  + (size_t)b * Gc * 512;
    const float* Kb = Hm + (size_t)b * Gc * 512;

    const int wm = (wid & 1) * 32;
    const int wn = (wid >> 1) * 40;
    const int lr = lane & 7;

    float c[2][5][4];
#pragma unroll
    for (int t = 0; t < 2; t++)
#pragma unroll
        for (int n = 0; n < 5; n++)
#pragma unroll
            for (int v = 0; v < 4; v++) c[t][n][v] = 0.f;

    uint32_t aoff[2], boff[3];
#pragma unroll
    for (int t = 0; t < 2; t++)
        aoff[t] = (uint32_t)((wm + t * 16 + ((lane >> 3) & 1) * 8 + lr) * 144
                             + (lane >> 4) * 16);
#pragma unroll
    for (int jp = 0; jp < 3; jp++)
        boff[jp] = (uint32_t)(SC_QBYTES
                              + (wn + jp * 16 + ((lane >> 4) & 1) * 8 + lr) * 144
                              + ((lane >> 3) & 1) * 16);

    auto load_stage = [&](int s, int k0) {
        uint32_t qb = smb + (uint32_t)(s * SC_STAGE);
        uint32_t kb = qb + SC_QBYTES;
#pragma unroll
        for (int l = 0; l < 2; l++) {   // Q tile: 64 rows x 32 floats (all valid)
            int id = tid + l * 256;
            int row = id >> 3, c4 = (id & 7) << 2;
            cp_async16(qb + (uint32_t)((row * 36 + c4) * 4),
                       Qb + (size_t)(m0 + row) * 512 + k0 + c4);
        }
#pragma unroll
        for (int i = 0; i < 5; i++) {   // K tile: 160 rows x 32 floats
            int id = tid + i * 256;
            int row = id >> 3, c4 = (id & 7) << 2;
            bool v = row < Gc;
            const float* src = v ? Kb + (size_t)row * 512 + k0 + c4 : Kb;
            cp_async16z(kb + (uint32_t)((row * 36 + c4) * 4), src, v);
        }
    };

    load_stage(0, 0);   cp_commit();
    load_stage(1, 32);  cp_commit();
    cp_wait1();
    __syncthreads();

    int scur = 0, sl = 2;
    for (int it = 0; it < 16; ++it) {
        if (it + 2 < 16) {
            load_stage(sl, (it + 2) * 32);
            cp_commit();
            sl = (sl == 2) ? 0 : sl + 1;
        }
        uint32_t qb = smb + (uint32_t)(scur * SC_STAGE);
        scur = (scur == 2) ? 0 : scur + 1;
#pragma unroll
        for (int kk = 0; kk < 4; kk++) {
            uint32_t a[2][4], bfr[6][2];
#pragma unroll
            for (int t = 0; t < 2; t++)
                ldsm_x4(a[t][0], a[t][1], a[t][2], a[t][3], qb + aoff[t] + kk * 32);
#pragma unroll
            for (int jp = 0; jp < 3; jp++) {
                uint32_t r0, r1, r2, r3;
                ldsm_x4(r0, r1, r2, r3, qb + boff[jp] + kk * 32);
                bfr[2 * jp][0] = tf32_bits_u(r0); bfr[2 * jp][1] = tf32_bits_u(r1);
                bfr[2 * jp + 1][0] = tf32_bits_u(r2); bfr[2 * jp + 1][1] = tf32_bits_u(r3);
            }
#pragma unroll
            for (int t = 0; t < 2; t++)
#pragma unroll
                for (int n = 0; n < 5; n++)
                    mma_tf32(c[t][n], a[t], bfr[n]);
        }
        if (it + 2 < 16)      cp_wait1();
        else if (it + 1 < 16) cp_wait0();
        __syncthreads();
    }

    const int g = lane >> 2;
    const int qd = lane & 3;
#pragma unroll
    for (int t = 0; t < 2; t++) {
        int r0 = wm + t * 16 + g;
#pragma unroll
        for (int n = 0; n < 5; n++) {
            int col = wn + n * 8 + 2 * qd;
            *reinterpret_cast<float2*>(&Ss[r0 * 164 + col]) = make_float2(c[t][n][0], c[t][n][1]);
            *reinterpret_cast<float2*>(&Ss[(r0 + 8) * 164 + col]) = make_float2(c[t][n][2], c[t][n][3]);
        }
    }
    __syncthreads();

    const float norm = 0.04419417382415922f;   // 1/sqrt(512)
#pragma unroll
    for (int rr = 0; rr < 8; rr++) {
        int i_loc = wid * 8 + rr;
        int gi = m0 + i_loc;                    // always < 128
        bool li = (gi >= LEAF_LO) && (gi < LEAF_HI);
        float v[5];
        float mx = -3.0e38f;
#pragma unroll
        for (int ch = 0; ch < 5; ch++) {
            int j = lane + ch * 32;
            float val = -3.0e38f;
            if (j < Gc) {
                float s = Ss[i_loc * 164 + j] * norm;
                bool mj = (mask_s[j] > 0) || (li && j >= LEAF_LO && j < LEAF_HI);
                val = mj ? -30.f : s;
            }
            v[ch] = val;
            mx = fmaxf(mx, val);
        }
#pragma unroll
        for (int o = 16; o; o >>= 1) mx = fmaxf(mx, __shfl_xor_sync(0xffffffffu, mx, o));
        float e[5];
        float sum = 0.f;
#pragma unroll
        for (int ch = 0; ch < 5; ch++) {
            int j = lane + ch * 32;
            e[ch] = (j < Gc) ? expf(v[ch] - mx) : 0.f;
            sum += e[ch];
        }
#pragma unroll
        for (int o = 16; o; o >>= 1) sum += __shfl_xor_sync(0xffffffffu, sum, o);
        float inv = 1.f / sum;
        float* Srow = S + ((size_t)b * Gc + gi) * SLD;
#pragma unroll
        for (int ch = 0; ch < 5; ch++) {
            int j = lane + ch * 32;
            if (j < SLD) {
                float p = 0.f;
                if (j < Gc) {
                    bool mj = (mask_s[j] > 0) || (li && j >= LEAF_LO && j < LEAF_HI);
                    p = mj ? 0.f : tf32_rn(e[ch] * inv);
                }
                Srow[j] = p;
            }
        }
    }
}

// ---------------------------------------------------------------------------
// heads (tf32 mma): X[i,n] = sum_j S[i,j] * h[j,n]; rows 0..127 only.
// B = RAW h via LDS.32, rounded in-register. Output tf32-rounded.
// ---------------------------------------------------------------------------
constexpr int HD_STAGE = 5120 + 8448;
constexpr int HD_DYN   = 2 * HD_STAGE;           // 27136

__global__ void __launch_bounds__(256)
heads_kernel(const float* __restrict__ S, const float* __restrict__ Hm,
             float* __restrict__ X) {
    extern __shared__ __align__(16) char smc[];
    const uint32_t smb = smem_u32(smc);
    const int tid = threadIdx.x;
    const int wid = tid >> 5;
    const int lane = tid & 31;
    const int n0 = blockIdx.x * 128;
    const int m0 = blockIdx.y * 64;              // 0 or 64
    const int b  = blockIdx.z;

    const float* Sb = S  + (size_t)b * Gc * SLD;
    const float* Vb = Hm + (size_t)b * Gc * 512;

    const int wm = (wid & 1) * 32;
    const int wn = (wid >> 1) * 32;
    const int lr = lane & 7;

    float c[2][4][4];
#pragma unroll
    for (int t = 0; t < 2; t++)
#pragma unroll
        for (int n = 0; n < 4; n++)
#pragma unroll
            for (int v = 0; v < 4; v++) c[t][n][v] = 0.f;

    uint32_t aoff[2];
#pragma unroll
    for (int t = 0; t < 2; t++)
        aoff[t] = (uint32_t)((wm + t * 16 + ((lane >> 3) & 1) * 8 + lr) * 80
                             + (lane >> 4) * 16);

    auto load_stage = [&](int s, int k0) {
        uint32_t sbse = smb + (uint32_t)(s * HD_STAGE);
        uint32_t vbse = sbse + 5120;
        {   // S tile: 64 rows x 16 floats (rows always valid)
            int row = tid >> 2, c4 = (tid & 3) << 2;
            cp_async16(sbse + (uint32_t)((row * 20 + c4) * 4),
                       Sb + (size_t)(m0 + row) * SLD + k0 + c4);
        }
#pragma unroll
        for (int i = 0; i < 2; i++) {   // h tile: 16 k-rows x 128 n
            int id = tid + i * 256;
            int row = id >> 5, c4 = (id & 31) << 2;
            bool v = (k0 + row) < Gc;
            const float* src = v ? Vb + (size_t)(k0 + row) * 512 + n0 + c4 : Vb;
            cp_async16z(vbse + (uint32_t)((row * 132 + c4) * 4), src, v);
        }
    };

    load_stage(0, 0);
    cp_commit();
    cp_wait0();
    __syncthreads();

    for (int it = 0; it < 9; ++it) {            // K = 144 = 9 x 16
        if (it + 1 < 9) {
            load_stage((it + 1) & 1, (it + 1) * 16);
            cp_commit();
        }
        uint32_t sbse = smb + (uint32_t)((it & 1) * HD_STAGE);
        const float* Vsm = reinterpret_cast<const float*>(smc + (it & 1) * HD_STAGE + 5120);
#pragma unroll
        for (int kk = 0; kk < 2; kk++) {
            uint32_t a[2][4];
#pragma unroll
            for (int t = 0; t < 2; t++)
                ldsm_x4(a[t][0], a[t][1], a[t][2], a[t][3], sbse + aoff[t] + kk * 32);
#pragma unroll
            for (int n = 0; n < 4; n++) {
                uint32_t bfr[2];
                int krow = kk * 8 + (lane & 3);
                int ncol = wn + n * 8 + (lane >> 2);
                bfr[0] = tf32_bits_f(Vsm[krow * 132 + ncol]);
                bfr[1] = tf32_bits_f(Vsm[(krow + 4) * 132 + ncol]);
#pragma unroll
                for (int t = 0; t < 2; t++)
                    mma_tf32(c[t][n], a[t], bfr);
            }
        }
        if (it + 1 < 9) cp_wait0();
        __syncthreads();
    }

    const int g = lane >> 2;
    const int qd = lane & 3;
#pragma unroll
    for (int t = 0; t < 2; t++) {
#pragma unroll
        for (int n = 0; n < 4; n++) {
            int col = n0 + wn + n * 8 + 2 * qd;
            int i0r = m0 + wm + t * 16 + g;     // always <= 127
            *reinterpret_cast<float2*>(X + ((size_t)b * Gc + i0r) * 512 + col) =
                make_float2(tf32_rn(c[t][n][0]), tf32_rn(c[t][n][1]));
            *reinterpret_cast<float2*>(X + ((size_t)b * Gc + i0r + 8) * 512 + col) =
                make_float2(tf32_rn(c[t][n][2]), tf32_rn(c[t][n][3]));
        }
    }
}

// ---------------------------------------------------------------------------
// Tail: rows 128..130 per batch — scores, softmax, X in one SIMT kernel.
// One CTA per batch, 256 threads.
// ---------------------------------------------------------------------------
__global__ void __launch_bounds__(256)
tail_kernel(const float* __restrict__ Q, const float* __restrict__ Hm,
            const int* __restrict__ mask, float* __restrict__ X) {
    __shared__ float qs[3][512];
    __shared__ float ps[3][132];
    __shared__ int mk[132];
    const int b = blockIdx.x;
    const int tid = threadIdx.x;
    const int wid = tid >> 5;
    const int lane = tid & 31;
    const float* Qb = Q  + ((size_t)b * Gc + 128) * 512;
    const float* hb = Hm + (size_t)b * Gc * 512;

    for (int i = tid; i < 3 * 512; i += 256) qs[i >> 9][i & 511] = Qb[i];
    if (tid < 132) mk[tid] = (tid < Gc) ? mask[b * Gc + tid] : 1;
    __syncthreads();

    // phase 1: raw scores for 3 rows (warp per j, strided)
    for (int j = wid; j < Gc; j += 8) {
        const float* hj = hb + (size_t)j * 512;
        float a0 = 0.f, a1 = 0.f, a2 = 0.f;
#pragma unroll
        for (int k = 0; k < 16; k++) {
            int idx = lane + k * 32;
            float hv = hj[idx];
            a0 = fmaf(hv, qs[0][idx], a0);
            a1 = fmaf(hv, qs[1][idx], a1);
            a2 = fmaf(hv, qs[2][idx], a2);
        }
#pragma unroll
        for (int o = 16; o; o >>= 1) {
            a0 += __shfl_xor_sync(0xffffffffu, a0, o);
            a1 += __shfl_xor_sync(0xffffffffu, a1, o);
            a2 += __shfl_xor_sync(0xffffffffu, a2, o);
        }
        if (lane == 0) { ps[0][j] = a0; ps[1][j] = a1; ps[2][j] = a2; }
    }
    __syncthreads();

    // phase 2: softmax rows 128..130 (warp w < 3 handles row 128+w)
    if (wid < 3) {
        const int gi = 128 + wid;
        const bool li = (gi >= LEAF_LO) && (gi < LEAF_HI);
        const float norm = 0.04419417382415922f;
        float v[5];
        float mx = -3.0e38f;
#pragma unroll
        for (int ch = 0; ch < 5; ch++) {
            int j = lane + ch * 32;
            float val = -3.0e38f;
            if (j < Gc) {
                bool mj = (mk[j] > 0) || (li && j >= LEAF_LO && j < LEAF_HI);
                val = mj ? -30.f : ps[wid][j] * norm;
            }
            v[ch] = val;
            mx = fmaxf(mx, val);
        }
#pragma unroll
        for (int o = 16; o; o >>= 1) mx = fmaxf(mx, __shfl_xor_sync(0xffffffffu, mx, o));
        float e[5];
        float sum = 0.f;
#pragma unroll
        for (int ch = 0; ch < 5; ch++) {
            int j = lane + ch * 32;
            e[ch] = (j < Gc) ? expf(v[ch] - mx) : 0.f;
            sum += e[ch];
        }
#pragma unroll
        for (int o = 16; o; o >>= 1) sum += __shfl_xor_sync(0xffffffffu, sum, o);
        float inv = 1.f / sum;
#pragma unroll
        for (int ch = 0; ch < 5; ch++) {
            int j = lane + ch * 32;
            if (j < Gc) {
                bool mj = (mk[j] > 0) || (li && j >= LEAF_LO && j < LEAF_HI);
                ps[wid][j] = mj ? 0.f : e[ch] * inv;
            }
        }
    }
    __syncthreads();

    // phase 3: X[i, n] = sum_j p[i][j] * h[j][n], n = tid and tid+256
    float acc[3][2] = {{0.f, 0.f}, {0.f, 0.f}, {0.f, 0.f}};
    for (int j = 0; j < Gc; j++) {
        float p0 = ps[0][j], p1 = ps[1][j], p2 = ps[2][j];
        float h0 = hb[(size_t)j * 512 + tid];
        float h1 = hb[(size_t)j * 512 + tid + 256];
        acc[0][0] = fmaf(p0, h0, acc[0][0]); acc[0][1] = fmaf(p0, h1, acc[0][1]);
        acc[1][0] = fmaf(p1, h0, acc[1][0]); acc[1][1] = fmaf(p1, h1, acc[1][1]);
        acc[2][0] = fmaf(p2, h0, acc[2][0]); acc[2][1] = fmaf(p2, h1, acc[2][1]);
    }
    float* Xb = X + ((size_t)b * Gc + 128) * 512;
#pragma unroll
    for (int i = 0; i < 3; i++) {
        Xb[(size_t)i * 512 + tid]       = tf32_rn(acc[i][0]);
        Xb[(size_t)i * 512 + tid + 256] = tf32_rn(acc[i][1]);
    }
}

// ---------------------------------------------------------------------------
// Launch
// ---------------------------------------------------------------------------
extern "C" void kernel_launch(void* const* d_in, const int* in_sizes, int n_in,
                              void* d_out, int out_size) {
    const float* q    = (const float*)d_in[0];
    const int*   mask = (const int*)d_in[1];
    const float* h    = (const float*)d_in[4];
    const float* Wq   = (const float*)d_in[5];
    const float* Wk   = (const float*)d_in[6];
    const float* Wv   = (const float*)d_in[7];
    const float* Wo   = (const float*)d_in[8];
    const float* bo   = (const float*)d_in[9];
    float* out = (float*)d_out;

    float *gQ, *gH, *gS, *gWr, *gWM;
    cudaGetSymbolAddress((void**)&gQ,  g_Q);
    cudaGetSymbolAddress((void**)&gH,  g_H);
    cudaGetSymbolAddress((void**)&gS,  g_S);
    cudaGetSymbolAddress((void**)&gWr, g_Wr);
    cudaGetSymbolAddress((void**)&gWM, g_WM);
    float* gWqT = gWr;
    float* gWkT = gWr + 1 * 512 * 512;
    float* gWvT = gWr + 2 * 512 * 512;
    float* gWo_ = gWr + 3 * 512 * 512;
    float* gWm  = gWM;                    // Wm[i,k] = (Wq^T Wk)[k,i]
    float* gWn  = gWM + 512 * 512;        // Wn[j,i] = (Wv^T Wo^T)[i,j]

    cudaFuncSetAttribute(mma_gemm_kernel<false, true, true>,
                         cudaFuncAttributeMaxDynamicSharedMemorySize, GM_SMEM);
    cudaFuncSetAttribute(mma_gemm_kernel<true, false, false>,
                         cudaFuncAttributeMaxDynamicSharedMemorySize, GM_SMEM);
    cudaFuncSetAttribute(tiny2_gemm_kernel,
                         cudaFuncAttributeMaxDynamicSharedMemorySize, GM_SMEM);
    cudaFuncSetAttribute(scores_softmax_kernel,
                         cudaFuncAttributeMaxDynamicSharedMemorySize, SC_DYN);

    // 0) weight prep: WqT, WkT, WvT (transpose+round), Wo (round)
    prep_weights_kernel<<<dim3(16, 16, 4), dim3(32, 8)>>>(Wq, Wk, Wv, Wo, gWr);

    // 1) both folded weights in one launch:
    //    Wm[i,k] = sum_j WkT[i,j]*WqT[k,j];  Wn[j,i] = sum_k Wo[j,k]*WvT[i,k]
    tiny2_gemm_kernel<<<dim3(4, 4, 2), 256, GM_SMEM>>>(gWkT, gWqT, gWm,
                                                       gWo_, gWvT, gWn);

    // 2) q' = q @ Wm^T  (raw q, fragments rounded in-register)
    mma_gemm_kernel<false, true, true><<<dim3(4, MTOT / 128), 256, GM_SMEM>>>(
        q, gWm, nullptr, gQ, 512);

    // 3) fused scores + softmax, rows 0..127 (raw h, rounded in-register)
    scores_softmax_kernel<<<dim3(2, Bc), 256, SC_DYN>>>(gQ, h, mask, gS);

    // 4) X = attn @ h, rows 0..127
    heads_kernel<<<dim3(4, 2, Bc), 256, HD_DYN>>>(gS, h, gH);

    // 5) tail: rows 128..130 (scores+softmax+X in one SIMT pass)
    tail_kernel<<<Bc, 256>>>(gQ, h, mask, gH);

    // 6) out = X @ Wn^T + bias
    mma_gemm_kernel<true, false, false><<<dim3(4, MTOT / 128), 256, GM_SMEM>>>(
        gH, gWn, bo, out, 512);
}

// round 9
// speedup vs baseline: 8.1022x; 1.4672x over previous
#include <cuda_runtime.h>
#include <cuda_fp16.h>
#include <math.h>
#include <stdint.h>

// ---------------------------------------------------------------------------
// Problem constants
// ---------------------------------------------------------------------------
constexpr int Bc   = 512;
constexpr int Gc   = 131;
constexpr int MTOT = Bc * Gc;      // 67072
constexpr int SLD  = 144;          // padded score row stride (fp16), zeros 131..143
constexpr int LEAF_LO = 80;
constexpr int LEAF_HI = 130;

// Scratch (device globals: allocation-free)
__device__ __half g_q16[(size_t)MTOT * 512];    // q  (fp16)
__device__ __half g_h16[(size_t)MTOT * 512];    // h  (fp16)
__device__ __half g_Qp [(size_t)MTOT * 512];    // q' = q·M
__device__ __half g_X16[(size_t)MTOT * 512];    // X  = attn·h
__device__ __half g_S16[(size_t)Bc * Gc * SLD]; // attn probs
__device__ __half g_W16[4][512 * 512];          // WqT, WkT, WvT, Wo (fp16)
__device__ __half g_WM16[2][512 * 512];         // Wm, Wn (folded, fp16)

// ---------------------------------------------------------------------------
// PTX helpers (baseline sm_75/80 PTX — valid for compute_103)
// ---------------------------------------------------------------------------
__device__ __forceinline__ uint32_t smem_u32(const void* p) {
    return (uint32_t)__cvta_generic_to_shared(p);
}
__device__ __forceinline__ void cp_async16(uint32_t sdst, const void* gsrc) {
    asm volatile("cp.async.cg.shared.global [%0], [%1], 16;" :: "r"(sdst), "l"(gsrc));
}
__device__ __forceinline__ void cp_async16z(uint32_t sdst, const void* gsrc, bool valid) {
    int sz = valid ? 16 : 0;
    asm volatile("cp.async.cg.shared.global [%0], [%1], 16, %2;"
                 :: "r"(sdst), "l"(gsrc), "r"(sz));
}
__device__ __forceinline__ void cp_commit() { asm volatile("cp.async.commit_group;"); }
__device__ __forceinline__ void cp_wait0()  { asm volatile("cp.async.wait_group 0;"); }
__device__ __forceinline__ void cp_wait1()  { asm volatile("cp.async.wait_group 1;"); }

__device__ __forceinline__ void ldsm_x4(uint32_t& r0, uint32_t& r1, uint32_t& r2,
                                        uint32_t& r3, uint32_t addr) {
    asm volatile("ldmatrix.sync.aligned.m8n8.x4.shared.b16 {%0,%1,%2,%3}, [%4];"
                 : "=r"(r0), "=r"(r1), "=r"(r2), "=r"(r3) : "r"(addr));
}
__device__ __forceinline__ void ldsm_x4_t(uint32_t& r0, uint32_t& r1, uint32_t& r2,
                                          uint32_t& r3, uint32_t addr) {
    asm volatile("ldmatrix.sync.aligned.m8n8.x4.trans.shared.b16 {%0,%1,%2,%3}, [%4];"
                 : "=r"(r0), "=r"(r1), "=r"(r2), "=r"(r3) : "r"(addr));
}
__device__ __forceinline__ void mma_f16(float* c, const uint32_t* a, const uint32_t* b) {
    asm volatile(
        "mma.sync.aligned.m16n8k16.row.col.f32.f16.f16.f32 "
        "{%0,%1,%2,%3}, {%4,%5,%6,%7}, {%8,%9}, {%0,%1,%2,%3};"
        : "+f"(c[0]), "+f"(c[1]), "+f"(c[2]), "+f"(c[3])
        : "r"(a[0]), "r"(a[1]), "r"(a[2]), "r"(a[3]), "r"(b[0]), "r"(b[1]));
}

// ---------------------------------------------------------------------------
// fp32 -> fp16 conversion (8 elements / thread / iter)
// ---------------------------------------------------------------------------
__global__ void cvt_f16_kernel(const float4* __restrict__ in,
                               uint4* __restrict__ out, int n8) {
    int i = blockIdx.x * blockDim.x + threadIdx.x;
    int stride = gridDim.x * blockDim.x;
    for (; i < n8; i += stride) {
        float4 v0 = in[2 * i], v1 = in[2 * i + 1];
        __half2 h0 = __floats2half2_rn(v0.x, v0.y);
        __half2 h1 = __floats2half2_rn(v0.z, v0.w);
        __half2 h2 = __floats2half2_rn(v1.x, v1.y);
        __half2 h3 = __floats2half2_rn(v1.z, v1.w);
        uint4 o;
        o.x = *reinterpret_cast<uint32_t*>(&h0);
        o.y = *reinterpret_cast<uint32_t*>(&h1);
        o.z = *reinterpret_cast<uint32_t*>(&h2);
        o.w = *reinterpret_cast<uint32_t*>(&h3);
        out[i] = o;
    }
}

// Weight prep: z=0,1,2 -> transpose Wq,Wk,Wv; z=3 -> plain Wo. All to fp16.
__global__ void prep_weights_kernel(const float* __restrict__ w0, const float* __restrict__ w1,
                                    const float* __restrict__ w2, const float* __restrict__ w3,
                                    __half* __restrict__ out) {
    __shared__ float tile[32][33];
    const int z = blockIdx.z;
    const float* in = (z == 0) ? w0 : (z == 1) ? w1 : (z == 2) ? w2 : w3;
    __half* o = out + (size_t)z * 512 * 512;
    const int tx = threadIdx.x, ty = threadIdx.y;
    const int x = blockIdx.x * 32 + tx;
    const int y0 = blockIdx.y * 32;
    if (z < 3) {
#pragma unroll
        for (int j = 0; j < 32; j += 8)
            tile[ty + j][tx] = in[(size_t)(y0 + ty + j) * 512 + x];
        __syncthreads();
        const int x2 = y0 + tx;
        const int y2 = blockIdx.x * 32;
#pragma unroll
        for (int j = 0; j < 32; j += 8)
            o[(size_t)(y2 + ty + j) * 512 + x2] = __float2half_rn(tile[tx][ty + j]);
    } else {
#pragma unroll
        for (int j = 0; j < 32; j += 8)
            o[(size_t)(y0 + ty + j) * 512 + x] =
                __float2half_rn(in[(size_t)(y0 + ty + j) * 512 + x]);
    }
}

// ---------------------------------------------------------------------------
// fp16 mma GEMM-NT: C[M,N] = A[M,512] @ W[N,512]^T  (fp32 accum)
// BM=128, BN=128, BK=64 fp16, 256 threads (8 warps: 4m x 2n, warp 32x64).
// 3-stage cp.async pipeline. OUTF32: fp32 output + bias; else fp16 output.
// ---------------------------------------------------------------------------
constexpr int GM_ROWH = 72;                       // fp16 elems / padded row
constexpr int GM_STAGE_B = 256 * GM_ROWH * 2;     // 36864 bytes
constexpr int GM_STAGES = 3;
constexpr int GM_SMEM = GM_STAGES * GM_STAGE_B;   // 110592
constexpr int GM_ITERS = 8;                       // 512 / 64

template <bool OUTF32>
__device__ __forceinline__ void gemm_body_f16(const __half* __restrict__ A,
                                              const __half* __restrict__ W,
                                              const float* __restrict__ bias,
                                              void* __restrict__ Cv, int CS,
                                              int bm, int bn) {
    extern __shared__ __align__(16) char smraw[];
    const uint32_t smb = smem_u32(smraw);
    const int tid = threadIdx.x;
    const int wid = tid >> 5;
    const int lane = tid & 31;
    const int wm = (wid & 3) * 32;
    const int wn = (wid >> 2) * 64;

    const __half* Ag = A + (size_t)bm * 512;
    const __half* Wg = W + (size_t)bn * 512;

    float c[2][8][4];
#pragma unroll
    for (int t = 0; t < 2; t++)
#pragma unroll
        for (int j = 0; j < 8; j++)
#pragma unroll
            for (int v = 0; v < 4; v++) c[t][j][v] = 0.f;

    const int lr = lane & 7;
    uint32_t aoff[2], boff[4];
#pragma unroll
    for (int t = 0; t < 2; t++)
        aoff[t] = (uint32_t)(((wm + t * 16 + ((lane >> 3) & 1) * 8 + lr) * GM_ROWH
                              + (lane >> 4) * 8) * 2);
#pragma unroll
    for (int jp = 0; jp < 4; jp++)
        boff[jp] = (uint32_t)(128 * GM_ROWH * 2
                              + ((wn + jp * 16 + ((lane >> 4) & 1) * 8 + lr) * GM_ROWH
                                 + ((lane >> 3) & 1) * 8) * 2);

    auto load_stage = [&](int s, int k0) {
        uint32_t base = smb + (uint32_t)(s * GM_STAGE_B);
#pragma unroll
        for (int i = 0; i < 4; i++) {
            int id = tid + i * 256;
            int row = id >> 3, c8 = (id & 7) << 3;
            cp_async16(base + (uint32_t)((row * GM_ROWH + c8) * 2),
                       Ag + (size_t)row * 512 + k0 + c8);
        }
#pragma unroll
        for (int i = 0; i < 4; i++) {
            int id = tid + i * 256;
            int row = id >> 3, c8 = (id & 7) << 3;
            cp_async16(base + (uint32_t)(((128 + row) * GM_ROWH + c8) * 2),
                       Wg + (size_t)row * 512 + k0 + c8);
        }
    };

    load_stage(0, 0);    cp_commit();
    load_stage(1, 64);   cp_commit();
    cp_wait1();
    __syncthreads();

    int sc = 0, sl = 2;
    for (int it = 0; it < GM_ITERS; ++it) {
        if (it + 2 < GM_ITERS) {
            load_stage(sl, (it + 2) * 64);
            cp_commit();
            sl = (sl == GM_STAGES - 1) ? 0 : sl + 1;
        }
        uint32_t base = smb + (uint32_t)(sc * GM_STAGE_B);
        sc = (sc == GM_STAGES - 1) ? 0 : sc + 1;
#pragma unroll
        for (int kk = 0; kk < 4; kk++) {       // 4 x k16 per 64-elt stage
            uint32_t a[2][4], b[8][2];
#pragma unroll
            for (int t = 0; t < 2; t++)
                ldsm_x4(a[t][0], a[t][1], a[t][2], a[t][3], base + aoff[t] + kk * 32);
#pragma unroll
            for (int jp = 0; jp < 4; jp++) {
                uint32_t r0, r1, r2, r3;
                ldsm_x4(r0, r1, r2, r3, base + boff[jp] + kk * 32);
                b[2 * jp][0] = r0;     b[2 * jp][1] = r1;
                b[2 * jp + 1][0] = r2; b[2 * jp + 1][1] = r3;
            }
#pragma unroll
            for (int t = 0; t < 2; t++)
#pragma unroll
                for (int j = 0; j < 8; j++)
                    mma_f16(c[t][j], a[t], b[j]);
        }
        if (it + 2 < GM_ITERS)      cp_wait1();
        else if (it + 1 < GM_ITERS) cp_wait0();
        __syncthreads();
    }

    const int g = lane >> 2;
    const int q = lane & 3;
#pragma unroll
    for (int j = 0; j < 8; j++) {
        int col = bn + wn + j * 8 + 2 * q;
        float b0 = 0.f, b1 = 0.f;
        if (OUTF32) { b0 = bias[col]; b1 = bias[col + 1]; }
#pragma unroll
        for (int t = 0; t < 2; t++) {
            int row0 = bm + wm + t * 16 + g;
            if (OUTF32) {
                float* Cf = (float*)Cv;
                *reinterpret_cast<float2*>(Cf + (size_t)row0 * CS + col) =
                    make_float2(c[t][j][0] + b0, c[t][j][1] + b1);
                *reinterpret_cast<float2*>(Cf + (size_t)(row0 + 8) * CS + col) =
                    make_float2(c[t][j][2] + b0, c[t][j][3] + b1);
            } else {
                __half* Ch = (__half*)Cv;
                __half2 p0 = __floats2half2_rn(c[t][j][0], c[t][j][1]);
                __half2 p1 = __floats2half2_rn(c[t][j][2], c[t][j][3]);
                *reinterpret_cast<__half2*>(Ch + (size_t)row0 * CS + col) = p0;
                *reinterpret_cast<__half2*>(Ch + (size_t)(row0 + 8) * CS + col) = p1;
            }
        }
    }
}

template <bool OUTF32>
__global__ void __launch_bounds__(256)
mma_gemm_f16(const __half* __restrict__ A, const __half* __restrict__ W,
             const float* __restrict__ bias, void* __restrict__ C, int CS) {
    gemm_body_f16<OUTF32>(A, W, bias, C, CS, blockIdx.y * 128, blockIdx.x * 128);
}

// both folded-weight 512^3 GEMMs in one launch
__global__ void __launch_bounds__(256)
tiny2_gemm_f16(const __half* __restrict__ A0, const __half* __restrict__ W0,
               __half* __restrict__ C0,
               const __half* __restrict__ A1, const __half* __restrict__ W1,
               __half* __restrict__ C1) {
    if (blockIdx.z == 0)
        gemm_body_f16<false>(A0, W0, nullptr, C0, 512, blockIdx.y * 128, blockIdx.x * 128);
    else
        gemm_body_f16<false>(A1, W1, nullptr, C1, 512, blockIdx.y * 128, blockIdx.x * 128);
}

// ---------------------------------------------------------------------------
// Fused scores + softmax (fp16 mma): 64 i-rows (rows 0..127) x 131 j x K=512.
// A = q' fp16, B = h fp16. Writes probs (fp16) to g_S16, stride 144 w/ zeros.
// ---------------------------------------------------------------------------
constexpr int SC_QB  = 64 * 72 * 2;               // 9216
constexpr int SC_STG = SC_QB + 168 * 72 * 2;      // 33408
constexpr int SC_DYN = 3 * SC_STG;                // 100224 (> fp32 stash 41984)

__global__ void __launch_bounds__(256)
scores_softmax_kernel(const __half* __restrict__ Q, const __half* __restrict__ Hm,
                      const int* __restrict__ mask, __half* __restrict__ S) {
    extern __shared__ __align__(16) char smc[];
    __shared__ int mask_s[144];
    const uint32_t smb = smem_u32(smc);
    float* Ss = reinterpret_cast<float*>(smc);   // epilogue stash [64][164] fp32
    const int tid = threadIdx.x;
    const int wid = tid >> 5;
    const int lane = tid & 31;
    const int m0 = blockIdx.x * 64;              // 0 or 64
    const int b  = blockIdx.y;

    if (tid < 144) mask_s[tid] = (tid < Gc) ? mask[b * Gc + tid] : 1;

    const __half* Qb = Q  + (size_t)b * Gc * 512;
    const __half* Kb = Hm + (size_t)b * Gc * 512;

    const int wm = (wid & 1) * 32;
    const int wn = (wid >> 1) * 40;
    const int lr = lane & 7;

    float c[2][5][4];
#pragma unroll
    for (int t = 0; t < 2; t++)
#pragma unroll
        for (int n = 0; n < 5; n++)
#pragma unroll
            for (int v = 0; v < 4; v++) c[t][n][v] = 0.f;

    uint32_t aoff[2], boff[3];
#pragma unroll
    for (int t = 0; t < 2; t++)
        aoff[t] = (uint32_t)(((wm + t * 16 + ((lane >> 3) & 1) * 8 + lr) * 72
                              + (lane >> 4) * 8) * 2);
#pragma unroll
    for (int jp = 0; jp < 3; jp++)
        boff[jp] = (uint32_t)(SC_QB
                              + ((wn + jp * 16 + ((lane >> 4) & 1) * 8 + lr) * 72
                                 + ((lane >> 3) & 1) * 8) * 2);

    auto load_stage = [&](int s, int k0) {
        uint32_t qb = smb + (uint32_t)(s * SC_STG);
        uint32_t kb = qb + SC_QB;
#pragma unroll
        for (int l = 0; l < 2; l++) {   // Q: 64 rows x 8 chunks
            int id = tid + l * 256;
            int row = id >> 3, c8 = (id & 7) << 3;
            cp_async16(qb + (uint32_t)((row * 72 + c8) * 2),
                       Qb + (size_t)(m0 + row) * 512 + k0 + c8);
        }
#pragma unroll
        for (int i = 0; i < 5; i++) {   // K: 160 rows x 8 chunks
            int id = tid + i * 256;
            int row = id >> 3, c8 = (id & 7) << 3;
            bool v = row < Gc;
            const __half* src = v ? Kb + (size_t)row * 512 + k0 + c8 : Kb;
            cp_async16z(kb + (uint32_t)((row * 72 + c8) * 2), src, v);
        }
    };

    load_stage(0, 0);    cp_commit();
    load_stage(1, 64);   cp_commit();
    cp_wait1();
    __syncthreads();

    int scur = 0, sl = 2;
    for (int it = 0; it < 8; ++it) {
        if (it + 2 < 8) {
            load_stage(sl, (it + 2) * 64);
            cp_commit();
            sl = (sl == 2) ? 0 : sl + 1;
        }
        uint32_t qb = smb + (uint32_t)(scur * SC_STG);
        scur = (scur == 2) ? 0 : scur + 1;
#pragma unroll
        for (int kk = 0; kk < 4; kk++) {
            uint32_t a[2][4], bfr[6][2];
#pragma unroll
            for (int t = 0; t < 2; t++)
                ldsm_x4(a[t][0], a[t][1], a[t][2], a[t][3], qb + aoff[t] + kk * 32);
#pragma unroll
            for (int jp = 0; jp < 3; jp++) {
                uint32_t r0, r1, r2, r3;
                ldsm_x4(r0, r1, r2, r3, qb + boff[jp] + kk * 32);
                bfr[2 * jp][0] = r0;     bfr[2 * jp][1] = r1;
                bfr[2 * jp + 1][0] = r2; bfr[2 * jp + 1][1] = r3;
            }
#pragma unroll
            for (int t = 0; t < 2; t++)
#pragma unroll
                for (int n = 0; n < 5; n++)   // bfr[5] = discarded padding tile
                    mma_f16(c[t][n], a[t], bfr[n]);
        }
        if (it + 2 < 8)      cp_wait1();
        else if (it + 1 < 8) cp_wait0();
        __syncthreads();
    }

    // stash accumulators fp32: Ss[64][164]
    const int g = lane >> 2;
    const int qd = lane & 3;
#pragma unroll
    for (int t = 0; t < 2; t++) {
        int r0 = wm + t * 16 + g;
#pragma unroll
        for (int n = 0; n < 5; n++) {
            int col = wn + n * 8 + 2 * qd;
            *reinterpret_cast<float2*>(&Ss[r0 * 164 + col]) = make_float2(c[t][n][0], c[t][n][1]);
            *reinterpret_cast<float2*>(&Ss[(r0 + 8) * 164 + col]) = make_float2(c[t][n][2], c[t][n][3]);
        }
    }
    __syncthreads();

    const float norm = 0.04419417382415922f;   // 1/sqrt(512)
#pragma unroll
    for (int rr = 0; rr < 8; rr++) {
        int i_loc = wid * 8 + rr;
        int gi = m0 + i_loc;                    // < 128 always
        bool li = (gi >= LEAF_LO) && (gi < LEAF_HI);
        float v[5];
        float mx = -3.0e38f;
#pragma unroll
        for (int ch = 0; ch < 5; ch++) {
            int j = lane + ch * 32;
            float val = -3.0e38f;
            if (j < Gc) {
                float s = Ss[i_loc * 164 + j] * norm;
                bool mj = (mask_s[j] > 0) || (li && j >= LEAF_LO && j < LEAF_HI);
                val = mj ? -30.f : s;
            }
            v[ch] = val;
            mx = fmaxf(mx, val);
        }
#pragma unroll
        for (int o = 16; o; o >>= 1) mx = fmaxf(mx, __shfl_xor_sync(0xffffffffu, mx, o));
        float e[5];
        float sum = 0.f;
#pragma unroll
        for (int ch = 0; ch < 5; ch++) {
            int j = lane + ch * 32;
            e[ch] = (j < Gc) ? expf(v[ch] - mx) : 0.f;
            sum += e[ch];
        }
#pragma unroll
        for (int o = 16; o; o >>= 1) sum += __shfl_xor_sync(0xffffffffu, sum, o);
        float inv = 1.f / sum;
        __half* Srow = S + ((size_t)b * Gc + gi) * SLD;
#pragma unroll
        for (int ch = 0; ch < 5; ch++) {
            int j = lane + ch * 32;
            if (j < SLD) {
                float p = 0.f;
                if (j < Gc) {
                    bool mj = (mask_s[j] > 0) || (li && j >= LEAF_LO && j < LEAF_HI);
                    p = mj ? 0.f : e[ch] * inv;
                }
                Srow[j] = __float2half_rn(p);
            }
        }
    }
}

// ---------------------------------------------------------------------------
// heads (fp16 mma): X[i,n] = sum_j S[i,j] * h[j,n]; rows 0..127; K=144 padded.
// A = S fp16 via ldsm; B = h fp16 via ldsm.x4.trans. Output fp16.
// ---------------------------------------------------------------------------
constexpr int HD_SB  = 64 * 24 * 2;    // 3072
constexpr int HD_VB  = 16 * 136 * 2;   // 4352
constexpr int HD_STG = HD_SB + HD_VB;  // 7424
constexpr int HD_DYN = 2 * HD_STG;     // 14848

__global__ void __launch_bounds__(256)
heads_kernel(const __half* __restrict__ S, const __half* __restrict__ Hm,
             __half* __restrict__ X) {
    extern __shared__ __align__(16) char smc[];
    const uint32_t smb = smem_u32(smc);
    const int tid = threadIdx.x;
    const int wid = tid >> 5;
    const int lane = tid & 31;
    const int n0 = blockIdx.x * 128;
    const int m0 = blockIdx.y * 64;              // 0 or 64
    const int b  = blockIdx.z;

    const __half* Sb = S  + (size_t)b * Gc * SLD;
    const __half* Vb = Hm + (size_t)b * Gc * 512;

    const int wm = (wid & 1) * 32;
    const int wn = (wid >> 1) * 32;
    const int lr = lane & 7;

    float c[2][4][4];
#pragma unroll
    for (int t = 0; t < 2; t++)
#pragma unroll
        for (int n = 0; n < 4; n++)
#pragma unroll
            for (int v = 0; v < 4; v++) c[t][n][v] = 0.f;

    uint32_t aoff[2];
#pragma unroll
    for (int t = 0; t < 2; t++)
        aoff[t] = (uint32_t)(((wm + t * 16 + ((lane >> 3) & 1) * 8 + lr) * 24
                              + (lane >> 4) * 8) * 2);
    // trans-B addresses: krow + n-offset
    const int tk = lr + ((lane >> 3) & 1) * 8;       // k-row 0..15
    const int tn = (lane >> 4) * 8;                  // n sub-offset 0/8

    auto load_stage = [&](int s, int k0) {
        uint32_t sbse = smb + (uint32_t)(s * HD_STG);
        uint32_t vbse = sbse + HD_SB;
        if (tid < 128) {    // S: 64 rows x 2 chunks
            int row = tid >> 1, c8 = (tid & 1) << 3;
            cp_async16(sbse + (uint32_t)((row * 24 + c8) * 2),
                       Sb + (size_t)(m0 + row) * SLD + k0 + c8);
        }
        {                   // V: 16 k-rows x 16 chunks (128 n)
            int row = tid >> 4, c8 = (tid & 15) << 3;
            bool v = (k0 + row) < Gc;
            const __half* src = v ? Vb + (size_t)(k0 + row) * 512 + n0 + c8 : Vb;
            cp_async16z(vbse + (uint32_t)((row * 136 + c8) * 2), src, v);
        }
    };

    load_stage(0, 0);
    cp_commit();
    cp_wait0();
    __syncthreads();

    for (int it = 0; it < 9; ++it) {            // K = 144 = 9 x 16
        if (it + 1 < 9) {
            load_stage((it + 1) & 1, (it + 1) * 16);
            cp_commit();
        }
        uint32_t sbse = smb + (uint32_t)((it & 1) * HD_STG);
        uint32_t vbse = sbse + HD_SB;
        uint32_t a[2][4], bfr[4][2];
#pragma unroll
        for (int t = 0; t < 2; t++)
            ldsm_x4(a[t][0], a[t][1], a[t][2], a[t][3], sbse + aoff[t]);
#pragma unroll
        for (int p = 0; p < 2; p++) {           // each x4.trans covers 2 n8-tiles
            uint32_t r0, r1, r2, r3;
            ldsm_x4_t(r0, r1, r2, r3,
                      vbse + (uint32_t)((tk * 136 + wn + p * 16 + tn) * 2));
            bfr[2 * p][0] = r0;     bfr[2 * p][1] = r1;
            bfr[2 * p + 1][0] = r2; bfr[2 * p + 1][1] = r3;
        }
#pragma unroll
        for (int t = 0; t < 2; t++)
#pragma unroll
            for (int n = 0; n < 4; n++)
                mma_f16(c[t][n], a[t], bfr[n]);
        if (it + 1 < 9) cp_wait0();
        __syncthreads();
    }

    const int g = lane >> 2;
    const int qd = lane & 3;
#pragma unroll
    for (int t = 0; t < 2; t++) {
#pragma unroll
        for (int n = 0; n < 4; n++) {
            int col = n0 + wn + n * 8 + 2 * qd;
            int i0r = m0 + wm + t * 16 + g;     // <= 127
            __half2 p0 = __floats2half2_rn(c[t][n][0], c[t][n][1]);
            __half2 p1 = __floats2half2_rn(c[t][n][2], c[t][n][3]);
            *reinterpret_cast<__half2*>(X + ((size_t)b * Gc + i0r) * 512 + col) = p0;
            *reinterpret_cast<__half2*>(X + ((size_t)b * Gc + i0r + 8) * 512 + col) = p1;
        }
    }
}

// ---------------------------------------------------------------------------
// Tail: rows 128..130 per batch — scores, softmax, X in one SIMT kernel.
// ---------------------------------------------------------------------------
__global__ void __launch_bounds__(256)
tail_kernel(const __half* __restrict__ Q, const __half* __restrict__ Hm,
            const int* __restrict__ mask, __half* __restrict__ X) {
    __shared__ float qs[3][512];
    __shared__ float ps[3][132];
    __shared__ int mk[132];
    const int b = blockIdx.x;
    const int tid = threadIdx.x;
    const int wid = tid >> 5;
    const int lane = tid & 31;
    const __half* Qb = Q  + ((size_t)b * Gc + 128) * 512;
    const __half* hb = Hm + (size_t)b * Gc * 512;

    for (int i = tid; i < 3 * 512; i += 256) qs[i >> 9][i & 511] = __half2float(Qb[i]);
    if (tid < 132) mk[tid] = (tid < Gc) ? mask[b * Gc + tid] : 1;
    __syncthreads();

    for (int j = wid; j < Gc; j += 8) {
        const __half* hj = hb + (size_t)j * 512;
        float a0 = 0.f, a1 = 0.f, a2 = 0.f;
#pragma unroll
        for (int k = 0; k < 16; k++) {
            int idx = lane + k * 32;
            float hv = __half2float(hj[idx]);
            a0 = fmaf(hv, qs[0][idx], a0);
            a1 = fmaf(hv, qs[1][idx], a1);
            a2 = fmaf(hv, qs[2][idx], a2);
        }
#pragma unroll
        for (int o = 16; o; o >>= 1) {
            a0 += __shfl_xor_sync(0xffffffffu, a0, o);
            a1 += __shfl_xor_sync(0xffffffffu, a1, o);
            a2 += __shfl_xor_sync(0xffffffffu, a2, o);
        }
        if (lane == 0) { ps[0][j] = a0; ps[1][j] = a1; ps[2][j] = a2; }
    }
    __syncthreads();

    if (wid < 3) {
        const int gi = 128 + wid;
        const bool li = (gi >= LEAF_LO) && (gi < LEAF_HI);
        const float norm = 0.04419417382415922f;
        float v[5];
        float mx = -3.0e38f;
#pragma unroll
        for (int ch = 0; ch < 5; ch++) {
            int j = lane + ch * 32;
            float val = -3.0e38f;
            if (j < Gc) {
                bool mj = (mk[j] > 0) || (li && j >= LEAF_LO && j < LEAF_HI);
                val = mj ? -30.f : ps[wid][j] * norm;
            }
            v[ch] = val;
            mx = fmaxf(mx, val);
        }
#pragma unroll
        for (int o = 16; o; o >>= 1) mx = fmaxf(mx, __shfl_xor_sync(0xffffffffu, mx, o));
        float e[5];
        float sum = 0.f;
#pragma unroll
        for (int ch = 0; ch < 5; ch++) {
            int j = lane + ch * 32;
            e[ch] = (j < Gc) ? expf(v[ch] - mx) : 0.f;
            sum += e[ch];
        }
#pragma unroll
        for (int o = 16; o; o >>= 1) sum += __shfl_xor_sync(0xffffffffu, sum, o);
        float inv = 1.f / sum;
#pragma unroll
        for (int ch = 0; ch < 5; ch++) {
            int j = lane + ch * 32;
            if (j < Gc) {
                bool mj = (mk[j] > 0) || (li && j >= LEAF_LO && j < LEAF_HI);
                ps[wid][j] = mj ? 0.f : e[ch] * inv;
            }
        }
    }
    __syncthreads();

    float acc[3][2] = {{0.f, 0.f}, {0.f, 0.f}, {0.f, 0.f}};
    for (int j = 0; j < Gc; j++) {
        float p0 = ps[0][j], p1 = ps[1][j], p2 = ps[2][j];
        float h0 = __half2float(hb[(size_t)j * 512 + tid]);
        float h1 = __half2float(hb[(size_t)j * 512 + tid + 256]);
        acc[0][0] = fmaf(p0, h0, acc[0][0]); acc[0][1] = fmaf(p0, h1, acc[0][1]);
        acc[1][0] = fmaf(p1, h0, acc[1][0]); acc[1][1] = fmaf(p1, h1, acc[1][1]);
        acc[2][0] = fmaf(p2, h0, acc[2][0]); acc[2][1] = fmaf(p2, h1, acc[2][1]);
    }
    __half* Xb = X + ((size_t)b * Gc + 128) * 512;
#pragma unroll
    for (int i = 0; i < 3; i++) {
        Xb[(size_t)i * 512 + tid]       = __float2half_rn(acc[i][0]);
        Xb[(size_t)i * 512 + tid + 256] = __float2half_rn(acc[i][1]);
    }
}

// ---------------------------------------------------------------------------
// Launch
// ---------------------------------------------------------------------------
extern "C" void kernel_launch(void* const* d_in, const int* in_sizes, int n_in,
                              void* d_out, int out_size) {
    const float* q    = (const float*)d_in[0];
    const int*   mask = (const int*)d_in[1];
    const float* h    = (const float*)d_in[4];
    const float* Wq   = (const float*)d_in[5];
    const float* Wk   = (const float*)d_in[6];
    const float* Wv   = (const float*)d_in[7];
    const float* Wo   = (const float*)d_in[8];
    const float* bo   = (const float*)d_in[9];
    float* out = (float*)d_out;

    __half *gq16, *gh16, *gQp, *gX16, *gS16, *gW16, *gWM16;
    cudaGetSymbolAddress((void**)&gq16, g_q16);
    cudaGetSymbolAddress((void**)&gh16, g_h16);
    cudaGetSymbolAddress((void**)&gQp,  g_Qp);
    cudaGetSymbolAddress((void**)&gX16, g_X16);
    cudaGetSymbolAddress((void**)&gS16, g_S16);
    cudaGetSymbolAddress((void**)&gW16, g_W16);
    cudaGetSymbolAddress((void**)&gWM16, g_WM16);
    __half* gWqT = gW16;
    __half* gWkT = gW16 + 1 * 512 * 512;
    __half* gWvT = gW16 + 2 * 512 * 512;
    __half* gWo_ = gW16 + 3 * 512 * 512;
    __half* gWm  = gWM16;                  // Wm[i,k] = sum_j Wk[j,i] Wq[j,k]
    __half* gWn  = gWM16 + 512 * 512;      // Wn[j,i] = sum_k Wo[j,k] Wv[k,i]

    cudaFuncSetAttribute(mma_gemm_f16<false>,
                         cudaFuncAttributeMaxDynamicSharedMemorySize, GM_SMEM);
    cudaFuncSetAttribute(mma_gemm_f16<true>,
                         cudaFuncAttributeMaxDynamicSharedMemorySize, GM_SMEM);
    cudaFuncSetAttribute(tiny2_gemm_f16,
                         cudaFuncAttributeMaxDynamicSharedMemorySize, GM_SMEM);
    cudaFuncSetAttribute(scores_softmax_kernel,
                         cudaFuncAttributeMaxDynamicSharedMemorySize, SC_DYN);

    // 0) weight prep (fp16: WqT, WkT, WvT transposed; Wo plain)
    prep_weights_kernel<<<dim3(16, 16, 4), dim3(32, 8)>>>(Wq, Wk, Wv, Wo, gW16);

    // 1-2) convert activations to fp16
    int n8 = (MTOT * 512) / 8;
    cvt_f16_kernel<<<4096, 256>>>((const float4*)q, (uint4*)gq16, n8);
    cvt_f16_kernel<<<4096, 256>>>((const float4*)h, (uint4*)gh16, n8);

    // 3) fold both weight products in one launch
    tiny2_gemm_f16<<<dim3(4, 4, 2), 256, GM_SMEM>>>(gWkT, gWqT, gWm,
                                                    gWo_, gWvT, gWn);

    // 4) q' = q @ Wm^T  (fp16 out)
    mma_gemm_f16<false><<<dim3(4, MTOT / 128), 256, GM_SMEM>>>(
        gq16, gWm, nullptr, gQp, 512);

    // 5) fused scores + softmax, rows 0..127  (ncu -s 5 target)
    scores_softmax_kernel<<<dim3(2, Bc), 256, SC_DYN>>>(gQp, gh16, mask, gS16);

    // 6) X = attn @ h, rows 0..127
    heads_kernel<<<dim3(4, 2, Bc), 256, HD_DYN>>>(gS16, gh16, gX16);

    // 7) tail rows 128..130
    tail_kernel<<<Bc, 256>>>(gQp, gh16, mask, gX16);

    // 8) out = X @ Wn^T + bias (fp32 out)
    mma_gemm_f16<true><<<dim3(4, MTOT / 128), 256, GM_SMEM>>>(
        gX16, gWn, bo, out, 512);
}

// round 10
// speedup vs baseline: 9.3638x; 1.1557x over previous
#include <cuda_runtime.h>
#include <cuda_fp16.h>
#include <math.h>
#include <stdint.h>

// ---------------------------------------------------------------------------
// Problem constants
// ---------------------------------------------------------------------------
constexpr int Bc   = 512;
constexpr int Gc   = 131;
constexpr int MTOT = Bc * Gc;      // 67072
constexpr int LEAF_LO = 80;
constexpr int LEAF_HI = 130;

// Scratch (device globals: allocation-free)
__device__ __half g_q16[(size_t)MTOT * 512];    // q  (fp16)
__device__ __half g_h16[(size_t)MTOT * 512];    // h  (fp16)
__device__ __half g_Qp [(size_t)MTOT * 512];    // q' = q·M
__device__ __half g_X16[(size_t)MTOT * 512];    // X  = attn·h
__device__ __half g_W16[4][512 * 512];          // WqT, WkT, WvT, Wo (fp16)
__device__ __half g_WM16[2][512 * 512];         // Wm, Wn (folded, fp16)

// ---------------------------------------------------------------------------
// PTX helpers (baseline sm_75/80 PTX — valid for compute_103)
// ---------------------------------------------------------------------------
__device__ __forceinline__ uint32_t smem_u32(const void* p) {
    return (uint32_t)__cvta_generic_to_shared(p);
}
__device__ __forceinline__ void cp_async16(uint32_t sdst, const void* gsrc) {
    asm volatile("cp.async.cg.shared.global [%0], [%1], 16;" :: "r"(sdst), "l"(gsrc));
}
__device__ __forceinline__ void cp_async16z(uint32_t sdst, const void* gsrc, bool valid) {
    int sz = valid ? 16 : 0;
    asm volatile("cp.async.cg.shared.global [%0], [%1], 16, %2;"
                 :: "r"(sdst), "l"(gsrc), "r"(sz));
}
__device__ __forceinline__ void cp_commit() { asm volatile("cp.async.commit_group;"); }
__device__ __forceinline__ void cp_wait0()  { asm volatile("cp.async.wait_group 0;"); }
__device__ __forceinline__ void cp_wait1()  { asm volatile("cp.async.wait_group 1;"); }

__device__ __forceinline__ void ldsm_x4(uint32_t& r0, uint32_t& r1, uint32_t& r2,
                                        uint32_t& r3, uint32_t addr) {
    asm volatile("ldmatrix.sync.aligned.m8n8.x4.shared.b16 {%0,%1,%2,%3}, [%4];"
                 : "=r"(r0), "=r"(r1), "=r"(r2), "=r"(r3) : "r"(addr));
}
__device__ __forceinline__ void ldsm_x4_t(uint32_t& r0, uint32_t& r1, uint32_t& r2,
                                          uint32_t& r3, uint32_t addr) {
    asm volatile("ldmatrix.sync.aligned.m8n8.x4.trans.shared.b16 {%0,%1,%2,%3}, [%4];"
                 : "=r"(r0), "=r"(r1), "=r"(r2), "=r"(r3) : "r"(addr));
}
__device__ __forceinline__ void mma_f16(float* c, const uint32_t* a, const uint32_t* b) {
    asm volatile(
        "mma.sync.aligned.m16n8k16.row.col.f32.f16.f16.f32 "
        "{%0,%1,%2,%3}, {%4,%5,%6,%7}, {%8,%9}, {%0,%1,%2,%3};"
        : "+f"(c[0]), "+f"(c[1]), "+f"(c[2]), "+f"(c[3])
        : "r"(a[0]), "r"(a[1]), "r"(a[2]), "r"(a[3]), "r"(b[0]), "r"(b[1]));
}

// ---------------------------------------------------------------------------
// prep_all: z=0 cvt q->fp16, z=1 cvt h->fp16, z=2..4 transpose+cvt Wq/Wk/Wv,
// z=5 plain cvt Wo. One launch => all run concurrently.
// grid (16,16,6), block (32,8)
// ---------------------------------------------------------------------------
__global__ void prep_all_kernel(const float4* __restrict__ q, const float4* __restrict__ h,
                                uint4* __restrict__ q16, uint4* __restrict__ h16,
                                const float* __restrict__ w0, const float* __restrict__ w1,
                                const float* __restrict__ w2, const float* __restrict__ w3,
                                __half* __restrict__ wout, int n8) {
    const int tx = threadIdx.x, ty = threadIdx.y;
    const int tid = ty * 32 + tx;
    const int z = blockIdx.z;
    if (z < 2) {
        const float4* in = z ? h : q;
        uint4* out = z ? h16 : q16;
        int blk = blockIdx.y * 16 + blockIdx.x;      // 0..255
        for (int i = blk * 256 + tid; i < n8; i += 256 * 256) {
            float4 v0 = in[2 * i], v1 = in[2 * i + 1];
            __half2 h0 = __floats2half2_rn(v0.x, v0.y);
            __half2 h1 = __floats2half2_rn(v0.z, v0.w);
            __half2 h2 = __floats2half2_rn(v1.x, v1.y);
            __half2 h3 = __floats2half2_rn(v1.z, v1.w);
            uint4 o;
            o.x = *reinterpret_cast<uint32_t*>(&h0);
            o.y = *reinterpret_cast<uint32_t*>(&h1);
            o.z = *reinterpret_cast<uint32_t*>(&h2);
            o.w = *reinterpret_cast<uint32_t*>(&h3);
            out[i] = o;
        }
    } else {
        __shared__ float tile[32][33];
        const int sel = z - 2;
        const float* in = (sel == 0) ? w0 : (sel == 1) ? w1 : (sel == 2) ? w2 : w3;
        __half* o = wout + (size_t)sel * 512 * 512;
        const int x = blockIdx.x * 32 + tx;
        const int y0 = blockIdx.y * 32;
        if (sel < 3) {
#pragma unroll
            for (int j = 0; j < 32; j += 8)
                tile[ty + j][tx] = in[(size_t)(y0 + ty + j) * 512 + x];
            __syncthreads();
            const int x2 = y0 + tx;
            const int y2 = blockIdx.x * 32;
#pragma unroll
            for (int j = 0; j < 32; j += 8)
                o[(size_t)(y2 + ty + j) * 512 + x2] = __float2half_rn(tile[tx][ty + j]);
        } else {
#pragma unroll
            for (int j = 0; j < 32; j += 8)
                o[(size_t)(y0 + ty + j) * 512 + x] =
                    __float2half_rn(in[(size_t)(y0 + ty + j) * 512 + x]);
        }
    }
}

// ---------------------------------------------------------------------------
// fp16 mma GEMM-NT (proven round-9 body): C[M,N] = A[M,512] @ W[N,512]^T
// ---------------------------------------------------------------------------
constexpr int GM_ROWH = 72;
constexpr int GM_STAGE_B = 256 * GM_ROWH * 2;     // 36864
constexpr int GM_STAGES = 3;
constexpr int GM_SMEM = GM_STAGES * GM_STAGE_B;   // 110592
constexpr int GM_ITERS = 8;

template <bool OUTF32>
__device__ __forceinline__ void gemm_body_f16(const __half* __restrict__ A,
                                              const __half* __restrict__ W,
                                              const float* __restrict__ bias,
                                              void* __restrict__ Cv, int CS,
                                              int bm, int bn) {
    extern __shared__ __align__(16) char smraw[];
    const uint32_t smb = smem_u32(smraw);
    const int tid = threadIdx.x;
    const int wid = tid >> 5;
    const int lane = tid & 31;
    const int wm = (wid & 3) * 32;
    const int wn = (wid >> 2) * 64;

    const __half* Ag = A + (size_t)bm * 512;
    const __half* Wg = W + (size_t)bn * 512;

    float c[2][8][4];
#pragma unroll
    for (int t = 0; t < 2; t++)
#pragma unroll
        for (int j = 0; j < 8; j++)
#pragma unroll
            for (int v = 0; v < 4; v++) c[t][j][v] = 0.f;

    const int lr = lane & 7;
    uint32_t aoff[2], boff[4];
#pragma unroll
    for (int t = 0; t < 2; t++)
        aoff[t] = (uint32_t)(((wm + t * 16 + ((lane >> 3) & 1) * 8 + lr) * GM_ROWH
                              + (lane >> 4) * 8) * 2);
#pragma unroll
    for (int jp = 0; jp < 4; jp++)
        boff[jp] = (uint32_t)(128 * GM_ROWH * 2
                              + ((wn + jp * 16 + ((lane >> 4) & 1) * 8 + lr) * GM_ROWH
                                 + ((lane >> 3) & 1) * 8) * 2);

    auto load_stage = [&](int s, int k0) {
        uint32_t base = smb + (uint32_t)(s * GM_STAGE_B);
#pragma unroll
        for (int i = 0; i < 4; i++) {
            int id = tid + i * 256;
            int row = id >> 3, c8 = (id & 7) << 3;
            cp_async16(base + (uint32_t)((row * GM_ROWH + c8) * 2),
                       Ag + (size_t)row * 512 + k0 + c8);
        }
#pragma unroll
        for (int i = 0; i < 4; i++) {
            int id = tid + i * 256;
            int row = id >> 3, c8 = (id & 7) << 3;
            cp_async16(base + (uint32_t)(((128 + row) * GM_ROWH + c8) * 2),
                       Wg + (size_t)row * 512 + k0 + c8);
        }
    };

    load_stage(0, 0);    cp_commit();
    load_stage(1, 64);   cp_commit();
    cp_wait1();
    __syncthreads();

    int sc = 0, sl = 2;
    for (int it = 0; it < GM_ITERS; ++it) {
        if (it + 2 < GM_ITERS) {
            load_stage(sl, (it + 2) * 64);
            cp_commit();
            sl = (sl == GM_STAGES - 1) ? 0 : sl + 1;
        }
        uint32_t base = smb + (uint32_t)(sc * GM_STAGE_B);
        sc = (sc == GM_STAGES - 1) ? 0 : sc + 1;
#pragma unroll
        for (int kk = 0; kk < 4; kk++) {
            uint32_t a[2][4], b[8][2];
#pragma unroll
            for (int t = 0; t < 2; t++)
                ldsm_x4(a[t][0], a[t][1], a[t][2], a[t][3], base + aoff[t] + kk * 32);
#pragma unroll
            for (int jp = 0; jp < 4; jp++) {
                uint32_t r0, r1, r2, r3;
                ldsm_x4(r0, r1, r2, r3, base + boff[jp] + kk * 32);
                b[2 * jp][0] = r0;     b[2 * jp][1] = r1;
                b[2 * jp + 1][0] = r2; b[2 * jp + 1][1] = r3;
            }
#pragma unroll
            for (int t = 0; t < 2; t++)
#pragma unroll
                for (int j = 0; j < 8; j++)
                    mma_f16(c[t][j], a[t], b[j]);
        }
        if (it + 2 < GM_ITERS)      cp_wait1();
        else if (it + 1 < GM_ITERS) cp_wait0();
        __syncthreads();
    }

    const int g = lane >> 2;
    const int q = lane & 3;
#pragma unroll
    for (int j = 0; j < 8; j++) {
        int col = bn + wn + j * 8 + 2 * q;
        float b0 = 0.f, b1 = 0.f;
        if (OUTF32) { b0 = bias[col]; b1 = bias[col + 1]; }
#pragma unroll
        for (int t = 0; t < 2; t++) {
            int row0 = bm + wm + t * 16 + g;
            if (OUTF32) {
                float* Cf = (float*)Cv;
                *reinterpret_cast<float2*>(Cf + (size_t)row0 * CS + col) =
                    make_float2(c[t][j][0] + b0, c[t][j][1] + b1);
                *reinterpret_cast<float2*>(Cf + (size_t)(row0 + 8) * CS + col) =
                    make_float2(c[t][j][2] + b0, c[t][j][3] + b1);
            } else {
                __half* Ch = (__half*)Cv;
                __half2 p0 = __floats2half2_rn(c[t][j][0], c[t][j][1]);
                __half2 p1 = __floats2half2_rn(c[t][j][2], c[t][j][3]);
                *reinterpret_cast<__half2*>(Ch + (size_t)row0 * CS + col) = p0;
                *reinterpret_cast<__half2*>(Ch + (size_t)(row0 + 8) * CS + col) = p1;
            }
        }
    }
}

template <bool OUTF32>
__global__ void __launch_bounds__(256)
mma_gemm_f16(const __half* __restrict__ A, const __half* __restrict__ W,
             const float* __restrict__ bias, void* __restrict__ C, int CS) {
    gemm_body_f16<OUTF32>(A, W, bias, C, CS, blockIdx.y * 128, blockIdx.x * 128);
}

__global__ void __launch_bounds__(256)
tiny2_gemm_f16(const __half* __restrict__ A0, const __half* __restrict__ W0,
               __half* __restrict__ C0,
               const __half* __restrict__ A1, const __half* __restrict__ W1,
               __half* __restrict__ C1) {
    if (blockIdx.z == 0)
        gemm_body_f16<false>(A0, W0, nullptr, C0, 512, blockIdx.y * 128, blockIdx.x * 128);
    else
        gemm_body_f16<false>(A1, W1, nullptr, C1, 512, blockIdx.y * 128, blockIdx.x * 128);
}

// ---------------------------------------------------------------------------
// FUSED attention: scores + softmax + heads (+tail CTAs), one launch.
// grid (3, Bc): x<2 -> 64-row tile (m0 = 64x); x==2 -> tail rows 128..130.
// Smem layout (dynamic, 86272 B):
//   [0, 66816)        scores 2-stage pipeline; later reused as fp32 stash
//                     Ss[64][164] and as V 2-stage pipeline (2x4352)
//   [66816, +19456)   Ps[64][152] fp16 attn probs (conflict-free ldsm stride)
// ---------------------------------------------------------------------------
constexpr int SC_QB   = 64 * 72 * 2;              // 9216
constexpr int SC_STG  = SC_QB + 168 * 72 * 2;     // 33408
constexpr int PS_OFF  = 2 * SC_STG;               // 66816
constexpr int PS_STR  = 152;                      // halves per Ps row
constexpr int AT_DYN  = PS_OFF + 64 * PS_STR * 2; // 86272
constexpr int HV_STG  = 16 * 136 * 2;             // 4352 (V stage)

__global__ void __launch_bounds__(256)
attention_kernel(const __half* __restrict__ Q, const __half* __restrict__ Hm,
                 const int* __restrict__ mask, __half* __restrict__ X) {
    extern __shared__ __align__(16) char smc[];
    __shared__ int mask_s[144];
    const uint32_t smb = smem_u32(smc);
    const int tid = threadIdx.x;
    const int wid = tid >> 5;
    const int lane = tid & 31;
    const int b = blockIdx.y;

    // ======================= TAIL CTA (rows 128..130) =======================
    if (blockIdx.x == 2) {
        float* qs = reinterpret_cast<float*>(smc);           // [3][512]
        float* ps = reinterpret_cast<float*>(smc + 6144);    // [3][132]
        int*   mk = reinterpret_cast<int*>(smc + 7808);      // [132]
        const __half* Qb = Q  + ((size_t)b * Gc + 128) * 512;
        const __half* hb = Hm + (size_t)b * Gc * 512;

        for (int i = tid; i < 3 * 512; i += 256) qs[i] = __half2float(Qb[i]);
        if (tid < 132) mk[tid] = (tid < Gc) ? mask[b * Gc + tid] : 1;
        __syncthreads();

        for (int j = wid; j < Gc; j += 8) {
            const __half* hj = hb + (size_t)j * 512;
            float a0 = 0.f, a1 = 0.f, a2 = 0.f;
#pragma unroll
            for (int k = 0; k < 16; k++) {
                int idx = lane + k * 32;
                float hv = __half2float(hj[idx]);
                a0 = fmaf(hv, qs[idx], a0);
                a1 = fmaf(hv, qs[512 + idx], a1);
                a2 = fmaf(hv, qs[1024 + idx], a2);
            }
#pragma unroll
            for (int o = 16; o; o >>= 1) {
                a0 += __shfl_xor_sync(0xffffffffu, a0, o);
                a1 += __shfl_xor_sync(0xffffffffu, a1, o);
                a2 += __shfl_xor_sync(0xffffffffu, a2, o);
            }
            if (lane == 0) { ps[j] = a0; ps[132 + j] = a1; ps[264 + j] = a2; }
        }
        __syncthreads();

        if (wid < 3) {
            const int gi = 128 + wid;
            const bool li = (gi >= LEAF_LO) && (gi < LEAF_HI);
            const float norm = 0.04419417382415922f;
            float v[5];
            float mx = -3.0e38f;
#pragma unroll
            for (int ch = 0; ch < 5; ch++) {
                int j = lane + ch * 32;
                float val = -3.0e38f;
                if (j < Gc) {
                    bool mj = (mk[j] > 0) || (li && j >= LEAF_LO && j < LEAF_HI);
                    val = mj ? -30.f : ps[wid * 132 + j] * norm;
                }
                v[ch] = val;
                mx = fmaxf(mx, val);
            }
#pragma unroll
            for (int o = 16; o; o >>= 1) mx = fmaxf(mx, __shfl_xor_sync(0xffffffffu, mx, o));
            float e[5];
            float sum = 0.f;
#pragma unroll
            for (int ch = 0; ch < 5; ch++) {
                int j = lane + ch * 32;
                e[ch] = (j < Gc) ? expf(v[ch] - mx) : 0.f;
                sum += e[ch];
            }
#pragma unroll
            for (int o = 16; o; o >>= 1) sum += __shfl_xor_sync(0xffffffffu, sum, o);
            float inv = 1.f / sum;
#pragma unroll
            for (int ch = 0; ch < 5; ch++) {
                int j = lane + ch * 32;
                if (j < Gc) {
                    bool mj = (mk[j] > 0) || (li && j >= LEAF_LO && j < LEAF_HI);
                    ps[wid * 132 + j] = mj ? 0.f : e[ch] * inv;
                }
            }
        }
        __syncthreads();

        float acc[3][2] = {{0.f, 0.f}, {0.f, 0.f}, {0.f, 0.f}};
        for (int j = 0; j < Gc; j++) {
            float p0 = ps[j], p1 = ps[132 + j], p2 = ps[264 + j];
            float h0 = __half2float(hb[(size_t)j * 512 + tid]);
            float h1 = __half2float(hb[(size_t)j * 512 + tid + 256]);
            acc[0][0] = fmaf(p0, h0, acc[0][0]); acc[0][1] = fmaf(p0, h1, acc[0][1]);
            acc[1][0] = fmaf(p1, h0, acc[1][0]); acc[1][1] = fmaf(p1, h1, acc[1][1]);
            acc[2][0] = fmaf(p2, h0, acc[2][0]); acc[2][1] = fmaf(p2, h1, acc[2][1]);
        }
        __half* Xb = X + ((size_t)b * Gc + 128) * 512;
#pragma unroll
        for (int i = 0; i < 3; i++) {
            Xb[(size_t)i * 512 + tid]       = __float2half_rn(acc[i][0]);
            Xb[(size_t)i * 512 + tid + 256] = __float2half_rn(acc[i][1]);
        }
        return;
    }

    // ======================= MAIN CTA (64 rows) =============================
    const int m0 = blockIdx.x * 64;
    if (tid < 144) mask_s[tid] = (tid < Gc) ? mask[b * Gc + tid] : 1;

    const __half* Qb = Q  + (size_t)b * Gc * 512;
    const __half* Kb = Hm + (size_t)b * Gc * 512;

    // ---- phase 1: scores (fp16 mma), 2-stage pipeline, K=512 = 8 x 64 ----
    {
        const int wm = (wid & 1) * 32;
        const int wn = (wid >> 1) * 40;
        const int lr = lane & 7;

        float c[2][5][4];
#pragma unroll
        for (int t = 0; t < 2; t++)
#pragma unroll
            for (int n = 0; n < 5; n++)
#pragma unroll
                for (int v = 0; v < 4; v++) c[t][n][v] = 0.f;

        uint32_t aoff[2], boff[3];
#pragma unroll
        for (int t = 0; t < 2; t++)
            aoff[t] = (uint32_t)(((wm + t * 16 + ((lane >> 3) & 1) * 8 + lr) * 72
                                  + (lane >> 4) * 8) * 2);
#pragma unroll
        for (int jp = 0; jp < 3; jp++)
            boff[jp] = (uint32_t)(SC_QB
                                  + ((wn + jp * 16 + ((lane >> 4) & 1) * 8 + lr) * 72
                                     + ((lane >> 3) & 1) * 8) * 2);

        auto load_stage = [&](int s, int k0) {
            uint32_t qb = smb + (uint32_t)(s * SC_STG);
            uint32_t kb = qb + SC_QB;
#pragma unroll
            for (int l = 0; l < 2; l++) {
                int id = tid + l * 256;
                int row = id >> 3, c8 = (id & 7) << 3;
                cp_async16(qb + (uint32_t)((row * 72 + c8) * 2),
                           Qb + (size_t)(m0 + row) * 512 + k0 + c8);
            }
#pragma unroll
            for (int i = 0; i < 5; i++) {
                int id = tid + i * 256;
                int row = id >> 3, c8 = (id & 7) << 3;
                bool v = row < Gc;
                const __half* src = v ? Kb + (size_t)row * 512 + k0 + c8 : Kb;
                cp_async16z(kb + (uint32_t)((row * 72 + c8) * 2), src, v);
            }
        };

        load_stage(0, 0);
        cp_commit();
        cp_wait0();
        __syncthreads();

        for (int it = 0; it < 8; ++it) {
            if (it + 1 < 8) {
                load_stage((it + 1) & 1, (it + 1) * 64);
                cp_commit();
            }
            uint32_t qb = smb + (uint32_t)((it & 1) * SC_STG);
#pragma unroll
            for (int kk = 0; kk < 4; kk++) {
                uint32_t a[2][4], bfr[6][2];
#pragma unroll
                for (int t = 0; t < 2; t++)
                    ldsm_x4(a[t][0], a[t][1], a[t][2], a[t][3], qb + aoff[t] + kk * 32);
#pragma unroll
                for (int jp = 0; jp < 3; jp++) {
                    uint32_t r0, r1, r2, r3;
                    ldsm_x4(r0, r1, r2, r3, qb + boff[jp] + kk * 32);
                    bfr[2 * jp][0] = r0;     bfr[2 * jp][1] = r1;
                    bfr[2 * jp + 1][0] = r2; bfr[2 * jp + 1][1] = r3;
                }
#pragma unroll
                for (int t = 0; t < 2; t++)
#pragma unroll
                    for (int n = 0; n < 5; n++)
                        mma_f16(c[t][n], a[t], bfr[n]);
            }
            if (it + 1 < 8) cp_wait0();
            __syncthreads();
        }

        // stash accumulators fp32 (reuse pipeline region): Ss[64][164]
        float* Ss = reinterpret_cast<float*>(smc);
        const int g = lane >> 2;
        const int qd = lane & 3;
#pragma unroll
        for (int t = 0; t < 2; t++) {
            int r0 = wm + t * 16 + g;
#pragma unroll
            for (int n = 0; n < 5; n++) {
                int col = wn + n * 8 + 2 * qd;
                *reinterpret_cast<float2*>(&Ss[r0 * 164 + col]) =
                    make_float2(c[t][n][0], c[t][n][1]);
                *reinterpret_cast<float2*>(&Ss[(r0 + 8) * 164 + col]) =
                    make_float2(c[t][n][2], c[t][n][3]);
            }
        }
    }
    __syncthreads();

    // ---- phase 2: softmax -> Ps[64][152] fp16 ----
    {
        float* Ss = reinterpret_cast<float*>(smc);
        __half* Ps = reinterpret_cast<__half*>(smc + PS_OFF);
        const float norm = 0.04419417382415922f;
#pragma unroll
        for (int rr = 0; rr < 8; rr++) {
            int i_loc = wid * 8 + rr;
            int gi = m0 + i_loc;                    // < 128
            bool li = (gi >= LEAF_LO) && (gi < LEAF_HI);
            float v[5];
            float mx = -3.0e38f;
#pragma unroll
            for (int ch = 0; ch < 5; ch++) {
                int j = lane + ch * 32;
                float val = -3.0e38f;
                if (j < Gc) {
                    float s = Ss[i_loc * 164 + j] * norm;
                    bool mj = (mask_s[j] > 0) || (li && j >= LEAF_LO && j < LEAF_HI);
                    val = mj ? -30.f : s;
                }
                v[ch] = val;
                mx = fmaxf(mx, val);
            }
#pragma unroll
            for (int o = 16; o; o >>= 1) mx = fmaxf(mx, __shfl_xor_sync(0xffffffffu, mx, o));
            float e[5];
            float sum = 0.f;
#pragma unroll
            for (int ch = 0; ch < 5; ch++) {
                int j = lane + ch * 32;
                e[ch] = (j < Gc) ? expf(v[ch] - mx) : 0.f;
                sum += e[ch];
            }
#pragma unroll
            for (int o = 16; o; o >>= 1) sum += __shfl_xor_sync(0xffffffffu, sum, o);
            float inv = 1.f / sum;
#pragma unroll
            for (int ch = 0; ch < 5; ch++) {
                int j = lane + ch * 32;
                if (j < 144) {
                    float p = 0.f;
                    if (j < Gc) {
                        bool mj = (mask_s[j] > 0) || (li && j >= LEAF_LO && j < LEAF_HI);
                        p = mj ? 0.f : e[ch] * inv;
                    }
                    Ps[i_loc * PS_STR + j] = __float2half_rn(p);
                }
            }
        }
    }
    __syncthreads();

    // ---- phase 3: heads. X[64,512] = P[64,144] @ Vk[144,512], n-tiled ----
    {
        const __half* Vb = Hm + (size_t)b * Gc * 512;
        const int wm = (wid & 1) * 32;
        const int wn = (wid >> 1) * 32;
        const int lr = lane & 7;
        const uint32_t ps_base = smb + PS_OFF;

        uint32_t aoff[2];
#pragma unroll
        for (int t = 0; t < 2; t++)
            aoff[t] = (uint32_t)(((wm + t * 16 + ((lane >> 3) & 1) * 8 + lr) * PS_STR
                                  + (lane >> 4) * 8) * 2);
        const int tk = lr + ((lane >> 3) & 1) * 8;
        const int tn = (lane >> 4) * 8;

        for (int nt = 0; nt < 4; nt++) {
            const int n0 = nt * 128;
            float c[2][4][4];
#pragma unroll
            for (int t = 0; t < 2; t++)
#pragma unroll
                for (int n = 0; n < 4; n++)
#pragma unroll
                    for (int v = 0; v < 4; v++) c[t][n][v] = 0.f;

            auto vload = [&](int s, int k0) {
                uint32_t vbse = smb + (uint32_t)(s * HV_STG);
                int row = tid >> 4, c8 = (tid & 15) << 3;
                bool v = (k0 + row) < Gc;
                const __half* src = v ? Vb + (size_t)(k0 + row) * 512 + n0 + c8 : Vb;
                cp_async16z(vbse + (uint32_t)((row * 136 + c8) * 2), src, v);
            };

            vload(0, 0);
            cp_commit();
            cp_wait0();
            __syncthreads();

            for (int it = 0; it < 9; ++it) {            // K = 144 = 9 x 16
                if (it + 1 < 9) {
                    vload((it + 1) & 1, (it + 1) * 16);
                    cp_commit();
                }
                uint32_t vbse = smb + (uint32_t)((it & 1) * HV_STG);
                uint32_t a[2][4], bfr[4][2];
#pragma unroll
                for (int t = 0; t < 2; t++)
                    ldsm_x4(a[t][0], a[t][1], a[t][2], a[t][3],
                            ps_base + aoff[t] + it * 32);
#pragma unroll
                for (int p = 0; p < 2; p++) {
                    uint32_t r0, r1, r2, r3;
                    ldsm_x4_t(r0, r1, r2, r3,
                              vbse + (uint32_t)((tk * 136 + wn + p * 16 + tn) * 2));
                    bfr[2 * p][0] = r0;     bfr[2 * p][1] = r1;
                    bfr[2 * p + 1][0] = r2; bfr[2 * p + 1][1] = r3;
                }
#pragma unroll
                for (int t = 0; t < 2; t++)
#pragma unroll
                    for (int n = 0; n < 4; n++)
                        mma_f16(c[t][n], a[t], bfr[n]);
                if (it + 1 < 9) cp_wait0();
                __syncthreads();
            }

            const int g = lane >> 2;
            const int qd = lane & 3;
#pragma unroll
            for (int t = 0; t < 2; t++) {
#pragma unroll
                for (int n = 0; n < 4; n++) {
                    int col = n0 + wn + n * 8 + 2 * qd;
                    int i0r = m0 + wm + t * 16 + g;
                    __half2 p0 = __floats2half2_rn(c[t][n][0], c[t][n][1]);
                    __half2 p1 = __floats2half2_rn(c[t][n][2], c[t][n][3]);
                    *reinterpret_cast<__half2*>(X + ((size_t)b * Gc + i0r) * 512 + col) = p0;
                    *reinterpret_cast<__half2*>(X + ((size_t)b * Gc + i0r + 8) * 512 + col) = p1;
                }
            }
            __syncthreads();   // vbuf stage 0 reused by next nt's vload
        }
    }
}

// ---------------------------------------------------------------------------
// Launch
// ---------------------------------------------------------------------------
extern "C" void kernel_launch(void* const* d_in, const int* in_sizes, int n_in,
                              void* d_out, int out_size) {
    const float* q    = (const float*)d_in[0];
    const int*   mask = (const int*)d_in[1];
    const float* h    = (const float*)d_in[4];
    const float* Wq   = (const float*)d_in[5];
    const float* Wk   = (const float*)d_in[6];
    const float* Wv   = (const float*)d_in[7];
    const float* Wo   = (const float*)d_in[8];
    const float* bo   = (const float*)d_in[9];
    float* out = (float*)d_out;

    __half *gq16, *gh16, *gQp, *gX16, *gW16, *gWM16;
    cudaGetSymbolAddress((void**)&gq16, g_q16);
    cudaGetSymbolAddress((void**)&gh16, g_h16);
    cudaGetSymbolAddress((void**)&gQp,  g_Qp);
    cudaGetSymbolAddress((void**)&gX16, g_X16);
    cudaGetSymbolAddress((void**)&gW16, g_W16);
    cudaGetSymbolAddress((void**)&gWM16, g_WM16);
    __half* gWqT = gW16;
    __half* gWkT = gW16 + 1 * 512 * 512;
    __half* gWvT = gW16 + 2 * 512 * 512;
    __half* gWo_ = gW16 + 3 * 512 * 512;
    __half* gWm  = gWM16;                  // Wm[i,k] = sum_j Wk[j,i] Wq[j,k]
    __half* gWn  = gWM16 + 512 * 512;      // Wn[j,i] = sum_k Wo[j,k] Wv[k,i]

    cudaFuncSetAttribute(mma_gemm_f16<false>,
                         cudaFuncAttributeMaxDynamicSharedMemorySize, GM_SMEM);
    cudaFuncSetAttribute(mma_gemm_f16<true>,
                         cudaFuncAttributeMaxDynamicSharedMemorySize, GM_SMEM);
    cudaFuncSetAttribute(tiny2_gemm_f16,
                         cudaFuncAttributeMaxDynamicSharedMemorySize, GM_SMEM);
    cudaFuncSetAttribute(attention_kernel,
                         cudaFuncAttributeMaxDynamicSharedMemorySize, AT_DYN);

    int n8 = (MTOT * 512) / 8;

    // 1) all prep work in one concurrent launch
    prep_all_kernel<<<dim3(16, 16, 6), dim3(32, 8)>>>(
        (const float4*)q, (const float4*)h, (uint4*)gq16, (uint4*)gh16,
        Wq, Wk, Wv, Wo, gW16, n8);

    // 2) fold both weight products
    tiny2_gemm_f16<<<dim3(4, 4, 2), 256, GM_SMEM>>>(gWkT, gWqT, gWm,
                                                    gWo_, gWvT, gWn);

    // 3) q' = q @ Wm^T
    mma_gemm_f16<false><<<dim3(4, MTOT / 128), 256, GM_SMEM>>>(
        gq16, gWm, nullptr, gQp, 512);

    // 4) fused attention: scores + softmax + heads + tail
    attention_kernel<<<dim3(3, Bc), 256, AT_DYN>>>(gQp, gh16, mask, gX16);

    // 5) out = X @ Wn^T + bias
    mma_gemm_f16<true><<<dim3(4, MTOT / 128), 256, GM_SMEM>>>(
        gX16, gWn, bo, out, 512);
}

// round 11
// speedup vs baseline: 9.6950x; 1.0354x over previous
#include <cuda_runtime.h>
#include <cuda_fp16.h>
#include <math.h>
#include <stdint.h>

// ---------------------------------------------------------------------------
// Problem constants
// ---------------------------------------------------------------------------
constexpr int Bc   = 512;
constexpr int Gc   = 131;
constexpr int MTOT = Bc * Gc;      // 67072
constexpr int LEAF_LO = 80;
constexpr int LEAF_HI = 130;

// Scratch (device globals: allocation-free)
__device__ __half g_q16[(size_t)MTOT * 512];    // q  (fp16)
__device__ __half g_h16[(size_t)MTOT * 512];    // h  (fp16)
__device__ __half g_Qp [(size_t)MTOT * 512];    // q' = q·M
__device__ __half g_X16[(size_t)MTOT * 512];    // X  = attn·h
__device__ __half g_W16[4][512 * 512];          // WqT, WkT, WvT, Wo (fp16)
__device__ __half g_WM16[2][512 * 512];         // Wm, Wn (folded, fp16)

// ---------------------------------------------------------------------------
// PTX helpers (baseline sm_75/80 PTX — valid for compute_103)
// ---------------------------------------------------------------------------
__device__ __forceinline__ uint32_t smem_u32(const void* p) {
    return (uint32_t)__cvta_generic_to_shared(p);
}
__device__ __forceinline__ void cp_async16(uint32_t sdst, const void* gsrc) {
    asm volatile("cp.async.cg.shared.global [%0], [%1], 16;" :: "r"(sdst), "l"(gsrc));
}
__device__ __forceinline__ void cp_async16z(uint32_t sdst, const void* gsrc, bool valid) {
    int sz = valid ? 16 : 0;
    asm volatile("cp.async.cg.shared.global [%0], [%1], 16, %2;"
                 :: "r"(sdst), "l"(gsrc), "r"(sz));
}
__device__ __forceinline__ void cp_commit() { asm volatile("cp.async.commit_group;"); }
__device__ __forceinline__ void cp_wait0()  { asm volatile("cp.async.wait_group 0;"); }
__device__ __forceinline__ void cp_wait1()  { asm volatile("cp.async.wait_group 1;"); }

__device__ __forceinline__ void ldsm_x4(uint32_t& r0, uint32_t& r1, uint32_t& r2,
                                        uint32_t& r3, uint32_t addr) {
    asm volatile("ldmatrix.sync.aligned.m8n8.x4.shared.b16 {%0,%1,%2,%3}, [%4];"
                 : "=r"(r0), "=r"(r1), "=r"(r2), "=r"(r3) : "r"(addr));
}
__device__ __forceinline__ void ldsm_x4_t(uint32_t& r0, uint32_t& r1, uint32_t& r2,
                                          uint32_t& r3, uint32_t addr) {
    asm volatile("ldmatrix.sync.aligned.m8n8.x4.trans.shared.b16 {%0,%1,%2,%3}, [%4];"
                 : "=r"(r0), "=r"(r1), "=r"(r2), "=r"(r3) : "r"(addr));
}
__device__ __forceinline__ void mma_f16(float* c, const uint32_t* a, const uint32_t* b) {
    asm volatile(
        "mma.sync.aligned.m16n8k16.row.col.f32.f16.f16.f32 "
        "{%0,%1,%2,%3}, {%4,%5,%6,%7}, {%8,%9}, {%0,%1,%2,%3};"
        : "+f"(c[0]), "+f"(c[1]), "+f"(c[2]), "+f"(c[3])
        : "r"(a[0]), "r"(a[1]), "r"(a[2]), "r"(a[3]), "r"(b[0]), "r"(b[1]));
}

// ---------------------------------------------------------------------------
// prep_all: z=0 cvt q->fp16, z=1 cvt h->fp16, z=2..4 transpose+cvt Wq/Wk/Wv,
// z=5 plain cvt Wo. One launch => all run concurrently.
// ---------------------------------------------------------------------------
__global__ void prep_all_kernel(const float4* __restrict__ q, const float4* __restrict__ h,
                                uint4* __restrict__ q16, uint4* __restrict__ h16,
                                const float* __restrict__ w0, const float* __restrict__ w1,
                                const float* __restrict__ w2, const float* __restrict__ w3,
                                __half* __restrict__ wout, int n8) {
    const int tx = threadIdx.x, ty = threadIdx.y;
    const int tid = ty * 32 + tx;
    const int z = blockIdx.z;
    if (z < 2) {
        const float4* in = z ? h : q;
        uint4* out = z ? h16 : q16;
        int blk = blockIdx.y * 16 + blockIdx.x;
        for (int i = blk * 256 + tid; i < n8; i += 256 * 256) {
            float4 v0 = in[2 * i], v1 = in[2 * i + 1];
            __half2 h0 = __floats2half2_rn(v0.x, v0.y);
            __half2 h1 = __floats2half2_rn(v0.z, v0.w);
            __half2 h2 = __floats2half2_rn(v1.x, v1.y);
            __half2 h3 = __floats2half2_rn(v1.z, v1.w);
            uint4 o;
            o.x = *reinterpret_cast<uint32_t*>(&h0);
            o.y = *reinterpret_cast<uint32_t*>(&h1);
            o.z = *reinterpret_cast<uint32_t*>(&h2);
            o.w = *reinterpret_cast<uint32_t*>(&h3);
            out[i] = o;
        }
    } else {
        __shared__ float tile[32][33];
        const int sel = z - 2;
        const float* in = (sel == 0) ? w0 : (sel == 1) ? w1 : (sel == 2) ? w2 : w3;
        __half* o = wout + (size_t)sel * 512 * 512;
        const int x = blockIdx.x * 32 + tx;
        const int y0 = blockIdx.y * 32;
        if (sel < 3) {
#pragma unroll
            for (int j = 0; j < 32; j += 8)
                tile[ty + j][tx] = in[(size_t)(y0 + ty + j) * 512 + x];
            __syncthreads();
            const int x2 = y0 + tx;
            const int y2 = blockIdx.x * 32;
#pragma unroll
            for (int j = 0; j < 32; j += 8)
                o[(size_t)(y2 + ty + j) * 512 + x2] = __float2half_rn(tile[tx][ty + j]);
        } else {
#pragma unroll
            for (int j = 0; j < 32; j += 8)
                o[(size_t)(y0 + ty + j) * 512 + x] =
                    __float2half_rn(in[(size_t)(y0 + ty + j) * 512 + x]);
        }
    }
}

// ---------------------------------------------------------------------------
// fp16 mma GEMM-NT (proven round-9 body): C[M,N] = A[M,512] @ W[N,512]^T
// ---------------------------------------------------------------------------
constexpr int GM_ROWH = 72;
constexpr int GM_STAGE_B = 256 * GM_ROWH * 2;     // 36864
constexpr int GM_STAGES = 3;
constexpr int GM_SMEM = GM_STAGES * GM_STAGE_B;   // 110592
constexpr int GM_ITERS = 8;

template <bool OUTF32>
__device__ __forceinline__ void gemm_body_f16(const __half* __restrict__ A,
                                              const __half* __restrict__ W,
                                              const float* __restrict__ bias,
                                              void* __restrict__ Cv, int CS,
                                              int bm, int bn) {
    extern __shared__ __align__(16) char smraw[];
    const uint32_t smb = smem_u32(smraw);
    const int tid = threadIdx.x;
    const int wid = tid >> 5;
    const int lane = tid & 31;
    const int wm = (wid & 3) * 32;
    const int wn = (wid >> 2) * 64;

    const __half* Ag = A + (size_t)bm * 512;
    const __half* Wg = W + (size_t)bn * 512;

    float c[2][8][4];
#pragma unroll
    for (int t = 0; t < 2; t++)
#pragma unroll
        for (int j = 0; j < 8; j++)
#pragma unroll
            for (int v = 0; v < 4; v++) c[t][j][v] = 0.f;

    const int lr = lane & 7;
    uint32_t aoff[2], boff[4];
#pragma unroll
    for (int t = 0; t < 2; t++)
        aoff[t] = (uint32_t)(((wm + t * 16 + ((lane >> 3) & 1) * 8 + lr) * GM_ROWH
                              + (lane >> 4) * 8) * 2);
#pragma unroll
    for (int jp = 0; jp < 4; jp++)
        boff[jp] = (uint32_t)(128 * GM_ROWH * 2
                              + ((wn + jp * 16 + ((lane >> 4) & 1) * 8 + lr) * GM_ROWH
                                 + ((lane >> 3) & 1) * 8) * 2);

    auto load_stage = [&](int s, int k0) {
        uint32_t base = smb + (uint32_t)(s * GM_STAGE_B);
#pragma unroll
        for (int i = 0; i < 4; i++) {
            int id = tid + i * 256;
            int row = id >> 3, c8 = (id & 7) << 3;
            cp_async16(base + (uint32_t)((row * GM_ROWH + c8) * 2),
                       Ag + (size_t)row * 512 + k0 + c8);
        }
#pragma unroll
        for (int i = 0; i < 4; i++) {
            int id = tid + i * 256;
            int row = id >> 3, c8 = (id & 7) << 3;
            cp_async16(base + (uint32_t)(((128 + row) * GM_ROWH + c8) * 2),
                       Wg + (size_t)row * 512 + k0 + c8);
        }
    };

    load_stage(0, 0);    cp_commit();
    load_stage(1, 64);   cp_commit();
    cp_wait1();
    __syncthreads();

    int sc = 0, sl = 2;
    for (int it = 0; it < GM_ITERS; ++it) {
        if (it + 2 < GM_ITERS) {
            load_stage(sl, (it + 2) * 64);
            cp_commit();
            sl = (sl == GM_STAGES - 1) ? 0 : sl + 1;
        }
        uint32_t base = smb + (uint32_t)(sc * GM_STAGE_B);
        sc = (sc == GM_STAGES - 1) ? 0 : sc + 1;
#pragma unroll
        for (int kk = 0; kk < 4; kk++) {
            uint32_t a[2][4], b[8][2];
#pragma unroll
            for (int t = 0; t < 2; t++)
                ldsm_x4(a[t][0], a[t][1], a[t][2], a[t][3], base + aoff[t] + kk * 32);
#pragma unroll
            for (int jp = 0; jp < 4; jp++) {
                uint32_t r0, r1, r2, r3;
                ldsm_x4(r0, r1, r2, r3, base + boff[jp] + kk * 32);
                b[2 * jp][0] = r0;     b[2 * jp][1] = r1;
                b[2 * jp + 1][0] = r2; b[2 * jp + 1][1] = r3;
            }
#pragma unroll
            for (int t = 0; t < 2; t++)
#pragma unroll
                for (int j = 0; j < 8; j++)
                    mma_f16(c[t][j], a[t], b[j]);
        }
        if (it + 2 < GM_ITERS)      cp_wait1();
        else if (it + 1 < GM_ITERS) cp_wait0();
        __syncthreads();
    }

    const int g = lane >> 2;
    const int q = lane & 3;
#pragma unroll
    for (int j = 0; j < 8; j++) {
        int col = bn + wn + j * 8 + 2 * q;
        float b0 = 0.f, b1 = 0.f;
        if (OUTF32) { b0 = bias[col]; b1 = bias[col + 1]; }
#pragma unroll
        for (int t = 0; t < 2; t++) {
            int row0 = bm + wm + t * 16 + g;
            if (OUTF32) {
                float* Cf = (float*)Cv;
                *reinterpret_cast<float2*>(Cf + (size_t)row0 * CS + col) =
                    make_float2(c[t][j][0] + b0, c[t][j][1] + b1);
                *reinterpret_cast<float2*>(Cf + (size_t)(row0 + 8) * CS + col) =
                    make_float2(c[t][j][2] + b0, c[t][j][3] + b1);
            } else {
                __half* Ch = (__half*)Cv;
                __half2 p0 = __floats2half2_rn(c[t][j][0], c[t][j][1]);
                __half2 p1 = __floats2half2_rn(c[t][j][2], c[t][j][3]);
                *reinterpret_cast<__half2*>(Ch + (size_t)row0 * CS + col) = p0;
                *reinterpret_cast<__half2*>(Ch + (size_t)(row0 + 8) * CS + col) = p1;
            }
        }
    }
}

template <bool OUTF32>
__global__ void __launch_bounds__(256)
mma_gemm_f16(const __half* __restrict__ A, const __half* __restrict__ W,
             const float* __restrict__ bias, void* __restrict__ C, int CS) {
    gemm_body_f16<OUTF32>(A, W, bias, C, CS, blockIdx.y * 128, blockIdx.x * 128);
}

__global__ void __launch_bounds__(256)
tiny2_gemm_f16(const __half* __restrict__ A0, const __half* __restrict__ W0,
               __half* __restrict__ C0,
               const __half* __restrict__ A1, const __half* __restrict__ W1,
               __half* __restrict__ C1) {
    if (blockIdx.z == 0)
        gemm_body_f16<false>(A0, W0, nullptr, C0, 512, blockIdx.y * 128, blockIdx.x * 128);
    else
        gemm_body_f16<false>(A1, W1, nullptr, C1, 512, blockIdx.y * 128, blockIdx.x * 128);
}

// ---------------------------------------------------------------------------
// FUSED attention. grid (3, Bc): x<2 -> 64-row mma tile; x==2 -> tail rows.
// Smem (dynamic, 97792 B):
//   region A [0, 78336): phase1 2x33408 scores pipeline -> fp32 stash
//                        Ss[64][164] -> phase3 2x39168 whole-tile V buffers
//   Ps at [78336, +19456): fp16 probs [64][152]
// ---------------------------------------------------------------------------
constexpr int SC_QB   = 64 * 72 * 2;              // 9216
constexpr int SC_STG  = SC_QB + 168 * 72 * 2;     // 33408
constexpr int HV_TILE = 144 * 136 * 2;            // 39168 whole V n-tile
constexpr int PS_OFF  = 2 * HV_TILE;              // 78336 (>= 2*SC_STG, >= stash)
constexpr int PS_STR  = 152;
constexpr int AT_DYN  = PS_OFF + 64 * PS_STR * 2; // 97792

__global__ void __launch_bounds__(256)
attention_kernel(const __half* __restrict__ Q, const __half* __restrict__ Hm,
                 const int* __restrict__ mask, __half* __restrict__ X) {
    extern __shared__ __align__(16) char smc[];
    __shared__ int mask_s[144];
    const uint32_t smb = smem_u32(smc);
    const int tid = threadIdx.x;
    const int wid = tid >> 5;
    const int lane = tid & 31;
    const int b = blockIdx.y;

    // ======================= TAIL CTA (rows 128..130) =======================
    if (blockIdx.x == 2) {
        float* qs = reinterpret_cast<float*>(smc);           // [3][512]
        float* ps = reinterpret_cast<float*>(smc + 6144);    // [3][132]
        int*   mk = reinterpret_cast<int*>(smc + 7808);      // [132]
        const __half* Qb = Q  + ((size_t)b * Gc + 128) * 512;
        const __half* hb = Hm + (size_t)b * Gc * 512;

        for (int i = tid; i < 3 * 512; i += 256) qs[i] = __half2float(Qb[i]);
        if (tid < 132) mk[tid] = (tid < Gc) ? mask[b * Gc + tid] : 1;
        __syncthreads();

        for (int j = wid; j < Gc; j += 8) {
            const __half* hj = hb + (size_t)j * 512;
            float a0 = 0.f, a1 = 0.f, a2 = 0.f;
#pragma unroll
            for (int k = 0; k < 16; k++) {
                int idx = lane + k * 32;
                float hv = __half2float(hj[idx]);
                a0 = fmaf(hv, qs[idx], a0);
                a1 = fmaf(hv, qs[512 + idx], a1);
                a2 = fmaf(hv, qs[1024 + idx], a2);
            }
#pragma unroll
            for (int o = 16; o; o >>= 1) {
                a0 += __shfl_xor_sync(0xffffffffu, a0, o);
                a1 += __shfl_xor_sync(0xffffffffu, a1, o);
                a2 += __shfl_xor_sync(0xffffffffu, a2, o);
            }
            if (lane == 0) { ps[j] = a0; ps[132 + j] = a1; ps[264 + j] = a2; }
        }
        __syncthreads();

        if (wid < 3) {
            const int gi = 128 + wid;
            const bool li = (gi >= LEAF_LO) && (gi < LEAF_HI);
            const float norm = 0.04419417382415922f;
            float v[5];
            float mx = -3.0e38f;
#pragma unroll
            for (int ch = 0; ch < 5; ch++) {
                int j = lane + ch * 32;
                float val = -3.0e38f;
                if (j < Gc) {
                    bool mj = (mk[j] > 0) || (li && j >= LEAF_LO && j < LEAF_HI);
                    val = mj ? -30.f : ps[wid * 132 + j] * norm;
                }
                v[ch] = val;
                mx = fmaxf(mx, val);
            }
#pragma unroll
            for (int o = 16; o; o >>= 1) mx = fmaxf(mx, __shfl_xor_sync(0xffffffffu, mx, o));
            float e[5];
            float sum = 0.f;
#pragma unroll
            for (int ch = 0; ch < 5; ch++) {
                int j = lane + ch * 32;
                e[ch] = (j < Gc) ? expf(v[ch] - mx) : 0.f;
                sum += e[ch];
            }
#pragma unroll
            for (int o = 16; o; o >>= 1) sum += __shfl_xor_sync(0xffffffffu, sum, o);
            float inv = 1.f / sum;
#pragma unroll
            for (int ch = 0; ch < 5; ch++) {
                int j = lane + ch * 32;
                if (j < Gc) {
                    bool mj = (mk[j] > 0) || (li && j >= LEAF_LO && j < LEAF_HI);
                    ps[wid * 132 + j] = mj ? 0.f : e[ch] * inv;
                }
            }
        }
        __syncthreads();

        float acc[3][2] = {{0.f, 0.f}, {0.f, 0.f}, {0.f, 0.f}};
        for (int j = 0; j < Gc; j++) {
            float p0 = ps[j], p1 = ps[132 + j], p2 = ps[264 + j];
            float h0 = __half2float(hb[(size_t)j * 512 + tid]);
            float h1 = __half2float(hb[(size_t)j * 512 + tid + 256]);
            acc[0][0] = fmaf(p0, h0, acc[0][0]); acc[0][1] = fmaf(p0, h1, acc[0][1]);
            acc[1][0] = fmaf(p1, h0, acc[1][0]); acc[1][1] = fmaf(p1, h1, acc[1][1]);
            acc[2][0] = fmaf(p2, h0, acc[2][0]); acc[2][1] = fmaf(p2, h1, acc[2][1]);
        }
        __half* Xb = X + ((size_t)b * Gc + 128) * 512;
#pragma unroll
        for (int i = 0; i < 3; i++) {
            Xb[(size_t)i * 512 + tid]       = __float2half_rn(acc[i][0]);
            Xb[(size_t)i * 512 + tid + 256] = __float2half_rn(acc[i][1]);
        }
        return;
    }

    // ======================= MAIN CTA (64 rows) =============================
    const int m0 = blockIdx.x * 64;
    if (tid < 144) mask_s[tid] = (tid < Gc) ? mask[b * Gc + tid] : 1;

    const __half* Qb = Q  + (size_t)b * Gc * 512;
    const __half* Kb = Hm + (size_t)b * Gc * 512;

    // ---- phase 1: scores (fp16 mma), 2-stage pipeline, K=512 = 8 x 64 ----
    {
        const int wm = (wid & 1) * 32;
        const int wn = (wid >> 1) * 40;
        const int lr = lane & 7;

        float c[2][5][4];
#pragma unroll
        for (int t = 0; t < 2; t++)
#pragma unroll
            for (int n = 0; n < 5; n++)
#pragma unroll
                for (int v = 0; v < 4; v++) c[t][n][v] = 0.f;

        uint32_t aoff[2], boff[3];
#pragma unroll
        for (int t = 0; t < 2; t++)
            aoff[t] = (uint32_t)(((wm + t * 16 + ((lane >> 3) & 1) * 8 + lr) * 72
                                  + (lane >> 4) * 8) * 2);
#pragma unroll
        for (int jp = 0; jp < 3; jp++)
            boff[jp] = (uint32_t)(SC_QB
                                  + ((wn + jp * 16 + ((lane >> 4) & 1) * 8 + lr) * 72
                                     + ((lane >> 3) & 1) * 8) * 2);

        auto load_stage = [&](int s, int k0) {
            uint32_t qb = smb + (uint32_t)(s * SC_STG);
            uint32_t kb = qb + SC_QB;
#pragma unroll
            for (int l = 0; l < 2; l++) {
                int id = tid + l * 256;
                int row = id >> 3, c8 = (id & 7) << 3;
                cp_async16(qb + (uint32_t)((row * 72 + c8) * 2),
                           Qb + (size_t)(m0 + row) * 512 + k0 + c8);
            }
#pragma unroll
            for (int i = 0; i < 5; i++) {
                int id = tid + i * 256;
                int row = id >> 3, c8 = (id & 7) << 3;
                bool v = row < Gc;
                const __half* src = v ? Kb + (size_t)row * 512 + k0 + c8 : Kb;
                cp_async16z(kb + (uint32_t)((row * 72 + c8) * 2), src, v);
            }
        };

        load_stage(0, 0);
        cp_commit();
        cp_wait0();
        __syncthreads();

        for (int it = 0; it < 8; ++it) {
            if (it + 1 < 8) {
                load_stage((it + 1) & 1, (it + 1) * 64);
                cp_commit();
            }
            uint32_t qb = smb + (uint32_t)((it & 1) * SC_STG);
#pragma unroll
            for (int kk = 0; kk < 4; kk++) {
                uint32_t a[2][4], bfr[6][2];
#pragma unroll
                for (int t = 0; t < 2; t++)
                    ldsm_x4(a[t][0], a[t][1], a[t][2], a[t][3], qb + aoff[t] + kk * 32);
#pragma unroll
                for (int jp = 0; jp < 3; jp++) {
                    uint32_t r0, r1, r2, r3;
                    ldsm_x4(r0, r1, r2, r3, qb + boff[jp] + kk * 32);
                    bfr[2 * jp][0] = r0;     bfr[2 * jp][1] = r1;
                    bfr[2 * jp + 1][0] = r2; bfr[2 * jp + 1][1] = r3;
                }
#pragma unroll
                for (int t = 0; t < 2; t++)
#pragma unroll
                    for (int n = 0; n < 5; n++)
                        mma_f16(c[t][n], a[t], bfr[n]);
            }
            if (it + 1 < 8) cp_wait0();
            __syncthreads();
        }

        // stash accumulators fp32 (reuse pipeline region): Ss[64][164]
        float* Ss = reinterpret_cast<float*>(smc);
        const int g = lane >> 2;
        const int qd = lane & 3;
#pragma unroll
        for (int t = 0; t < 2; t++) {
            int r0 = wm + t * 16 + g;
#pragma unroll
            for (int n = 0; n < 5; n++) {
                int col = wn + n * 8 + 2 * qd;
                *reinterpret_cast<float2*>(&Ss[r0 * 164 + col]) =
                    make_float2(c[t][n][0], c[t][n][1]);
                *reinterpret_cast<float2*>(&Ss[(r0 + 8) * 164 + col]) =
                    make_float2(c[t][n][2], c[t][n][3]);
            }
        }
    }
    __syncthreads();

    // ---- phase 2: softmax -> Ps[64][152] fp16 ----
    {
        float* Ss = reinterpret_cast<float*>(smc);
        __half* Ps = reinterpret_cast<__half*>(smc + PS_OFF);
        const float norm = 0.04419417382415922f;
#pragma unroll
        for (int rr = 0; rr < 8; rr++) {
            int i_loc = wid * 8 + rr;
            int gi = m0 + i_loc;                    // < 128
            bool li = (gi >= LEAF_LO) && (gi < LEAF_HI);
            float v[5];
            float mx = -3.0e38f;
#pragma unroll
            for (int ch = 0; ch < 5; ch++) {
                int j = lane + ch * 32;
                float val = -3.0e38f;
                if (j < Gc) {
                    float s = Ss[i_loc * 164 + j] * norm;
                    bool mj = (mask_s[j] > 0) || (li && j >= LEAF_LO && j < LEAF_HI);
                    val = mj ? -30.f : s;
                }
                v[ch] = val;
                mx = fmaxf(mx, val);
            }
#pragma unroll
            for (int o = 16; o; o >>= 1) mx = fmaxf(mx, __shfl_xor_sync(0xffffffffu, mx, o));
            float e[5];
            float sum = 0.f;
#pragma unroll
            for (int ch = 0; ch < 5; ch++) {
                int j = lane + ch * 32;
                e[ch] = (j < Gc) ? expf(v[ch] - mx) : 0.f;
                sum += e[ch];
            }
#pragma unroll
            for (int o = 16; o; o >>= 1) sum += __shfl_xor_sync(0xffffffffu, sum, o);
            float inv = 1.f / sum;
#pragma unroll
            for (int ch = 0; ch < 5; ch++) {
                int j = lane + ch * 32;
                if (j < 144) {
                    float p = 0.f;
                    if (j < Gc) {
                        bool mj = (mask_s[j] > 0) || (li && j >= LEAF_LO && j < LEAF_HI);
                        p = mj ? 0.f : e[ch] * inv;
                    }
                    Ps[i_loc * PS_STR + j] = __float2half_rn(p);
                }
            }
        }
    }
    __syncthreads();

    // ---- phase 3: heads. Whole-tile V double buffering: one wait + one
    // barrier per n-tile; 9 mma iterations run uninterrupted while the next
    // n-tile's V streams in.
    {
        const __half* Vb = Hm + (size_t)b * Gc * 512;
        const int wm = (wid & 1) * 32;
        const int wn = (wid >> 1) * 32;
        const int lr = lane & 7;
        const uint32_t ps_base = smb + PS_OFF;

        uint32_t aoff[2];
#pragma unroll
        for (int t = 0; t < 2; t++)
            aoff[t] = (uint32_t)(((wm + t * 16 + ((lane >> 3) & 1) * 8 + lr) * PS_STR
                                  + (lane >> 4) * 8) * 2);
        const int tk = lr + ((lane >> 3) & 1) * 8;
        const int tn = (lane >> 4) * 8;

        // whole-tile V load: 144 rows x 128 cols fp16 = 2304 16B chunks
        auto vload_tile = [&](int s, int n0) {
            uint32_t vbse = smb + (uint32_t)(s * HV_TILE);
#pragma unroll
            for (int i = 0; i < 9; i++) {
                int id = tid + i * 256;
                int row = id >> 4, c8 = (id & 15) << 3;
                bool v = row < Gc;
                const __half* src = v ? Vb + (size_t)row * 512 + n0 + c8 : Vb;
                cp_async16z(vbse + (uint32_t)((row * 136 + c8) * 2), src, v);
            }
        };

        vload_tile(0, 0);
        cp_commit();

        for (int nt = 0; nt < 4; nt++) {
            cp_wait0();          // tile nt resident (only pending group)
            __syncthreads();     // all warps see it; prior reads of other buf done
            if (nt + 1 < 4) {
                vload_tile((nt + 1) & 1, (nt + 1) * 128);
                cp_commit();
            }
            uint32_t vbse = smb + (uint32_t)((nt & 1) * HV_TILE);
            const int n0 = nt * 128;

            float c[2][4][4];
#pragma unroll
            for (int t = 0; t < 2; t++)
#pragma unroll
                for (int n = 0; n < 4; n++)
#pragma unroll
                    for (int v = 0; v < 4; v++) c[t][n][v] = 0.f;

#pragma unroll
            for (int it = 0; it < 9; ++it) {        // K = 144 = 9 x 16
                uint32_t a[2][4], bfr[4][2];
#pragma unroll
                for (int t = 0; t < 2; t++)
                    ldsm_x4(a[t][0], a[t][1], a[t][2], a[t][3],
                            ps_base + aoff[t] + it * 32);
#pragma unroll
                for (int p = 0; p < 2; p++) {
                    uint32_t r0, r1, r2, r3;
                    ldsm_x4_t(r0, r1, r2, r3,
                              vbse + (uint32_t)(((it * 16 + tk) * 136
                                                 + wn + p * 16 + tn) * 2));
                    bfr[2 * p][0] = r0;     bfr[2 * p][1] = r1;
                    bfr[2 * p + 1][0] = r2; bfr[2 * p + 1][1] = r3;
                }
#pragma unroll
                for (int t = 0; t < 2; t++)
#pragma unroll
                    for (int n = 0; n < 4; n++)
                        mma_f16(c[t][n], a[t], bfr[n]);
            }

            const int g = lane >> 2;
            const int qd = lane & 3;
#pragma unroll
            for (int t = 0; t < 2; t++) {
#pragma unroll
                for (int n = 0; n < 4; n++) {
                    int col = n0 + wn + n * 8 + 2 * qd;
                    int i0r = m0 + wm + t * 16 + g;
                    __half2 p0 = __floats2half2_rn(c[t][n][0], c[t][n][1]);
                    __half2 p1 = __floats2half2_rn(c[t][n][2], c[t][n][3]);
                    *reinterpret_cast<__half2*>(X + ((size_t)b * Gc + i0r) * 512 + col) = p0;
                    *reinterpret_cast<__half2*>(X + ((size_t)b * Gc + i0r + 8) * 512 + col) = p1;
                }
            }
        }
    }
}

// ---------------------------------------------------------------------------
// Launch
// ---------------------------------------------------------------------------
extern "C" void kernel_launch(void* const* d_in, const int* in_sizes, int n_in,
                              void* d_out, int out_size) {
    const float* q    = (const float*)d_in[0];
    const int*   mask = (const int*)d_in[1];
    const float* h    = (const float*)d_in[4];
    const float* Wq   = (const float*)d_in[5];
    const float* Wk   = (const float*)d_in[6];
    const float* Wv   = (const float*)d_in[7];
    const float* Wo   = (const float*)d_in[8];
    const float* bo   = (const float*)d_in[9];
    float* out = (float*)d_out;

    __half *gq16, *gh16, *gQp, *gX16, *gW16, *gWM16;
    cudaGetSymbolAddress((void**)&gq16, g_q16);
    cudaGetSymbolAddress((void**)&gh16, g_h16);
    cudaGetSymbolAddress((void**)&gQp,  g_Qp);
    cudaGetSymbolAddress((void**)&gX16, g_X16);
    cudaGetSymbolAddress((void**)&gW16, g_W16);
    cudaGetSymbolAddress((void**)&gWM16, g_WM16);
    __half* gWqT = gW16;
    __half* gWkT = gW16 + 1 * 512 * 512;
    __half* gWvT = gW16 + 2 * 512 * 512;
    __half* gWo_ = gW16 + 3 * 512 * 512;
    __half* gWm  = gWM16;                  // Wm[i,k] = sum_j Wk[j,i] Wq[j,k]
    __half* gWn  = gWM16 + 512 * 512;      // Wn[j,i] = sum_k Wo[j,k] Wv[k,i]

    cudaFuncSetAttribute(mma_gemm_f16<false>,
                         cudaFuncAttributeMaxDynamicSharedMemorySize, GM_SMEM);
    cudaFuncSetAttribute(mma_gemm_f16<true>,
                         cudaFuncAttributeMaxDynamicSharedMemorySize, GM_SMEM);
    cudaFuncSetAttribute(tiny2_gemm_f16,
                         cudaFuncAttributeMaxDynamicSharedMemorySize, GM_SMEM);
    cudaFuncSetAttribute(attention_kernel,
                         cudaFuncAttributeMaxDynamicSharedMemorySize, AT_DYN);

    int n8 = (MTOT * 512) / 8;

    // 1) all prep work in one concurrent launch
    prep_all_kernel<<<dim3(16, 16, 6), dim3(32, 8)>>>(
        (const float4*)q, (const float4*)h, (uint4*)gq16, (uint4*)gh16,
        Wq, Wk, Wv, Wo, gW16, n8);

    // 2) fold both weight products
    tiny2_gemm_f16<<<dim3(4, 4, 2), 256, GM_SMEM>>>(gWkT, gWqT, gWm,
                                                    gWo_, gWvT, gWn);

    // 3) q' = q @ Wm^T
    mma_gemm_f16<false><<<dim3(4, MTOT / 128), 256, GM_SMEM>>>(
        gq16, gWm, nullptr, gQp, 512);

    // 4) fused attention: scores + softmax + heads + tail
    attention_kernel<<<dim3(3, Bc), 256, AT_DYN>>>(gQp, gh16, mask, gX16);

    // 5) out = X @ Wn^T + bias
    mma_gemm_f16<true><<<dim3(4, MTOT / 128), 256, GM_SMEM>>>(
        gX16, gWn, bo, out, 512);
}